// round 2
// baseline (speedup 1.0000x reference)
#include <cuda_runtime.h>
#include <math.h>

#define NMAX 100000
#define RMAX 3

// Scratch (device globals; no allocation allowed)
__device__ __align__(256) float g_z[(size_t)NMAX * 192];            // [N][3][64] accum -> z_r
__device__ __align__(256) float g_hsrc[(size_t)RMAX * NMAX * 64];   // h_src per relation
__device__ __align__(256) float g_el[RMAX * NMAX];                  // el per relation
__device__ __align__(256) float g_er[RMAX * NMAX];                  // er per relation
__device__ __align__(256) float g_den[RMAX * NMAX];                 // softmax denominators
__device__ __align__(256) float g_wpart[4];                         // semantic logit partials

// ---------- packed f32x2 helpers (sm_103a) ----------
__device__ __forceinline__ unsigned long long pack2(float a, float b) {
    unsigned long long r;
    asm("mov.b64 %0, {%1, %2};" : "=l"(r) : "f"(a), "f"(b));
    return r;
}
__device__ __forceinline__ void unpack2(unsigned long long v, float& a, float& b) {
    asm("mov.b64 {%0, %1}, %2;" : "=f"(a), "=f"(b) : "l"(v));
}
__device__ __forceinline__ void fma2(unsigned long long& d, unsigned long long a, unsigned long long b) {
    asm("fma.rn.f32x2 %0, %1, %2, %0;" : "+l"(d) : "l"(a), "l"(b));
}
__device__ __forceinline__ void red_add_v4(float* addr, float a, float b, float c, float d) {
    asm volatile("red.global.add.v4.f32 [%0], {%1, %2, %3, %4};"
                 :: "l"(addr), "f"(a), "f"(b), "f"(c), "f"(d) : "memory");
}
__device__ __forceinline__ float tanh_approx(float x) {
    float y;
    asm("tanh.approx.f32 %0, %1;" : "=f"(y) : "f"(x));
    return y;
}

// ---------- zero scratch ----------
__global__ void k_zero(int nz4, int nden) {
    int i = blockIdx.x * blockDim.x + threadIdx.x;
    int stride = gridDim.x * blockDim.x;
    float4* z4 = (float4*)g_z;
    float4 zv = make_float4(0.f, 0.f, 0.f, 0.f);
    for (int j = i; j < nz4; j += stride) z4[j] = zv;
    for (int j = i; j < nden; j += stride) g_den[j] = 0.f;
    if (i < 4) g_wpart[i] = 0.f;
}

// ---------- merged GEMM: 4 segments (seg 0 = dst path, seg 1..3 = src paths) ----------
// 2 threads per row (each does 32 of 64 output cols) -> half the regs, 3x occupancy.
__global__ __launch_bounds__(256) void k_gemm(
    const float* __restrict__ dst_feat, const float* __restrict__ neigh,
    const float* __restrict__ Wt, const float* __restrict__ bt,
    const float* __restrict__ attn_l, const float* __restrict__ attn_r, int N)
{
    __shared__ __align__(16) float Ws[128 * 64];
    __shared__ float bs[64];
    __shared__ float as[3 * 64];
    int tid = threadIdx.x;
    int seg = blockIdx.y;

    const float* X;
    const float* W;
    const float* bias;
    const float* av;
    int n_av;
    if (seg == 0) {
        X = dst_feat; W = Wt; bias = bt; av = attn_r; n_av = 3;
    } else {
        int r = seg - 1;
        X = neigh + (size_t)r * N * 128;
        W = Wt + (size_t)(r + 1) * 128 * 64;
        bias = bt + (size_t)(r + 1) * 64;
        av = attn_l + (size_t)r * 64;
        n_av = 1;
    }

    const float4* W4 = (const float4*)W;
    float4* Ws4 = (float4*)Ws;
    #pragma unroll
    for (int i = 0; i < 8; i++) Ws4[tid + 256 * i] = W4[tid + 256 * i];
    if (tid < 64) bs[tid] = bias[tid];
    if (tid < n_av * 64) as[tid] = av[tid];
    __syncthreads();

    int row = blockIdx.x * 128 + (tid >> 1);
    int half = tid & 1;
    if (row >= N) return;
    int c0 = half * 32;

    unsigned long long acc[16];
    #pragma unroll
    for (int m = 0; m < 16; m++) acc[m] = pack2(bs[c0 + 2 * m], bs[c0 + 2 * m + 1]);

    const float4* Xr = (const float4*)(X + (size_t)row * 128);
    const ulonglong2* Wp = (const ulonglong2*)Ws;

    #pragma unroll 4
    for (int k0 = 0; k0 < 32; k0++) {
        float4 xv = Xr[k0];
        #pragma unroll
        for (int kk = 0; kk < 4; kk++) {
            float xs = (kk == 0) ? xv.x : (kk == 1) ? xv.y : (kk == 2) ? xv.z : xv.w;
            unsigned long long xx = pack2(xs, xs);
            const ulonglong2* wr = Wp + (k0 * 4 + kk) * 16 + half * 8;
            #pragma unroll
            for (int j = 0; j < 8; j++) {
                ulonglong2 w = wr[j];
                fma2(acc[2 * j], w.x, xx);
                fma2(acc[2 * j + 1], w.y, xx);
            }
        }
    }

    float h[32];
    #pragma unroll
    for (int m = 0; m < 16; m++) unpack2(acc[m], h[2 * m], h[2 * m + 1]);

    if (seg > 0) {
        float4* o4 = (float4*)(g_hsrc + ((size_t)(seg - 1) * N + row) * 64 + c0);
        #pragma unroll
        for (int q = 0; q < 8; q++)
            o4[q] = make_float4(h[4 * q], h[4 * q + 1], h[4 * q + 2], h[4 * q + 3]);
    }

    for (int v = 0; v < n_av; v++) {
        float e = 0.f;
        #pragma unroll
        for (int j = 0; j < 32; j++) e += h[j] * as[v * 64 + c0 + j];
        e += __shfl_xor_sync(0xffffffffu, e, 1);
        if (half == 0) {
            if (seg == 0) g_er[(size_t)v * N + row] = e;
            else          g_el[(size_t)(seg - 1) * N + row] = e;
        }
    }
}

// ---------- merged edge pass over all 3 relations ----------
__global__ __launch_bounds__(256) void k_edge(
    const int* __restrict__ src, const int* __restrict__ dst, int N, int E)
{
    int t = blockIdx.x * blockDim.x + threadIdx.x;
    int g = t >> 4;
    int lane = t & 15;
    int gsz = (gridDim.x * blockDim.x) >> 4;
    const float4* h4 = (const float4*)g_hsrc;
    int E2 = 2 * E, E3 = 3 * E;

    for (int e = g; e < E3; e += gsz) {
        int r = (e >= E2) ? 2 : (e >= E) ? 1 : 0;
        int s = __ldg(&src[e]);
        int d = __ldg(&dst[e]);
        float x = __ldg(&g_el[(size_t)r * N + s]) + __ldg(&g_er[(size_t)r * N + d]);
        float lr = x > 0.f ? x : 0.01f * x;
        float p = __expf(lr);
        float4 v = __ldg(&h4[((size_t)r * N + s) * 16 + lane]);
        float* addr = g_z + (size_t)d * 192 + r * 64 + lane * 4;
        red_add_v4(addr, p * v.x, p * v.y, p * v.z, p * v.w);
        if (lane == 0) atomicAdd(&g_den[(size_t)r * N + d], p);
    }
}

// ---------- merged finalize: z = elu(num/den) for all (row, r); fused semantic logits ----------
__global__ __launch_bounds__(256) void k_finalize(
    const float* __restrict__ W1, const float* __restrict__ b1,
    const float* __restrict__ w2, int N)
{
    __shared__ __align__(16) float W1s[64 * 128];
    __shared__ float b1s[128], w2s[128];
    __shared__ float zbuf[8][64];
    __shared__ float wsum[8][3];
    int tid = threadIdx.x, wid = tid >> 5, lane = tid & 31;
    const float4* W14 = (const float4*)W1;
    float4* W1s4 = (float4*)W1s;
    #pragma unroll
    for (int i = 0; i < 8; i++) W1s4[tid + 256 * i] = W14[tid + 256 * i];
    if (tid < 128) { b1s[tid] = b1[tid]; w2s[tid] = w2[tid]; }
    __syncthreads();

    int items = 3 * N;
    int nwarps = gridDim.x * 8;
    int N2 = 2 * N;
    float tacc[3] = {0.f, 0.f, 0.f};
    const ulonglong2* Wp = (const ulonglong2*)W1s;

    for (int item = blockIdx.x * 8 + wid; item < items; item += nwarps) {
        int r = (item >= N2) ? 2 : (item >= N) ? 1 : 0;
        int row = item - r * N;

        float* zr = g_z + (size_t)row * 192 + r * 64;
        float den = g_den[(size_t)r * N + row];
        float dinv = den > 0.f ? 1.f / den : 0.f;   // zero-degree -> elu(0)=0
        float z0 = zr[lane] * dinv;
        float z1 = zr[32 + lane] * dinv;
        z0 = z0 > 0.f ? z0 : expm1f(z0);
        z1 = z1 > 0.f ? z1 : expm1f(z1);
        zr[lane] = z0;
        zr[32 + lane] = z1;
        zbuf[wid][lane] = z0;
        zbuf[wid][32 + lane] = z1;
        __syncwarp();

        unsigned long long h01 = pack2(b1s[4 * lane], b1s[4 * lane + 1]);
        unsigned long long h23 = pack2(b1s[4 * lane + 2], b1s[4 * lane + 3]);
        #pragma unroll 8
        for (int i = 0; i < 64; i++) {
            float zi = zbuf[wid][i];
            unsigned long long zz = pack2(zi, zi);
            ulonglong2 w = Wp[i * 32 + lane];
            fma2(h01, w.x, zz);
            fma2(h23, w.y, zz);
        }
        __syncwarp();
        float h0, h1, h2, h3;
        unpack2(h01, h0, h1);
        unpack2(h23, h2, h3);
        h0 = tanh_approx(h0); h1 = tanh_approx(h1);
        h2 = tanh_approx(h2); h3 = tanh_approx(h3);
        float tv = h0 * w2s[4 * lane] + h1 * w2s[4 * lane + 1]
                 + h2 * w2s[4 * lane + 2] + h3 * w2s[4 * lane + 3];
        tacc[r] += tv;
    }

    #pragma unroll
    for (int r = 0; r < 3; r++) {
        float s = tacc[r];
        #pragma unroll
        for (int o = 16; o; o >>= 1) s += __shfl_xor_sync(0xffffffffu, s, o);
        if (lane == 0) wsum[wid][r] = s;
    }
    __syncthreads();
    if (tid < 3) {
        float s = 0.f;
        #pragma unroll
        for (int w = 0; w < 8; w++) s += wsum[w][tid];
        atomicAdd(&g_wpart[tid], s);
    }
}

// ---------- semantic softmax + mix ----------
__global__ void k_mix(float* __restrict__ out, int N, float invN) {
    float w0 = g_wpart[0] * invN, w1 = g_wpart[1] * invN, w2v = g_wpart[2] * invN;
    float m = fmaxf(w0, fmaxf(w1, w2v));
    float e0 = __expf(w0 - m), e1 = __expf(w1 - m), e2 = __expf(w2v - m);
    float si = 1.f / (e0 + e1 + e2);
    float a0 = e0 * si, a1 = e1 * si, a2 = e2 * si;

    const float4* z4 = (const float4*)g_z;
    float4* o4 = (float4*)out;
    int total = N * 16;
    int i = blockIdx.x * blockDim.x + threadIdx.x;
    int stride = gridDim.x * blockDim.x;
    for (int idx = i; idx < total; idx += stride) {
        int n = idx >> 4, q = idx & 15;
        float4 v0 = z4[(size_t)n * 48 + q];
        float4 v1 = z4[(size_t)n * 48 + 16 + q];
        float4 v2 = z4[(size_t)n * 48 + 32 + q];
        float4 o;
        o.x = a0 * v0.x + a1 * v1.x + a2 * v2.x;
        o.y = a0 * v0.y + a1 * v1.y + a2 * v2.y;
        o.z = a0 * v0.z + a1 * v1.z + a2 * v2.z;
        o.w = a0 * v0.w + a1 * v1.w + a2 * v2.w;
        o4[idx] = o;
    }
}

extern "C" void kernel_launch(void* const* d_in, const int* in_sizes, int n_in,
                              void* d_out, int out_size) {
    const float* dst_feat = (const float*)d_in[0];
    const float* neigh    = (const float*)d_in[1];
    const float* Wt       = (const float*)d_in[2];
    const float* bt       = (const float*)d_in[3];
    const float* attn_l   = (const float*)d_in[4];
    const float* attn_r   = (const float*)d_in[5];
    const float* W1       = (const float*)d_in[6];
    const float* b1       = (const float*)d_in[7];
    const float* w2       = (const float*)d_in[8];
    const int*   src      = (const int*)d_in[9];
    const int*   dst      = (const int*)d_in[10];

    int N = in_sizes[0] / 128;          // 100000
    int E = in_sizes[9] / 3;            // 1000000
    (void)n_in; (void)out_size;

    k_zero<<<2048, 256>>>(N * 48, 3 * N);

    dim3 ggrid((N * 2 + 255) / 256, 4);
    k_gemm<<<ggrid, 256>>>(dst_feat, neigh, Wt, bt, attn_l, attn_r, N);

    k_edge<<<3552, 256>>>(src, dst, N, E);

    k_finalize<<<2048, 256>>>(W1, b1, w2, N);

    k_mix<<<1024, 256>>>((float*)d_out, N, 1.0f / (float)N);
}

// round 3
// speedup vs baseline: 1.4523x; 1.4523x over previous
#include <cuda_runtime.h>
#include <math.h>

#define NMAX 100000
#define RMAX 3

// Scratch (device globals; no allocation allowed)
__device__ __align__(256) float g_z[(size_t)NMAX * 192];            // [N][3][64] accum -> z_r
__device__ __align__(256) float g_hsrc[(size_t)RMAX * NMAX * 64];   // h_src per relation
__device__ __align__(256) float g_el[RMAX * NMAX];                  // el per relation
__device__ __align__(256) float g_er[RMAX * NMAX];                  // er per relation
__device__ __align__(256) float g_den[RMAX * NMAX];                 // softmax denominators
__device__ __align__(256) float g_wpart[4];                         // semantic logit partials

// ---------- packed f32x2 helpers (sm_103a) ----------
__device__ __forceinline__ unsigned long long pack2(float a, float b) {
    unsigned long long r;
    asm("mov.b64 %0, {%1, %2};" : "=l"(r) : "f"(a), "f"(b));
    return r;
}
__device__ __forceinline__ void unpack2(unsigned long long v, float& a, float& b) {
    asm("mov.b64 {%0, %1}, %2;" : "=f"(a), "=f"(b) : "l"(v));
}
__device__ __forceinline__ void fma2(unsigned long long& d, unsigned long long a, unsigned long long b) {
    asm("fma.rn.f32x2 %0, %1, %2, %0;" : "+l"(d) : "l"(a), "l"(b));
}
__device__ __forceinline__ void red_add_v4(float* addr, float a, float b, float c, float d) {
    asm volatile("red.global.add.v4.f32 [%0], {%1, %2, %3, %4};"
                 :: "l"(addr), "f"(a), "f"(b), "f"(c), "f"(d) : "memory");
}
__device__ __forceinline__ float tanh_approx(float x) {
    float y;
    asm("tanh.approx.f32 %0, %1;" : "=f"(y) : "f"(x));
    return y;
}

// ---------- zero scratch ----------
__global__ void k_zero(int nz4, int nden) {
    int i = blockIdx.x * blockDim.x + threadIdx.x;
    int stride = gridDim.x * blockDim.x;
    float4* z4 = (float4*)g_z;
    float4 zv = make_float4(0.f, 0.f, 0.f, 0.f);
    for (int j = i; j < nz4; j += stride) z4[j] = zv;
    for (int j = i; j < nden; j += stride) g_den[j] = 0.f;
    if (i < 4) g_wpart[i] = 0.f;
}

// ---------- merged GEMM: 4 segments (seg 0 = dst path, seg 1..3 = src paths) ----------
// Register-blocked: each thread computes 4 rows x 16 cols. 4 lanes (col groups)
// cover 64 cols; each LDS of W serves 4 rows (and is multicast across row-groups).
__global__ __launch_bounds__(256) void k_gemm(
    const float* __restrict__ dst_feat, const float* __restrict__ neigh,
    const float* __restrict__ Wt, const float* __restrict__ bt,
    const float* __restrict__ attn_l, const float* __restrict__ attn_r, int N)
{
    __shared__ __align__(16) float Ws[128 * 64];
    __shared__ float bs[64];
    __shared__ float as[3 * 64];
    int tid = threadIdx.x;
    int seg = blockIdx.y;

    const float* X;
    const float* W;
    const float* bias;
    const float* av;
    int n_av;
    if (seg == 0) {
        X = dst_feat; W = Wt; bias = bt; av = attn_r; n_av = 3;
    } else {
        int r = seg - 1;
        X = neigh + (size_t)r * N * 128;
        W = Wt + (size_t)(r + 1) * 128 * 64;
        bias = bt + (size_t)(r + 1) * 64;
        av = attn_l + (size_t)r * 64;
        n_av = 1;
    }

    const float4* W4 = (const float4*)W;
    float4* Ws4 = (float4*)Ws;
    #pragma unroll
    for (int i = 0; i < 8; i++) Ws4[tid + 256 * i] = W4[tid + 256 * i];
    if (tid < 64) bs[tid] = bias[tid];
    if (tid < n_av * 64) as[tid] = av[tid];
    __syncthreads();

    int cg = tid & 3;            // col group: cols cg*16 .. cg*16+15
    int rg = tid >> 2;           // row group: 4 rows
    int c0 = cg * 16;
    int row0 = blockIdx.x * 256 + rg * 4;

    unsigned long long acc[4][8];
    #pragma unroll
    for (int rb = 0; rb < 4; rb++)
        #pragma unroll
        for (int m = 0; m < 8; m++)
            acc[rb][m] = pack2(bs[c0 + 2 * m], bs[c0 + 2 * m + 1]);

    int rc0 = min(row0 + 0, N - 1);
    int rc1 = min(row0 + 1, N - 1);
    int rc2 = min(row0 + 2, N - 1);
    int rc3 = min(row0 + 3, N - 1);
    const float4* Xr0 = (const float4*)(X + (size_t)rc0 * 128);
    const float4* Xr1 = (const float4*)(X + (size_t)rc1 * 128);
    const float4* Xr2 = (const float4*)(X + (size_t)rc2 * 128);
    const float4* Xr3 = (const float4*)(X + (size_t)rc3 * 128);
    const float* Wb = Ws + c0;

    #pragma unroll 2
    for (int k0 = 0; k0 < 32; k0++) {
        float4 xv[4];
        xv[0] = Xr0[k0]; xv[1] = Xr1[k0]; xv[2] = Xr2[k0]; xv[3] = Xr3[k0];
        #pragma unroll
        for (int kk = 0; kk < 4; kk++) {
            const ulonglong2* wr = (const ulonglong2*)(Wb + (k0 * 4 + kk) * 64);
            ulonglong2 w0 = wr[0], w1 = wr[1], w2 = wr[2], w3 = wr[3];
            #pragma unroll
            for (int rb = 0; rb < 4; rb++) {
                float xs = (kk == 0) ? xv[rb].x : (kk == 1) ? xv[rb].y
                         : (kk == 2) ? xv[rb].z : xv[rb].w;
                unsigned long long xx = pack2(xs, xs);
                fma2(acc[rb][0], w0.x, xx); fma2(acc[rb][1], w0.y, xx);
                fma2(acc[rb][2], w1.x, xx); fma2(acc[rb][3], w1.y, xx);
                fma2(acc[rb][4], w2.x, xx); fma2(acc[rb][5], w2.y, xx);
                fma2(acc[rb][6], w3.x, xx); fma2(acc[rb][7], w3.y, xx);
            }
        }
    }

    #pragma unroll
    for (int rb = 0; rb < 4; rb++) {
        int row = row0 + rb;
        float h[16];
        #pragma unroll
        for (int m = 0; m < 8; m++) unpack2(acc[rb][m], h[2 * m], h[2 * m + 1]);

        if (seg > 0 && row < N) {
            float4* o4 = (float4*)(g_hsrc + ((size_t)(seg - 1) * N + row) * 64 + c0);
            #pragma unroll
            for (int q = 0; q < 4; q++)
                o4[q] = make_float4(h[4 * q], h[4 * q + 1], h[4 * q + 2], h[4 * q + 3]);
        }
        for (int v = 0; v < n_av; v++) {
            float e = 0.f;
            #pragma unroll
            for (int j = 0; j < 16; j++) e += h[j] * as[v * 64 + c0 + j];
            e += __shfl_xor_sync(0xffffffffu, e, 1);
            e += __shfl_xor_sync(0xffffffffu, e, 2);
            if (cg == 0 && row < N) {
                if (seg == 0) g_er[(size_t)v * N + row] = e;
                else          g_el[(size_t)(seg - 1) * N + row] = e;
            }
        }
    }
}

// ---------- merged edge pass over all 3 relations ----------
__global__ __launch_bounds__(256) void k_edge(
    const int* __restrict__ src, const int* __restrict__ dst, int N, int E)
{
    int t = blockIdx.x * blockDim.x + threadIdx.x;
    int g = t >> 4;
    int lane = t & 15;
    int gsz = (gridDim.x * blockDim.x) >> 4;
    const float4* h4 = (const float4*)g_hsrc;
    int E2 = 2 * E, E3 = 3 * E;

    for (int e = g; e < E3; e += gsz) {
        int r = (e >= E2) ? 2 : (e >= E) ? 1 : 0;
        int s = __ldg(&src[e]);
        int d = __ldg(&dst[e]);
        float x = __ldg(&g_el[(size_t)r * N + s]) + __ldg(&g_er[(size_t)r * N + d]);
        float lr = x > 0.f ? x : 0.01f * x;
        float p = __expf(lr);
        float4 v = __ldg(&h4[((size_t)r * N + s) * 16 + lane]);
        float* addr = g_z + (size_t)d * 192 + r * 64 + lane * 4;
        red_add_v4(addr, p * v.x, p * v.y, p * v.z, p * v.w);
        if (lane == 0) atomicAdd(&g_den[(size_t)r * N + d], p);
    }
}

// ---------- finalize: z = elu(num/den); fused semantic logits, 8 items/warp ----------
__global__ __launch_bounds__(128) void k_finalize(
    const float* __restrict__ W1, const float* __restrict__ b1,
    const float* __restrict__ w2, int N)
{
    __shared__ __align__(16) float W1s[64 * 128];   // 32 KB
    __shared__ float b1s[128], w2s[128];
    __shared__ float zb[4][8][64];                  // 8 KB
    __shared__ float wsum[4][3];
    int tid = threadIdx.x, wid = tid >> 5, lane = tid & 31;
    const float4* W14 = (const float4*)W1;
    float4* W1s4 = (float4*)W1s;
    #pragma unroll
    for (int i = 0; i < 16; i++) W1s4[tid + 128 * i] = W14[tid + 128 * i];
    b1s[tid] = b1[tid];
    w2s[tid] = w2[tid];
    __syncthreads();

    int items = 3 * N, N2 = 2 * N;
    float t0 = 0.f, t1 = 0.f, t2 = 0.f;
    const ulonglong2* Wp = (const ulonglong2*)W1s;
    int stride = gridDim.x * 32;

    for (int item0 = blockIdx.x * 32 + wid * 8; item0 < items; item0 += stride) {
        int rs[8]; bool val[8];
        #pragma unroll
        for (int b = 0; b < 8; b++) {
            int item = item0 + b;
            val[b] = item < items;
            int it = val[b] ? item : 0;
            int r = (it >= N2) ? 2 : (it >= N) ? 1 : 0;
            rs[b] = r;
            int row = it - r * N;
            float* zr = g_z + (size_t)row * 192 + r * 64;
            float den = g_den[(size_t)r * N + row];
            float dinv = den > 0.f ? 1.f / den : 0.f;  // zero-degree -> elu(0)=0
            float z0 = zr[lane] * dinv;
            float z1 = zr[32 + lane] * dinv;
            z0 = z0 > 0.f ? z0 : expm1f(z0);
            z1 = z1 > 0.f ? z1 : expm1f(z1);
            if (val[b]) { zr[lane] = z0; zr[32 + lane] = z1; }
            zb[wid][b][lane] = z0;
            zb[wid][b][32 + lane] = z1;
        }
        __syncwarp();

        unsigned long long a01[8], a23[8];
        #pragma unroll
        for (int b = 0; b < 8; b++) {
            a01[b] = pack2(b1s[4 * lane], b1s[4 * lane + 1]);
            a23[b] = pack2(b1s[4 * lane + 2], b1s[4 * lane + 3]);
        }
        #pragma unroll 4
        for (int i = 0; i < 64; i++) {
            ulonglong2 w = Wp[i * 32 + lane];
            #pragma unroll
            for (int b = 0; b < 8; b++) {
                float zi = zb[wid][b][i];
                unsigned long long zz = pack2(zi, zi);
                fma2(a01[b], w.x, zz);
                fma2(a23[b], w.y, zz);
            }
        }

        #pragma unroll
        for (int b = 0; b < 8; b++) {
            if (!val[b]) continue;
            float h0, h1, h2, h3;
            unpack2(a01[b], h0, h1);
            unpack2(a23[b], h2, h3);
            h0 = tanh_approx(h0); h1 = tanh_approx(h1);
            h2 = tanh_approx(h2); h3 = tanh_approx(h3);
            float tv = h0 * w2s[4 * lane] + h1 * w2s[4 * lane + 1]
                     + h2 * w2s[4 * lane + 2] + h3 * w2s[4 * lane + 3];
            int r = rs[b];
            if (r == 0) t0 += tv; else if (r == 1) t1 += tv; else t2 += tv;
        }
        __syncwarp();
    }

    #pragma unroll
    for (int o = 16; o; o >>= 1) {
        t0 += __shfl_xor_sync(0xffffffffu, t0, o);
        t1 += __shfl_xor_sync(0xffffffffu, t1, o);
        t2 += __shfl_xor_sync(0xffffffffu, t2, o);
    }
    if (lane == 0) { wsum[wid][0] = t0; wsum[wid][1] = t1; wsum[wid][2] = t2; }
    __syncthreads();
    if (tid < 3) {
        float s = 0.f;
        #pragma unroll
        for (int w = 0; w < 4; w++) s += wsum[w][tid];
        atomicAdd(&g_wpart[tid], s);
    }
}

// ---------- semantic softmax + mix ----------
__global__ void k_mix(float* __restrict__ out, int N, float invN) {
    float w0 = g_wpart[0] * invN, w1 = g_wpart[1] * invN, w2v = g_wpart[2] * invN;
    float m = fmaxf(w0, fmaxf(w1, w2v));
    float e0 = __expf(w0 - m), e1 = __expf(w1 - m), e2 = __expf(w2v - m);
    float si = 1.f / (e0 + e1 + e2);
    float a0 = e0 * si, a1 = e1 * si, a2 = e2 * si;

    const float4* z4 = (const float4*)g_z;
    float4* o4 = (float4*)out;
    int total = N * 16;
    int i = blockIdx.x * blockDim.x + threadIdx.x;
    int stride = gridDim.x * blockDim.x;
    for (int idx = i; idx < total; idx += stride) {
        int n = idx >> 4, q = idx & 15;
        float4 v0 = z4[(size_t)n * 48 + q];
        float4 v1 = z4[(size_t)n * 48 + 16 + q];
        float4 v2 = z4[(size_t)n * 48 + 32 + q];
        float4 o;
        o.x = a0 * v0.x + a1 * v1.x + a2 * v2.x;
        o.y = a0 * v0.y + a1 * v1.y + a2 * v2.y;
        o.z = a0 * v0.z + a1 * v1.z + a2 * v2.z;
        o.w = a0 * v0.w + a1 * v1.w + a2 * v2.w;
        o4[idx] = o;
    }
}

extern "C" void kernel_launch(void* const* d_in, const int* in_sizes, int n_in,
                              void* d_out, int out_size) {
    const float* dst_feat = (const float*)d_in[0];
    const float* neigh    = (const float*)d_in[1];
    const float* Wt       = (const float*)d_in[2];
    const float* bt       = (const float*)d_in[3];
    const float* attn_l   = (const float*)d_in[4];
    const float* attn_r   = (const float*)d_in[5];
    const float* W1       = (const float*)d_in[6];
    const float* b1       = (const float*)d_in[7];
    const float* w2       = (const float*)d_in[8];
    const int*   src      = (const int*)d_in[9];
    const int*   dst      = (const int*)d_in[10];

    int N = in_sizes[0] / 128;          // 100000
    int E = in_sizes[9] / 3;            // 1000000
    (void)n_in; (void)out_size;

    k_zero<<<2048, 256>>>(N * 48, 3 * N);

    dim3 ggrid((N + 255) / 256, 4);
    k_gemm<<<ggrid, 256>>>(dst_feat, neigh, Wt, bt, attn_l, attn_r, N);

    k_edge<<<3552, 256>>>(src, dst, N, E);

    k_finalize<<<1184, 128>>>(W1, b1, w2, N);

    k_mix<<<1024, 256>>>((float*)d_out, N, 1.0f / (float)N);
}

// round 4
// speedup vs baseline: 1.4867x; 1.0237x over previous
#include <cuda_runtime.h>
#include <math.h>

#define NMAX 100000
#define RMAX 3

// Scratch (device globals; no allocation allowed)
__device__ __align__(256) float g_z[(size_t)NMAX * 192];            // [N][3][64] accum -> z_r
__device__ __align__(256) float g_hsrc[(size_t)RMAX * NMAX * 64];   // h_src per relation
__device__ __align__(256) float g_el[RMAX * NMAX];                  // el per relation
__device__ __align__(256) float g_er[RMAX * NMAX];                  // er per relation
__device__ __align__(256) float g_den[RMAX * NMAX];                 // softmax denominators
__device__ __align__(256) float g_wpart[4];                         // semantic logit partials

// ---------- packed f32x2 helpers (sm_103a) ----------
__device__ __forceinline__ unsigned long long pack2(float a, float b) {
    unsigned long long r;
    asm("mov.b64 %0, {%1, %2};" : "=l"(r) : "f"(a), "f"(b));
    return r;
}
__device__ __forceinline__ void unpack2(unsigned long long v, float& a, float& b) {
    asm("mov.b64 {%0, %1}, %2;" : "=f"(a), "=f"(b) : "l"(v));
}
__device__ __forceinline__ void fma2(unsigned long long& d, unsigned long long a, unsigned long long b) {
    asm("fma.rn.f32x2 %0, %1, %2, %0;" : "+l"(d) : "l"(a), "l"(b));
}
__device__ __forceinline__ void red_add_v4(float* addr, float a, float b, float c, float d) {
    asm volatile("red.global.add.v4.f32 [%0], {%1, %2, %3, %4};"
                 :: "l"(addr), "f"(a), "f"(b), "f"(c), "f"(d) : "memory");
}
__device__ __forceinline__ float tanh_approx(float x) {
    float y;
    asm("tanh.approx.f32 %0, %1;" : "=f"(y) : "f"(x));
    return y;
}

// ---------- merged GEMM: 4 segments (seg 0 = dst path, seg 1..3 = src paths) ----------
// Register-blocked: each thread computes 4 rows x 16 cols.
__global__ __launch_bounds__(256) void k_gemm(
    const float* __restrict__ dst_feat, const float* __restrict__ neigh,
    const float* __restrict__ Wt, const float* __restrict__ bt,
    const float* __restrict__ attn_l, const float* __restrict__ attn_r, int N)
{
    __shared__ __align__(16) float Ws[128 * 64];
    __shared__ float bs[64];
    __shared__ float as[3 * 64];
    int tid = threadIdx.x;
    int seg = blockIdx.y;

    const float* X;
    const float* W;
    const float* bias;
    const float* av;
    int n_av;
    if (seg == 0) {
        X = dst_feat; W = Wt; bias = bt; av = attn_r; n_av = 3;
    } else {
        int r = seg - 1;
        X = neigh + (size_t)r * N * 128;
        W = Wt + (size_t)(r + 1) * 128 * 64;
        bias = bt + (size_t)(r + 1) * 64;
        av = attn_l + (size_t)r * 64;
        n_av = 1;
    }

    const float4* W4 = (const float4*)W;
    float4* Ws4 = (float4*)Ws;
    #pragma unroll
    for (int i = 0; i < 8; i++) Ws4[tid + 256 * i] = W4[tid + 256 * i];
    if (tid < 64) bs[tid] = bias[tid];
    if (tid < n_av * 64) as[tid] = av[tid];
    __syncthreads();

    int cg = tid & 3;            // col group: cols cg*16 .. cg*16+15
    int rg = tid >> 2;           // row group: 4 rows
    int c0 = cg * 16;
    int row0 = blockIdx.x * 256 + rg * 4;

    unsigned long long acc[4][8];
    #pragma unroll
    for (int rb = 0; rb < 4; rb++)
        #pragma unroll
        for (int m = 0; m < 8; m++)
            acc[rb][m] = pack2(bs[c0 + 2 * m], bs[c0 + 2 * m + 1]);

    int rc0 = min(row0 + 0, N - 1);
    int rc1 = min(row0 + 1, N - 1);
    int rc2 = min(row0 + 2, N - 1);
    int rc3 = min(row0 + 3, N - 1);
    const float4* Xr0 = (const float4*)(X + (size_t)rc0 * 128);
    const float4* Xr1 = (const float4*)(X + (size_t)rc1 * 128);
    const float4* Xr2 = (const float4*)(X + (size_t)rc2 * 128);
    const float4* Xr3 = (const float4*)(X + (size_t)rc3 * 128);
    const float* Wb = Ws + c0;

    #pragma unroll 2
    for (int k0 = 0; k0 < 32; k0++) {
        float4 xv[4];
        xv[0] = Xr0[k0]; xv[1] = Xr1[k0]; xv[2] = Xr2[k0]; xv[3] = Xr3[k0];
        #pragma unroll
        for (int kk = 0; kk < 4; kk++) {
            const ulonglong2* wr = (const ulonglong2*)(Wb + (k0 * 4 + kk) * 64);
            ulonglong2 w0 = wr[0], w1 = wr[1], w2 = wr[2], w3 = wr[3];
            #pragma unroll
            for (int rb = 0; rb < 4; rb++) {
                float xs = (kk == 0) ? xv[rb].x : (kk == 1) ? xv[rb].y
                         : (kk == 2) ? xv[rb].z : xv[rb].w;
                unsigned long long xx = pack2(xs, xs);
                fma2(acc[rb][0], w0.x, xx); fma2(acc[rb][1], w0.y, xx);
                fma2(acc[rb][2], w1.x, xx); fma2(acc[rb][3], w1.y, xx);
                fma2(acc[rb][4], w2.x, xx); fma2(acc[rb][5], w2.y, xx);
                fma2(acc[rb][6], w3.x, xx); fma2(acc[rb][7], w3.y, xx);
            }
        }
    }

    #pragma unroll
    for (int rb = 0; rb < 4; rb++) {
        int row = row0 + rb;
        float h[16];
        #pragma unroll
        for (int m = 0; m < 8; m++) unpack2(acc[rb][m], h[2 * m], h[2 * m + 1]);

        if (seg > 0 && row < N) {
            float4* o4 = (float4*)(g_hsrc + ((size_t)(seg - 1) * N + row) * 64 + c0);
            #pragma unroll
            for (int q = 0; q < 4; q++)
                o4[q] = make_float4(h[4 * q], h[4 * q + 1], h[4 * q + 2], h[4 * q + 3]);
        }
        for (int v = 0; v < n_av; v++) {
            float e = 0.f;
            #pragma unroll
            for (int j = 0; j < 16; j++) e += h[j] * as[v * 64 + c0 + j];
            e += __shfl_xor_sync(0xffffffffu, e, 1);
            e += __shfl_xor_sync(0xffffffffu, e, 2);
            if (cg == 0 && row < N) {
                if (seg == 0) g_er[(size_t)v * N + row] = e;
                else          g_el[(size_t)(seg - 1) * N + row] = e;
            }
        }
    }
}

// ---------- merged edge pass over all 3 relations ----------
__global__ __launch_bounds__(256) void k_edge(
    const int* __restrict__ src, const int* __restrict__ dst, int N, int E)
{
    int t = blockIdx.x * blockDim.x + threadIdx.x;
    int g = t >> 4;
    int lane = t & 15;
    int gsz = (gridDim.x * blockDim.x) >> 4;
    const float4* h4 = (const float4*)g_hsrc;
    int E2 = 2 * E, E3 = 3 * E;

    for (int e = g; e < E3; e += gsz) {
        int r = (e >= E2) ? 2 : (e >= E) ? 1 : 0;
        int s = __ldg(&src[e]);
        int d = __ldg(&dst[e]);
        float x = __ldg(&g_el[(size_t)r * N + s]) + __ldg(&g_er[(size_t)r * N + d]);
        float lr = x > 0.f ? x : 0.01f * x;
        float p = __expf(lr);
        float4 v = __ldg(&h4[((size_t)r * N + s) * 16 + lane]);
        float* addr = g_z + (size_t)d * 192 + r * 64 + lane * 4;
        red_add_v4(addr, p * v.x, p * v.y, p * v.z, p * v.w);
        if (lane == 0) atomicAdd(&g_den[(size_t)r * N + d], p);
    }
}

// ---------- finalize: z = elu(num/den); fused semantic logits ----------
// 8 items/warp, zb pre-packed u64 (no per-iter MOVs), software-pipelined tile loads.
__global__ __launch_bounds__(128) void k_finalize(
    const float* __restrict__ W1, const float* __restrict__ b1,
    const float* __restrict__ w2, int N)
{
    __shared__ __align__(16) float W1s[64 * 128];               // 32 KB
    __shared__ float b1s[128], w2s[128];
    __shared__ __align__(16) unsigned long long zb[4][8][64];   // 16 KB
    __shared__ float wsum[4][3];
    int tid = threadIdx.x, wid = tid >> 5, lane = tid & 31;
    const float4* W14 = (const float4*)W1;
    float4* W1s4 = (float4*)W1s;
    #pragma unroll
    for (int i = 0; i < 16; i++) W1s4[tid + 128 * i] = W14[tid + 128 * i];
    b1s[tid] = b1[tid];
    w2s[tid] = w2[tid];
    __syncthreads();

    int items = 3 * N, N2 = 2 * N;
    float t0 = 0.f, t1 = 0.f, t2 = 0.f;
    const ulonglong2* Wp = (const ulonglong2*)W1s;
    int stride = gridDim.x * 32;

    int item0 = blockIdx.x * 32 + wid * 8;
    float pz0[8], pz1[8], pden[8];
    // initial prefetch
    #pragma unroll
    for (int b = 0; b < 8; b++) {
        int it = item0 + b;
        bool v = it < items;
        int iu = v ? it : 0;
        int r = (iu >= N2) ? 2 : (iu >= N) ? 1 : 0;
        int row = iu - r * N;
        const float* zr = g_z + (size_t)row * 192 + r * 64;
        pz0[b]  = v ? zr[lane] : 0.f;
        pz1[b]  = v ? zr[32 + lane] : 0.f;
        pden[b] = v ? g_den[(size_t)r * N + row] : 1.f;
    }

    for (; item0 < items; item0 += stride) {
        int rs[8]; bool val[8];
        // stage current tile: elu(num/den) -> g_z writeback + packed smem
        #pragma unroll
        for (int b = 0; b < 8; b++) {
            int it = item0 + b;
            val[b] = it < items;
            int iu = val[b] ? it : 0;
            int r = (iu >= N2) ? 2 : (iu >= N) ? 1 : 0;
            rs[b] = r;
            int row = iu - r * N;
            float den = pden[b];
            float dinv = den > 0.f ? 1.f / den : 0.f;   // zero-degree -> elu(0)=0
            float z0 = pz0[b] * dinv;
            float z1 = pz1[b] * dinv;
            z0 = z0 > 0.f ? z0 : (__expf(z0) - 1.f);
            z1 = z1 > 0.f ? z1 : (__expf(z1) - 1.f);
            if (val[b]) {
                float* zr = g_z + (size_t)row * 192 + r * 64;
                zr[lane] = z0;
                zr[32 + lane] = z1;
            }
            zb[wid][b][lane] = pack2(z0, z0);
            zb[wid][b][32 + lane] = pack2(z1, z1);
        }
        // prefetch next tile (overlaps with GEMM below)
        int nx = item0 + stride;
        #pragma unroll
        for (int b = 0; b < 8; b++) {
            int it = nx + b;
            bool v = it < items;
            int iu = v ? it : 0;
            int r = (iu >= N2) ? 2 : (iu >= N) ? 1 : 0;
            int row = iu - r * N;
            const float* zr = g_z + (size_t)row * 192 + r * 64;
            pz0[b]  = v ? zr[lane] : 0.f;
            pz1[b]  = v ? zr[32 + lane] : 0.f;
            pden[b] = v ? g_den[(size_t)r * N + row] : 1.f;
        }
        __syncwarp();

        unsigned long long a01[8], a23[8];
        #pragma unroll
        for (int b = 0; b < 8; b++) {
            a01[b] = pack2(b1s[4 * lane], b1s[4 * lane + 1]);
            a23[b] = pack2(b1s[4 * lane + 2], b1s[4 * lane + 3]);
        }
        #pragma unroll 4
        for (int i = 0; i < 64; i++) {
            ulonglong2 w = Wp[i * 32 + lane];
            #pragma unroll
            for (int b = 0; b < 8; b++) {
                unsigned long long zz = zb[wid][b][i];
                fma2(a01[b], w.x, zz);
                fma2(a23[b], w.y, zz);
            }
        }

        #pragma unroll
        for (int b = 0; b < 8; b++) {
            if (!val[b]) continue;
            float h0, h1, h2, h3;
            unpack2(a01[b], h0, h1);
            unpack2(a23[b], h2, h3);
            h0 = tanh_approx(h0); h1 = tanh_approx(h1);
            h2 = tanh_approx(h2); h3 = tanh_approx(h3);
            float tv = h0 * w2s[4 * lane] + h1 * w2s[4 * lane + 1]
                     + h2 * w2s[4 * lane + 2] + h3 * w2s[4 * lane + 3];
            int r = rs[b];
            if (r == 0) t0 += tv; else if (r == 1) t1 += tv; else t2 += tv;
        }
        __syncwarp();
    }

    #pragma unroll
    for (int o = 16; o; o >>= 1) {
        t0 += __shfl_xor_sync(0xffffffffu, t0, o);
        t1 += __shfl_xor_sync(0xffffffffu, t1, o);
        t2 += __shfl_xor_sync(0xffffffffu, t2, o);
    }
    if (lane == 0) { wsum[wid][0] = t0; wsum[wid][1] = t1; wsum[wid][2] = t2; }
    __syncthreads();
    if (tid < 3) {
        float s = 0.f;
        #pragma unroll
        for (int w = 0; w < 4; w++) s += wsum[w][tid];
        atomicAdd(&g_wpart[tid], s);
    }
}

// ---------- semantic softmax + mix ----------
__global__ void k_mix(float* __restrict__ out, int N, float invN) {
    float w0 = g_wpart[0] * invN, w1 = g_wpart[1] * invN, w2v = g_wpart[2] * invN;
    float m = fmaxf(w0, fmaxf(w1, w2v));
    float e0 = __expf(w0 - m), e1 = __expf(w1 - m), e2 = __expf(w2v - m);
    float si = 1.f / (e0 + e1 + e2);
    float a0 = e0 * si, a1 = e1 * si, a2 = e2 * si;

    const float4* z4 = (const float4*)g_z;
    float4* o4 = (float4*)out;
    int total = N * 16;
    int i = blockIdx.x * blockDim.x + threadIdx.x;
    int stride = gridDim.x * blockDim.x;
    for (int idx = i; idx < total; idx += stride) {
        int n = idx >> 4, q = idx & 15;
        float4 v0 = z4[(size_t)n * 48 + q];
        float4 v1 = z4[(size_t)n * 48 + 16 + q];
        float4 v2 = z4[(size_t)n * 48 + 32 + q];
        float4 o;
        o.x = a0 * v0.x + a1 * v1.x + a2 * v2.x;
        o.y = a0 * v0.y + a1 * v1.y + a2 * v2.y;
        o.z = a0 * v0.z + a1 * v1.z + a2 * v2.z;
        o.w = a0 * v0.w + a1 * v1.w + a2 * v2.w;
        o4[idx] = o;
    }
}

extern "C" void kernel_launch(void* const* d_in, const int* in_sizes, int n_in,
                              void* d_out, int out_size) {
    const float* dst_feat = (const float*)d_in[0];
    const float* neigh    = (const float*)d_in[1];
    const float* Wt       = (const float*)d_in[2];
    const float* bt       = (const float*)d_in[3];
    const float* attn_l   = (const float*)d_in[4];
    const float* attn_r   = (const float*)d_in[5];
    const float* W1       = (const float*)d_in[6];
    const float* b1       = (const float*)d_in[7];
    const float* w2       = (const float*)d_in[8];
    const int*   src      = (const int*)d_in[9];
    const int*   dst      = (const int*)d_in[10];

    int N = in_sizes[0] / 128;          // 100000
    int E = in_sizes[9] / 3;            // 1000000
    (void)n_in; (void)out_size;

    // zero scratch via memset nodes (graph-capturable, faster than a kernel)
    void* zp = nullptr; void* dp = nullptr; void* wp = nullptr;
    cudaGetSymbolAddress(&zp, g_z);
    cudaGetSymbolAddress(&dp, g_den);
    cudaGetSymbolAddress(&wp, g_wpart);
    cudaMemsetAsync(zp, 0, (size_t)N * 192 * sizeof(float));
    cudaMemsetAsync(dp, 0, (size_t)3 * N * sizeof(float));
    cudaMemsetAsync(wp, 0, 4 * sizeof(float));

    dim3 ggrid((N + 255) / 256, 4);
    k_gemm<<<ggrid, 256>>>(dst_feat, neigh, Wt, bt, attn_l, attn_r, N);

    k_edge<<<3552, 256>>>(src, dst, N, E);

    k_finalize<<<1184, 128>>>(W1, b1, w2, N);

    k_mix<<<1024, 256>>>((float*)d_out, N, 1.0f / (float)N);
}

// round 5
// speedup vs baseline: 1.5014x; 1.0099x over previous
#include <cuda_runtime.h>
#include <math.h>

#define NMAX 100000
#define RMAX 3

// Scratch (device globals; no allocation allowed)
__device__ __align__(256) float g_z[(size_t)NMAX * 192];            // [N][3][64] accum -> z_r
__device__ __align__(256) float g_hsrc[(size_t)RMAX * NMAX * 64];   // h_src per relation
__device__ __align__(256) float g_el[RMAX * NMAX];                  // el per relation
__device__ __align__(256) float g_er[RMAX * NMAX];                  // er per relation
__device__ __align__(256) float g_den[RMAX * NMAX];                 // softmax denominators
__device__ __align__(256) float g_wpart[4];                         // semantic logit partials

// ---------- packed f32x2 helpers (sm_103a) ----------
__device__ __forceinline__ unsigned long long pack2(float a, float b) {
    unsigned long long r;
    asm("mov.b64 %0, {%1, %2};" : "=l"(r) : "f"(a), "f"(b));
    return r;
}
__device__ __forceinline__ void unpack2(unsigned long long v, float& a, float& b) {
    asm("mov.b64 {%0, %1}, %2;" : "=f"(a), "=f"(b) : "l"(v));
}
__device__ __forceinline__ void fma2(unsigned long long& d, unsigned long long a, unsigned long long b) {
    asm("fma.rn.f32x2 %0, %1, %2, %0;" : "+l"(d) : "l"(a), "l"(b));
}
__device__ __forceinline__ void red_add_v4(float* addr, float a, float b, float c, float d) {
    asm volatile("red.global.add.v4.f32 [%0], {%1, %2, %3, %4};"
                 :: "l"(addr), "f"(a), "f"(b), "f"(c), "f"(d) : "memory");
}
__device__ __forceinline__ float tanh_approx(float x) {
    float y;
    asm("tanh.approx.f32 %0, %1;" : "=f"(y) : "f"(x));
    return y;
}

// ---------- merged GEMM: 4 segments (seg 0 = dst path, seg 1..3 = src paths) ----------
// Warp tile = 16 rows x 64 cols: cg = tid&7 (8 cols each), rg = tid>>3 (4 rows each).
// Each X LDG.128 touches only 4 lines/warp (4 row-groups) -> 8x fewer L1 wavefronts.
__global__ __launch_bounds__(256) void k_gemm(
    const float* __restrict__ dst_feat, const float* __restrict__ neigh,
    const float* __restrict__ Wt, const float* __restrict__ bt,
    const float* __restrict__ attn_l, const float* __restrict__ attn_r, int N)
{
    __shared__ __align__(16) float Ws[128 * 64];
    __shared__ float bs[64];
    __shared__ float as[3 * 64];
    int tid = threadIdx.x;
    int seg = blockIdx.y;

    const float* X;
    const float* W;
    const float* bias;
    const float* av;
    int n_av;
    if (seg == 0) {
        X = dst_feat; W = Wt; bias = bt; av = attn_r; n_av = 3;
    } else {
        int r = seg - 1;
        X = neigh + (size_t)r * N * 128;
        W = Wt + (size_t)(r + 1) * 128 * 64;
        bias = bt + (size_t)(r + 1) * 64;
        av = attn_l + (size_t)r * 64;
        n_av = 1;
    }

    const float4* W4 = (const float4*)W;
    float4* Ws4 = (float4*)Ws;
    #pragma unroll
    for (int i = 0; i < 8; i++) Ws4[tid + 256 * i] = W4[tid + 256 * i];
    if (tid < 64) bs[tid] = bias[tid];
    if (tid < n_av * 64) as[tid] = av[tid];
    __syncthreads();

    int cg = tid & 7;            // col group: cols cg*8 .. cg*8+7
    int rg = tid >> 3;           // row group: 4 rows
    int c0 = cg * 8;
    int row0 = blockIdx.x * 128 + rg * 4;

    unsigned long long acc[4][4];
    #pragma unroll
    for (int rb = 0; rb < 4; rb++)
        #pragma unroll
        for (int m = 0; m < 4; m++)
            acc[rb][m] = pack2(bs[c0 + 2 * m], bs[c0 + 2 * m + 1]);

    int rc0 = min(row0 + 0, N - 1);
    int rc1 = min(row0 + 1, N - 1);
    int rc2 = min(row0 + 2, N - 1);
    int rc3 = min(row0 + 3, N - 1);
    const float4* Xr0 = (const float4*)(X + (size_t)rc0 * 128);
    const float4* Xr1 = (const float4*)(X + (size_t)rc1 * 128);
    const float4* Xr2 = (const float4*)(X + (size_t)rc2 * 128);
    const float4* Xr3 = (const float4*)(X + (size_t)rc3 * 128);
    const float* Wb = Ws + c0;

    #pragma unroll 2
    for (int k0 = 0; k0 < 32; k0++) {
        float4 xv[4];
        xv[0] = Xr0[k0]; xv[1] = Xr1[k0]; xv[2] = Xr2[k0]; xv[3] = Xr3[k0];
        #pragma unroll
        for (int kk = 0; kk < 4; kk++) {
            const ulonglong2* wr = (const ulonglong2*)(Wb + (k0 * 4 + kk) * 64);
            ulonglong2 w0 = wr[0], w1 = wr[1];
            #pragma unroll
            for (int rb = 0; rb < 4; rb++) {
                float xs = (kk == 0) ? xv[rb].x : (kk == 1) ? xv[rb].y
                         : (kk == 2) ? xv[rb].z : xv[rb].w;
                unsigned long long xx = pack2(xs, xs);
                fma2(acc[rb][0], w0.x, xx); fma2(acc[rb][1], w0.y, xx);
                fma2(acc[rb][2], w1.x, xx); fma2(acc[rb][3], w1.y, xx);
            }
        }
    }

    #pragma unroll
    for (int rb = 0; rb < 4; rb++) {
        int row = row0 + rb;
        float h[8];
        #pragma unroll
        for (int m = 0; m < 4; m++) unpack2(acc[rb][m], h[2 * m], h[2 * m + 1]);

        if (seg > 0 && row < N) {
            float4* o4 = (float4*)(g_hsrc + ((size_t)(seg - 1) * N + row) * 64 + c0);
            o4[0] = make_float4(h[0], h[1], h[2], h[3]);
            o4[1] = make_float4(h[4], h[5], h[6], h[7]);
        }
        for (int v = 0; v < n_av; v++) {
            float e = 0.f;
            #pragma unroll
            for (int j = 0; j < 8; j++) e += h[j] * as[v * 64 + c0 + j];
            e += __shfl_xor_sync(0xffffffffu, e, 1);
            e += __shfl_xor_sync(0xffffffffu, e, 2);
            e += __shfl_xor_sync(0xffffffffu, e, 4);
            if (cg == 0 && row < N) {
                if (seg == 0) g_er[(size_t)v * N + row] = e;
                else          g_el[(size_t)(seg - 1) * N + row] = e;
            }
        }
    }
}

// ---------- merged edge pass over all 3 relations ----------
__global__ __launch_bounds__(256) void k_edge(
    const int* __restrict__ src, const int* __restrict__ dst, int N, int E)
{
    int t = blockIdx.x * blockDim.x + threadIdx.x;
    int g = t >> 4;
    int lane = t & 15;
    int gsz = (gridDim.x * blockDim.x) >> 4;
    const float4* h4 = (const float4*)g_hsrc;
    int E2 = 2 * E, E3 = 3 * E;

    for (int e = g; e < E3; e += gsz) {
        int r = (e >= E2) ? 2 : (e >= E) ? 1 : 0;
        int s = __ldg(&src[e]);
        int d = __ldg(&dst[e]);
        float x = __ldg(&g_el[(size_t)r * N + s]) + __ldg(&g_er[(size_t)r * N + d]);
        float lr = x > 0.f ? x : 0.01f * x;
        float p = __expf(lr);
        float4 v = __ldg(&h4[((size_t)r * N + s) * 16 + lane]);
        float* addr = g_z + (size_t)d * 192 + r * 64 + lane * 4;
        red_add_v4(addr, p * v.x, p * v.y, p * v.z, p * v.w);
        if (lane == 0) atomicAdd(&g_den[(size_t)r * N + d], p);
    }
}

// ---------- finalize: z = elu(num/den); fused semantic logits ----------
// 8 items/warp, zb pre-packed u64, software-pipelined tile loads.
__global__ __launch_bounds__(128) void k_finalize(
    const float* __restrict__ W1, const float* __restrict__ b1,
    const float* __restrict__ w2, int N)
{
    __shared__ __align__(16) float W1s[64 * 128];               // 32 KB
    __shared__ float b1s[128], w2s[128];
    __shared__ __align__(16) unsigned long long zb[4][8][64];   // 16 KB
    __shared__ float wsum[4][3];
    int tid = threadIdx.x, wid = tid >> 5, lane = tid & 31;
    const float4* W14 = (const float4*)W1;
    float4* W1s4 = (float4*)W1s;
    #pragma unroll
    for (int i = 0; i < 16; i++) W1s4[tid + 128 * i] = W14[tid + 128 * i];
    b1s[tid] = b1[tid];
    w2s[tid] = w2[tid];
    __syncthreads();

    int items = 3 * N, N2 = 2 * N;
    float t0 = 0.f, t1 = 0.f, t2 = 0.f;
    const ulonglong2* Wp = (const ulonglong2*)W1s;
    int stride = gridDim.x * 32;

    int item0 = blockIdx.x * 32 + wid * 8;
    float pz0[8], pz1[8], pden[8];
    #pragma unroll
    for (int b = 0; b < 8; b++) {
        int it = item0 + b;
        bool v = it < items;
        int iu = v ? it : 0;
        int r = (iu >= N2) ? 2 : (iu >= N) ? 1 : 0;
        int row = iu - r * N;
        const float* zr = g_z + (size_t)row * 192 + r * 64;
        pz0[b]  = v ? zr[lane] : 0.f;
        pz1[b]  = v ? zr[32 + lane] : 0.f;
        pden[b] = v ? g_den[(size_t)r * N + row] : 1.f;
    }

    for (; item0 < items; item0 += stride) {
        int rs[8]; bool val[8];
        #pragma unroll
        for (int b = 0; b < 8; b++) {
            int it = item0 + b;
            val[b] = it < items;
            int iu = val[b] ? it : 0;
            int r = (iu >= N2) ? 2 : (iu >= N) ? 1 : 0;
            rs[b] = r;
            int row = iu - r * N;
            float den = pden[b];
            float dinv = den > 0.f ? 1.f / den : 0.f;   // zero-degree -> elu(0)=0
            float z0 = pz0[b] * dinv;
            float z1 = pz1[b] * dinv;
            z0 = z0 > 0.f ? z0 : (__expf(z0) - 1.f);
            z1 = z1 > 0.f ? z1 : (__expf(z1) - 1.f);
            if (val[b]) {
                float* zr = g_z + (size_t)row * 192 + r * 64;
                zr[lane] = z0;
                zr[32 + lane] = z1;
            }
            zb[wid][b][lane] = pack2(z0, z0);
            zb[wid][b][32 + lane] = pack2(z1, z1);
        }
        int nx = item0 + stride;
        #pragma unroll
        for (int b = 0; b < 8; b++) {
            int it = nx + b;
            bool v = it < items;
            int iu = v ? it : 0;
            int r = (iu >= N2) ? 2 : (iu >= N) ? 1 : 0;
            int row = iu - r * N;
            const float* zr = g_z + (size_t)row * 192 + r * 64;
            pz0[b]  = v ? zr[lane] : 0.f;
            pz1[b]  = v ? zr[32 + lane] : 0.f;
            pden[b] = v ? g_den[(size_t)r * N + row] : 1.f;
        }
        __syncwarp();

        unsigned long long a01[8], a23[8];
        #pragma unroll
        for (int b = 0; b < 8; b++) {
            a01[b] = pack2(b1s[4 * lane], b1s[4 * lane + 1]);
            a23[b] = pack2(b1s[4 * lane + 2], b1s[4 * lane + 3]);
        }
        #pragma unroll 4
        for (int i = 0; i < 64; i++) {
            ulonglong2 w = Wp[i * 32 + lane];
            #pragma unroll
            for (int b = 0; b < 8; b++) {
                unsigned long long zz = zb[wid][b][i];
                fma2(a01[b], w.x, zz);
                fma2(a23[b], w.y, zz);
            }
        }

        #pragma unroll
        for (int b = 0; b < 8; b++) {
            if (!val[b]) continue;
            float h0, h1, h2, h3;
            unpack2(a01[b], h0, h1);
            unpack2(a23[b], h2, h3);
            h0 = tanh_approx(h0); h1 = tanh_approx(h1);
            h2 = tanh_approx(h2); h3 = tanh_approx(h3);
            float tv = h0 * w2s[4 * lane] + h1 * w2s[4 * lane + 1]
                     + h2 * w2s[4 * lane + 2] + h3 * w2s[4 * lane + 3];
            int r = rs[b];
            if (r == 0) t0 += tv; else if (r == 1) t1 += tv; else t2 += tv;
        }
        __syncwarp();
    }

    #pragma unroll
    for (int o = 16; o; o >>= 1) {
        t0 += __shfl_xor_sync(0xffffffffu, t0, o);
        t1 += __shfl_xor_sync(0xffffffffu, t1, o);
        t2 += __shfl_xor_sync(0xffffffffu, t2, o);
    }
    if (lane == 0) { wsum[wid][0] = t0; wsum[wid][1] = t1; wsum[wid][2] = t2; }
    __syncthreads();
    if (tid < 3) {
        float s = 0.f;
        #pragma unroll
        for (int w = 0; w < 4; w++) s += wsum[w][tid];
        atomicAdd(&g_wpart[tid], s);
    }
}

// ---------- semantic softmax + mix ----------
__global__ void k_mix(float* __restrict__ out, int N, float invN) {
    float w0 = g_wpart[0] * invN, w1 = g_wpart[1] * invN, w2v = g_wpart[2] * invN;
    float m = fmaxf(w0, fmaxf(w1, w2v));
    float e0 = __expf(w0 - m), e1 = __expf(w1 - m), e2 = __expf(w2v - m);
    float si = 1.f / (e0 + e1 + e2);
    float a0 = e0 * si, a1 = e1 * si, a2 = e2 * si;

    const float4* z4 = (const float4*)g_z;
    float4* o4 = (float4*)out;
    int total = N * 16;
    int i = blockIdx.x * blockDim.x + threadIdx.x;
    int stride = gridDim.x * blockDim.x;
    for (int idx = i; idx < total; idx += stride) {
        int n = idx >> 4, q = idx & 15;
        float4 v0 = z4[(size_t)n * 48 + q];
        float4 v1 = z4[(size_t)n * 48 + 16 + q];
        float4 v2 = z4[(size_t)n * 48 + 32 + q];
        float4 o;
        o.x = a0 * v0.x + a1 * v1.x + a2 * v2.x;
        o.y = a0 * v0.y + a1 * v1.y + a2 * v2.y;
        o.z = a0 * v0.z + a1 * v1.z + a2 * v2.z;
        o.w = a0 * v0.w + a1 * v1.w + a2 * v2.w;
        o4[idx] = o;
    }
}

extern "C" void kernel_launch(void* const* d_in, const int* in_sizes, int n_in,
                              void* d_out, int out_size) {
    const float* dst_feat = (const float*)d_in[0];
    const float* neigh    = (const float*)d_in[1];
    const float* Wt       = (const float*)d_in[2];
    const float* bt       = (const float*)d_in[3];
    const float* attn_l   = (const float*)d_in[4];
    const float* attn_r   = (const float*)d_in[5];
    const float* W1       = (const float*)d_in[6];
    const float* b1       = (const float*)d_in[7];
    const float* w2       = (const float*)d_in[8];
    const int*   src      = (const int*)d_in[9];
    const int*   dst      = (const int*)d_in[10];

    int N = in_sizes[0] / 128;          // 100000
    int E = in_sizes[9] / 3;            // 1000000
    (void)n_in; (void)out_size;

    // zero scratch via memset nodes (graph-capturable)
    void* zp = nullptr; void* dp = nullptr; void* wp = nullptr;
    cudaGetSymbolAddress(&zp, g_z);
    cudaGetSymbolAddress(&dp, g_den);
    cudaGetSymbolAddress(&wp, g_wpart);
    cudaMemsetAsync(zp, 0, (size_t)N * 192 * sizeof(float));
    cudaMemsetAsync(dp, 0, (size_t)3 * N * sizeof(float));
    cudaMemsetAsync(wp, 0, 4 * sizeof(float));

    dim3 ggrid((N + 127) / 128, 4);
    k_gemm<<<ggrid, 256>>>(dst_feat, neigh, Wt, bt, attn_l, attn_r, N);

    k_edge<<<3552, 256>>>(src, dst, N, E);

    k_finalize<<<1184, 128>>>(W1, b1, w2, N);

    k_mix<<<1024, 256>>>((float*)d_out, N, 1.0f / (float)N);
}

// round 7
// speedup vs baseline: 1.5219x; 1.0137x over previous
#include <cuda_runtime.h>
#include <cuda_fp16.h>
#include <math.h>
#include <string.h>

#define NMAX 100000
#define RMAX 3

// Scratch (device globals; no allocation allowed)
__device__ __align__(256) float g_z[(size_t)NMAX * 192];             // [N][3][64] accum -> z_r
__device__ __align__(256) __half g_hsrc[(size_t)RMAX * NMAX * 64];   // h_src per relation (fp16)
__device__ __align__(256) float g_el[RMAX * NMAX];                   // el per relation
__device__ __align__(256) float g_er[RMAX * NMAX];                   // er per relation
__device__ __align__(256) float g_den[RMAX * NMAX];                  // softmax denominators
__device__ __align__(256) float g_wpart[4];                          // semantic logit partials

// ---------- packed f32x2 helpers (sm_103a) ----------
__device__ __forceinline__ unsigned long long pack2(float a, float b) {
    unsigned long long r;
    asm("mov.b64 %0, {%1, %2};" : "=l"(r) : "f"(a), "f"(b));
    return r;
}
__device__ __forceinline__ void unpack2(unsigned long long v, float& a, float& b) {
    asm("mov.b64 {%0, %1}, %2;" : "=f"(a), "=f"(b) : "l"(v));
}
__device__ __forceinline__ void fma2(unsigned long long& d, unsigned long long a, unsigned long long b) {
    asm("fma.rn.f32x2 %0, %1, %2, %0;" : "+l"(d) : "l"(a), "l"(b));
}
__device__ __forceinline__ void red_add_v4(float* addr, float a, float b, float c, float d) {
    asm volatile("red.global.add.v4.f32 [%0], {%1, %2, %3, %4};"
                 :: "l"(addr), "f"(a), "f"(b), "f"(c), "f"(d) : "memory");
}
__device__ __forceinline__ float tanh_approx(float x) {
    float y;
    asm("tanh.approx.f32 %0, %1;" : "=f"(y) : "f"(x));
    return y;
}
__device__ __forceinline__ unsigned int h2_as_u32(__half2 h) {
    unsigned int u;
    memcpy(&u, &h, 4);
    return u;
}
__device__ __forceinline__ __half2 u32_as_h2(unsigned int u) {
    __half2 h;
    memcpy(&h, &u, 4);
    return h;
}

// ---------- merged GEMM: 4 segments (seg 0 = dst path, seg 1..3 = src paths) ----------
// Warp tile = 16 rows x 64 cols: cg = tid&7 (8 cols each), rg = tid>>3 (4 rows each).
__global__ __launch_bounds__(256) void k_gemm(
    const float* __restrict__ dst_feat, const float* __restrict__ neigh,
    const float* __restrict__ Wt, const float* __restrict__ bt,
    const float* __restrict__ attn_l, const float* __restrict__ attn_r, int N)
{
    __shared__ __align__(16) float Ws[128 * 64];
    __shared__ float bs[64];
    __shared__ float as[3 * 64];
    int tid = threadIdx.x;
    int seg = blockIdx.y;

    const float* X;
    const float* W;
    const float* bias;
    const float* av;
    int n_av;
    if (seg == 0) {
        X = dst_feat; W = Wt; bias = bt; av = attn_r; n_av = 3;
    } else {
        int r = seg - 1;
        X = neigh + (size_t)r * N * 128;
        W = Wt + (size_t)(r + 1) * 128 * 64;
        bias = bt + (size_t)(r + 1) * 64;
        av = attn_l + (size_t)r * 64;
        n_av = 1;
    }

    const float4* W4 = (const float4*)W;
    float4* Ws4 = (float4*)Ws;
    #pragma unroll
    for (int i = 0; i < 8; i++) Ws4[tid + 256 * i] = W4[tid + 256 * i];
    if (tid < 64) bs[tid] = bias[tid];
    if (tid < n_av * 64) as[tid] = av[tid];
    __syncthreads();

    int cg = tid & 7;            // col group: cols cg*8 .. cg*8+7
    int rg = tid >> 3;           // row group: 4 rows
    int c0 = cg * 8;
    int row0 = blockIdx.x * 128 + rg * 4;

    unsigned long long acc[4][4];
    #pragma unroll
    for (int rb = 0; rb < 4; rb++)
        #pragma unroll
        for (int m = 0; m < 4; m++)
            acc[rb][m] = pack2(bs[c0 + 2 * m], bs[c0 + 2 * m + 1]);

    int rc0 = min(row0 + 0, N - 1);
    int rc1 = min(row0 + 1, N - 1);
    int rc2 = min(row0 + 2, N - 1);
    int rc3 = min(row0 + 3, N - 1);
    const float4* Xr0 = (const float4*)(X + (size_t)rc0 * 128);
    const float4* Xr1 = (const float4*)(X + (size_t)rc1 * 128);
    const float4* Xr2 = (const float4*)(X + (size_t)rc2 * 128);
    const float4* Xr3 = (const float4*)(X + (size_t)rc3 * 128);
    const float* Wb = Ws + c0;

    #pragma unroll 2
    for (int k0 = 0; k0 < 32; k0++) {
        float4 xv[4];
        xv[0] = Xr0[k0]; xv[1] = Xr1[k0]; xv[2] = Xr2[k0]; xv[3] = Xr3[k0];
        #pragma unroll
        for (int kk = 0; kk < 4; kk++) {
            const ulonglong2* wr = (const ulonglong2*)(Wb + (k0 * 4 + kk) * 64);
            ulonglong2 w0 = wr[0], w1 = wr[1];
            #pragma unroll
            for (int rb = 0; rb < 4; rb++) {
                float xs = (kk == 0) ? xv[rb].x : (kk == 1) ? xv[rb].y
                         : (kk == 2) ? xv[rb].z : xv[rb].w;
                unsigned long long xx = pack2(xs, xs);
                fma2(acc[rb][0], w0.x, xx); fma2(acc[rb][1], w0.y, xx);
                fma2(acc[rb][2], w1.x, xx); fma2(acc[rb][3], w1.y, xx);
            }
        }
    }

    #pragma unroll
    for (int rb = 0; rb < 4; rb++) {
        int row = row0 + rb;
        float h[8];
        #pragma unroll
        for (int m = 0; m < 4; m++) unpack2(acc[rb][m], h[2 * m], h[2 * m + 1]);

        if (seg > 0 && row < N) {
            // store h as fp16 (16B per thread: 8 halves)
            uint4 pk;
            pk.x = h2_as_u32(__floats2half2_rn(h[0], h[1]));
            pk.y = h2_as_u32(__floats2half2_rn(h[2], h[3]));
            pk.z = h2_as_u32(__floats2half2_rn(h[4], h[5]));
            pk.w = h2_as_u32(__floats2half2_rn(h[6], h[7]));
            *(uint4*)(g_hsrc + ((size_t)(seg - 1) * N + row) * 64 + c0) = pk;
        }
        for (int v = 0; v < n_av; v++) {
            float e = 0.f;
            #pragma unroll
            for (int j = 0; j < 8; j++) e += h[j] * as[v * 64 + c0 + j];
            e += __shfl_xor_sync(0xffffffffu, e, 1);
            e += __shfl_xor_sync(0xffffffffu, e, 2);
            e += __shfl_xor_sync(0xffffffffu, e, 4);
            if (cg == 0 && row < N) {
                if (seg == 0) g_er[(size_t)v * N + row] = e;
                else          g_el[(size_t)(seg - 1) * N + row] = e;
            }
        }
    }
}

// ---------- merged edge pass over all 3 relations (fp16 h gather) ----------
__global__ __launch_bounds__(256) void k_edge(
    const int* __restrict__ src, const int* __restrict__ dst, int N, int E)
{
    int t = blockIdx.x * blockDim.x + threadIdx.x;
    int g = t >> 4;
    int lane = t & 15;
    int gsz = (gridDim.x * blockDim.x) >> 4;
    const uint2* h2 = (const uint2*)g_hsrc;    // 8B = 4 halves per lane
    int E2 = 2 * E, E3 = 3 * E;

    for (int e = g; e < E3; e += gsz) {
        int r = (e >= E2) ? 2 : (e >= E) ? 1 : 0;
        int s = __ldg(&src[e]);
        int d = __ldg(&dst[e]);
        float x = __ldg(&g_el[(size_t)r * N + s]) + __ldg(&g_er[(size_t)r * N + d]);
        float lr = x > 0.f ? x : 0.01f * x;
        float p = __expf(lr);
        uint2 v = __ldg(&h2[((size_t)r * N + s) * 16 + lane]);
        float2 f0 = __half22float2(u32_as_h2(v.x));
        float2 f1 = __half22float2(u32_as_h2(v.y));
        float* addr = g_z + (size_t)d * 192 + r * 64 + lane * 4;
        red_add_v4(addr, p * f0.x, p * f0.y, p * f1.x, p * f1.y);
        if (lane == 0) atomicAdd(&g_den[(size_t)r * N + d], p);
    }
}

// ---------- finalize: z = elu(num/den); fused semantic logits ----------
// 256-thread blocks sharing W1s; 8 items/warp; __launch_bounds__ forces 3 blocks/SM.
__global__ __launch_bounds__(256, 3) void k_finalize(
    const float* __restrict__ W1, const float* __restrict__ b1,
    const float* __restrict__ w2, int N)
{
    __shared__ __align__(16) float W1s[64 * 128];               // 32 KB
    __shared__ float b1s[128], w2s[128];
    __shared__ __align__(16) unsigned long long zb[8][8][64];   // 32 KB
    __shared__ float wsum[8][3];
    int tid = threadIdx.x, wid = tid >> 5, lane = tid & 31;
    const float4* W14 = (const float4*)W1;
    float4* W1s4 = (float4*)W1s;
    #pragma unroll
    for (int i = 0; i < 8; i++) W1s4[tid + 256 * i] = W14[tid + 256 * i];
    if (tid < 128) { b1s[tid] = b1[tid]; w2s[tid] = w2[tid]; }
    __syncthreads();

    int items = 3 * N, N2 = 2 * N;
    float t0 = 0.f, t1 = 0.f, t2 = 0.f;
    const ulonglong2* Wp = (const ulonglong2*)W1s;
    int stride = gridDim.x * 64;

    for (int item0 = blockIdx.x * 64 + wid * 8; item0 < items; item0 += stride) {
        int rs[8]; bool val[8];
        #pragma unroll
        for (int b = 0; b < 8; b++) {
            int it = item0 + b;
            val[b] = it < items;
            int iu = val[b] ? it : 0;
            int r = (iu >= N2) ? 2 : (iu >= N) ? 1 : 0;
            rs[b] = r;
            int row = iu - r * N;
            float* zr = g_z + (size_t)row * 192 + r * 64;
            float den = g_den[(size_t)r * N + row];
            float dinv = den > 0.f ? 1.f / den : 0.f;   // zero-degree -> elu(0)=0
            float z0 = zr[lane] * dinv;
            float z1 = zr[32 + lane] * dinv;
            z0 = z0 > 0.f ? z0 : (__expf(z0) - 1.f);
            z1 = z1 > 0.f ? z1 : (__expf(z1) - 1.f);
            if (val[b]) {
                zr[lane] = z0;
                zr[32 + lane] = z1;
            }
            zb[wid][b][lane] = pack2(z0, z0);
            zb[wid][b][32 + lane] = pack2(z1, z1);
        }
        __syncwarp();

        unsigned long long a01[8], a23[8];
        #pragma unroll
        for (int b = 0; b < 8; b++) {
            a01[b] = pack2(b1s[4 * lane], b1s[4 * lane + 1]);
            a23[b] = pack2(b1s[4 * lane + 2], b1s[4 * lane + 3]);
        }
        #pragma unroll 4
        for (int i = 0; i < 64; i++) {
            ulonglong2 w = Wp[i * 32 + lane];
            #pragma unroll
            for (int b = 0; b < 8; b++) {
                unsigned long long zz = zb[wid][b][i];
                fma2(a01[b], w.x, zz);
                fma2(a23[b], w.y, zz);
            }
        }

        #pragma unroll
        for (int b = 0; b < 8; b++) {
            if (!val[b]) continue;
            float h0, h1, h2v, h3;
            unpack2(a01[b], h0, h1);
            unpack2(a23[b], h2v, h3);
            h0 = tanh_approx(h0); h1 = tanh_approx(h1);
            h2v = tanh_approx(h2v); h3 = tanh_approx(h3);
            float tv = h0 * w2s[4 * lane] + h1 * w2s[4 * lane + 1]
                     + h2v * w2s[4 * lane + 2] + h3 * w2s[4 * lane + 3];
            int r = rs[b];
            if (r == 0) t0 += tv; else if (r == 1) t1 += tv; else t2 += tv;
        }
        __syncwarp();
    }

    #pragma unroll
    for (int o = 16; o; o >>= 1) {
        t0 += __shfl_xor_sync(0xffffffffu, t0, o);
        t1 += __shfl_xor_sync(0xffffffffu, t1, o);
        t2 += __shfl_xor_sync(0xffffffffu, t2, o);
    }
    if (lane == 0) { wsum[wid][0] = t0; wsum[wid][1] = t1; wsum[wid][2] = t2; }
    __syncthreads();
    if (tid < 3) {
        float s = 0.f;
        #pragma unroll
        for (int w = 0; w < 8; w++) s += wsum[w][tid];
        atomicAdd(&g_wpart[tid], s);
    }
}

// ---------- semantic softmax + mix ----------
__global__ void k_mix(float* __restrict__ out, int N, float invN) {
    float w0 = g_wpart[0] * invN, w1 = g_wpart[1] * invN, w2v = g_wpart[2] * invN;
    float m = fmaxf(w0, fmaxf(w1, w2v));
    float e0 = __expf(w0 - m), e1 = __expf(w1 - m), e2 = __expf(w2v - m);
    float si = 1.f / (e0 + e1 + e2);
    float a0 = e0 * si, a1 = e1 * si, a2 = e2 * si;

    const float4* z4 = (const float4*)g_z;
    float4* o4 = (float4*)out;
    int total = N * 16;
    int i = blockIdx.x * blockDim.x + threadIdx.x;
    int stride = gridDim.x * blockDim.x;
    for (int idx = i; idx < total; idx += stride) {
        int n = idx >> 4, q = idx & 15;
        float4 v0 = z4[(size_t)n * 48 + q];
        float4 v1 = z4[(size_t)n * 48 + 16 + q];
        float4 v2 = z4[(size_t)n * 48 + 32 + q];
        float4 o;
        o.x = a0 * v0.x + a1 * v1.x + a2 * v2.x;
        o.y = a0 * v0.y + a1 * v1.y + a2 * v2.y;
        o.z = a0 * v0.z + a1 * v1.z + a2 * v2.z;
        o.w = a0 * v0.w + a1 * v1.w + a2 * v2.w;
        o4[idx] = o;
    }
}

extern "C" void kernel_launch(void* const* d_in, const int* in_sizes, int n_in,
                              void* d_out, int out_size) {
    const float* dst_feat = (const float*)d_in[0];
    const float* neigh    = (const float*)d_in[1];
    const float* Wt       = (const float*)d_in[2];
    const float* bt       = (const float*)d_in[3];
    const float* attn_l   = (const float*)d_in[4];
    const float* attn_r   = (const float*)d_in[5];
    const float* W1       = (const float*)d_in[6];
    const float* b1       = (const float*)d_in[7];
    const float* w2       = (const float*)d_in[8];
    const int*   src      = (const int*)d_in[9];
    const int*   dst      = (const int*)d_in[10];

    int N = in_sizes[0] / 128;          // 100000
    int E = in_sizes[9] / 3;            // 1000000
    (void)n_in; (void)out_size;

    // zero scratch via memset nodes (graph-capturable)
    void* zp = nullptr; void* dp = nullptr; void* wp = nullptr;
    cudaGetSymbolAddress(&zp, g_z);
    cudaGetSymbolAddress(&dp, g_den);
    cudaGetSymbolAddress(&wp, g_wpart);
    cudaMemsetAsync(zp, 0, (size_t)N * 192 * sizeof(float));
    cudaMemsetAsync(dp, 0, (size_t)3 * N * sizeof(float));
    cudaMemsetAsync(wp, 0, 4 * sizeof(float));

    dim3 ggrid((N + 127) / 128, 4);
    k_gemm<<<ggrid, 256>>>(dst_feat, neigh, Wt, bt, attn_l, attn_r, N);

    k_edge<<<3552, 256>>>(src, dst, N, E);

    k_finalize<<<444, 256>>>(W1, b1, w2, N);

    k_mix<<<1024, 256>>>((float*)d_out, N, 1.0f / (float)N);
}

// round 8
// speedup vs baseline: 1.6450x; 1.0809x over previous
#include <cuda_runtime.h>
#include <cuda_fp16.h>
#include <math.h>
#include <string.h>

#define NMAX 100000
#define RMAX 3
#define EMAX 1000000

// Scratch (device globals; no allocation allowed)
__device__ __align__(256) float g_z[(size_t)NMAX * 192];             // [N][3][64] final z_r
__device__ __align__(256) __half g_hsrc[(size_t)RMAX * NMAX * 64];   // h_src per relation (fp16)
__device__ __align__(256) float g_el[RMAX * NMAX];                   // el per relation
__device__ __align__(256) float g_er[RMAX * NMAX];                   // er per relation
__device__ __align__(256) int   g_off[RMAX * NMAX + 1];              // CSR row offsets
__device__ __align__(256) int   g_cur[RMAX * NMAX];                  // counts -> fill cursors
__device__ __align__(256) int   g_csr[(size_t)RMAX * EMAX];          // CSR src indices
__device__ __align__(256) int   g_tsum[256];                         // scan tile sums
__device__ __align__(256) float g_wpart[4];                          // semantic logit partials

// ---------- packed f32x2 helpers (sm_103a) ----------
__device__ __forceinline__ unsigned long long pack2(float a, float b) {
    unsigned long long r;
    asm("mov.b64 %0, {%1, %2};" : "=l"(r) : "f"(a), "f"(b));
    return r;
}
__device__ __forceinline__ void unpack2(unsigned long long v, float& a, float& b) {
    asm("mov.b64 {%0, %1}, %2;" : "=f"(a), "=f"(b) : "l"(v));
}
__device__ __forceinline__ void fma2(unsigned long long& d, unsigned long long a, unsigned long long b) {
    asm("fma.rn.f32x2 %0, %1, %2, %0;" : "+l"(d) : "l"(a), "l"(b));
}
__device__ __forceinline__ float tanh_approx(float x) {
    float y;
    asm("tanh.approx.f32 %0, %1;" : "=f"(y) : "f"(x));
    return y;
}
__device__ __forceinline__ unsigned int h2_as_u32(__half2 h) {
    unsigned int u;
    memcpy(&u, &h, 4);
    return u;
}
__device__ __forceinline__ __half2 u32_as_h2(unsigned int u) {
    __half2 h;
    memcpy(&h, &u, 4);
    return h;
}

// ---------- merged GEMM: 4 segments (seg 0 = dst path, seg 1..3 = src paths) ----------
__global__ __launch_bounds__(256) void k_gemm(
    const float* __restrict__ dst_feat, const float* __restrict__ neigh,
    const float* __restrict__ Wt, const float* __restrict__ bt,
    const float* __restrict__ attn_l, const float* __restrict__ attn_r, int N)
{
    __shared__ __align__(16) float Ws[128 * 64];
    __shared__ float bs[64];
    __shared__ float as[3 * 64];
    int tid = threadIdx.x;
    int seg = blockIdx.y;

    const float* X;
    const float* W;
    const float* bias;
    const float* av;
    int n_av;
    if (seg == 0) {
        X = dst_feat; W = Wt; bias = bt; av = attn_r; n_av = 3;
    } else {
        int r = seg - 1;
        X = neigh + (size_t)r * N * 128;
        W = Wt + (size_t)(r + 1) * 128 * 64;
        bias = bt + (size_t)(r + 1) * 64;
        av = attn_l + (size_t)r * 64;
        n_av = 1;
    }

    const float4* W4 = (const float4*)W;
    float4* Ws4 = (float4*)Ws;
    #pragma unroll
    for (int i = 0; i < 8; i++) Ws4[tid + 256 * i] = W4[tid + 256 * i];
    if (tid < 64) bs[tid] = bias[tid];
    if (tid < n_av * 64) as[tid] = av[tid];
    __syncthreads();

    int cg = tid & 7;            // col group: cols cg*8 .. cg*8+7
    int rg = tid >> 3;           // row group: 4 rows
    int c0 = cg * 8;
    int row0 = blockIdx.x * 128 + rg * 4;

    unsigned long long acc[4][4];
    #pragma unroll
    for (int rb = 0; rb < 4; rb++)
        #pragma unroll
        for (int m = 0; m < 4; m++)
            acc[rb][m] = pack2(bs[c0 + 2 * m], bs[c0 + 2 * m + 1]);

    int rc0 = min(row0 + 0, N - 1);
    int rc1 = min(row0 + 1, N - 1);
    int rc2 = min(row0 + 2, N - 1);
    int rc3 = min(row0 + 3, N - 1);
    const float4* Xr0 = (const float4*)(X + (size_t)rc0 * 128);
    const float4* Xr1 = (const float4*)(X + (size_t)rc1 * 128);
    const float4* Xr2 = (const float4*)(X + (size_t)rc2 * 128);
    const float4* Xr3 = (const float4*)(X + (size_t)rc3 * 128);
    const float* Wb = Ws + c0;

    #pragma unroll 2
    for (int k0 = 0; k0 < 32; k0++) {
        float4 xv[4];
        xv[0] = Xr0[k0]; xv[1] = Xr1[k0]; xv[2] = Xr2[k0]; xv[3] = Xr3[k0];
        #pragma unroll
        for (int kk = 0; kk < 4; kk++) {
            const ulonglong2* wr = (const ulonglong2*)(Wb + (k0 * 4 + kk) * 64);
            ulonglong2 w0 = wr[0], w1 = wr[1];
            #pragma unroll
            for (int rb = 0; rb < 4; rb++) {
                float xs = (kk == 0) ? xv[rb].x : (kk == 1) ? xv[rb].y
                         : (kk == 2) ? xv[rb].z : xv[rb].w;
                unsigned long long xx = pack2(xs, xs);
                fma2(acc[rb][0], w0.x, xx); fma2(acc[rb][1], w0.y, xx);
                fma2(acc[rb][2], w1.x, xx); fma2(acc[rb][3], w1.y, xx);
            }
        }
    }

    #pragma unroll
    for (int rb = 0; rb < 4; rb++) {
        int row = row0 + rb;
        float h[8];
        #pragma unroll
        for (int m = 0; m < 4; m++) unpack2(acc[rb][m], h[2 * m], h[2 * m + 1]);

        if (seg > 0 && row < N) {
            uint4 pk;
            pk.x = h2_as_u32(__floats2half2_rn(h[0], h[1]));
            pk.y = h2_as_u32(__floats2half2_rn(h[2], h[3]));
            pk.z = h2_as_u32(__floats2half2_rn(h[4], h[5]));
            pk.w = h2_as_u32(__floats2half2_rn(h[6], h[7]));
            *(uint4*)(g_hsrc + ((size_t)(seg - 1) * N + row) * 64 + c0) = pk;
        }
        for (int v = 0; v < n_av; v++) {
            float e = 0.f;
            #pragma unroll
            for (int j = 0; j < 8; j++) e += h[j] * as[v * 64 + c0 + j];
            e += __shfl_xor_sync(0xffffffffu, e, 1);
            e += __shfl_xor_sync(0xffffffffu, e, 2);
            e += __shfl_xor_sync(0xffffffffu, e, 4);
            if (cg == 0 && row < N) {
                if (seg == 0) g_er[(size_t)v * N + row] = e;
                else          g_el[(size_t)(seg - 1) * N + row] = e;
            }
        }
    }
}

// ---------- CSR build: histogram ----------
__global__ void k_hist(const int* __restrict__ dst, int N, int E, int E2, int E3) {
    int i = blockIdx.x * blockDim.x + threadIdx.x;
    int st = gridDim.x * blockDim.x;
    for (int e = i; e < E3; e += st) {
        int r = (e >= E2) ? 2 : (e >= E) ? 1 : 0;
        atomicAdd(&g_cur[r * N + __ldg(&dst[e])], 1);
    }
}

// ---------- scan stage A: per-tile (2048) exclusive scan ----------
__global__ void k_scanA(int n) {
    __shared__ int sd[256];
    int tid = threadIdx.x;
    int base = blockIdx.x * 2048 + tid * 8;
    int c[8], pre[8];
    int s = 0;
    #pragma unroll
    for (int i = 0; i < 8; i++) c[i] = (base + i < n) ? g_cur[base + i] : 0;
    #pragma unroll
    for (int i = 0; i < 8; i++) { pre[i] = s; s += c[i]; }
    sd[tid] = s;
    __syncthreads();
    for (int o = 1; o < 256; o <<= 1) {
        int v = (tid >= o) ? sd[tid - o] : 0;
        __syncthreads();
        sd[tid] += v;
        __syncthreads();
    }
    int excl = sd[tid] - s;
    #pragma unroll
    for (int i = 0; i < 8; i++)
        if (base + i < n) g_off[base + i] = excl + pre[i];
    if (tid == 255) g_tsum[blockIdx.x] = sd[255];
}

// ---------- scan stage B: exclusive scan of tile sums (single block) ----------
__global__ void k_scanB(int nt) {
    __shared__ int sd[256];
    int tid = threadIdx.x;
    int v = (tid < nt) ? g_tsum[tid] : 0;
    sd[tid] = v;
    __syncthreads();
    for (int o = 1; o < 256; o <<= 1) {
        int x = (tid >= o) ? sd[tid - o] : 0;
        __syncthreads();
        sd[tid] += x;
        __syncthreads();
    }
    if (tid < nt) g_tsum[tid] = sd[tid] - v;
}

// ---------- scan stage C: add tile offsets; copy to cursors; set sentinel ----------
__global__ void k_scanC(int n, int total) {
    int i = blockIdx.x * blockDim.x + threadIdx.x;
    int st = gridDim.x * blockDim.x;
    for (int j = i; j < n; j += st) {
        int o = g_off[j] + g_tsum[j >> 11];
        g_off[j] = o;
        g_cur[j] = o;
    }
    if (i == 0) g_off[n] = total;
}

// ---------- CSR fill ----------
__global__ void k_fill(const int* __restrict__ src, const int* __restrict__ dst,
                       int N, int E, int E2, int E3) {
    int i = blockIdx.x * blockDim.x + threadIdx.x;
    int st = gridDim.x * blockDim.x;
    for (int e = i; e < E3; e += st) {
        int r = (e >= E2) ? 2 : (e >= E) ? 1 : 0;
        int idx = r * N + __ldg(&dst[e]);
        int pos = atomicAdd(&g_cur[idx], 1);
        g_csr[pos] = __ldg(&src[e]);
    }
}

// ---------- aggregate: per (r,dst) gather + softmax-normalize + elu ----------
__global__ __launch_bounds__(256) void k_agg(int N) {
    int t = blockIdx.x * blockDim.x + threadIdx.x;
    int g = t >> 4;
    int lane = t & 15;
    int gsz = (gridDim.x * blockDim.x) >> 4;
    int items = 3 * N, N2 = 2 * N;
    const uint2* h2 = (const uint2*)g_hsrc;

    for (int item = g; item < items; item += gsz) {
        int r = (item >= N2) ? 2 : (item >= N) ? 1 : 0;
        int d = item - r * N;
        float er = __ldg(&g_er[item]);          // g_er layout is [r][row] == item
        int j0 = __ldg(&g_off[item]);
        int j1 = __ldg(&g_off[item + 1]);
        float a0 = 0.f, a1 = 0.f, a2 = 0.f, a3 = 0.f, den = 0.f;
        const float* elr = g_el + (size_t)r * N;
        const uint2* hr = h2 + (size_t)r * N * 16 + lane;
        for (int j = j0; j < j1; j++) {
            int s = __ldg(&g_csr[j]);
            float x = __ldg(&elr[s]) + er;
            float lr = x > 0.f ? x : 0.01f * x;
            float p = __expf(lr);
            uint2 v = __ldg(&hr[(size_t)s * 16]);
            float2 f0 = __half22float2(u32_as_h2(v.x));
            float2 f1 = __half22float2(u32_as_h2(v.y));
            a0 += p * f0.x; a1 += p * f0.y; a2 += p * f1.x; a3 += p * f1.y;
            den += p;
        }
        float dinv = den > 0.f ? 1.f / den : 0.f;   // zero-degree -> elu(0)=0
        a0 *= dinv; a1 *= dinv; a2 *= dinv; a3 *= dinv;
        a0 = a0 > 0.f ? a0 : (__expf(a0) - 1.f);
        a1 = a1 > 0.f ? a1 : (__expf(a1) - 1.f);
        a2 = a2 > 0.f ? a2 : (__expf(a2) - 1.f);
        a3 = a3 > 0.f ? a3 : (__expf(a3) - 1.f);
        *(float4*)(g_z + (size_t)d * 192 + r * 64 + lane * 4) =
            make_float4(a0, a1, a2, a3);
    }
}

// ---------- finalize: semantic logits only (z already final) ----------
__global__ __launch_bounds__(256, 3) void k_finalize(
    const float* __restrict__ W1, const float* __restrict__ b1,
    const float* __restrict__ w2, int N)
{
    __shared__ __align__(16) float W1s[64 * 128];               // 32 KB
    __shared__ float b1s[128], w2s[128];
    __shared__ __align__(16) unsigned long long zb[8][8][64];   // 32 KB
    __shared__ float wsum[8][3];
    int tid = threadIdx.x, wid = tid >> 5, lane = tid & 31;
    const float4* W14 = (const float4*)W1;
    float4* W1s4 = (float4*)W1s;
    #pragma unroll
    for (int i = 0; i < 8; i++) W1s4[tid + 256 * i] = W14[tid + 256 * i];
    if (tid < 128) { b1s[tid] = b1[tid]; w2s[tid] = w2[tid]; }
    __syncthreads();

    int items = 3 * N, N2 = 2 * N;
    float t0 = 0.f, t1 = 0.f, t2 = 0.f;
    const ulonglong2* Wp = (const ulonglong2*)W1s;
    int stride = gridDim.x * 64;

    for (int item0 = blockIdx.x * 64 + wid * 8; item0 < items; item0 += stride) {
        int rs[8]; bool val[8];
        #pragma unroll
        for (int b = 0; b < 8; b++) {
            int it = item0 + b;
            val[b] = it < items;
            int iu = val[b] ? it : 0;
            int r = (iu >= N2) ? 2 : (iu >= N) ? 1 : 0;
            rs[b] = r;
            int row = iu - r * N;
            const float* zr = g_z + (size_t)row * 192 + r * 64;
            float z0 = zr[lane];
            float z1 = zr[32 + lane];
            zb[wid][b][lane] = pack2(z0, z0);
            zb[wid][b][32 + lane] = pack2(z1, z1);
        }
        __syncwarp();

        unsigned long long a01[8], a23[8];
        #pragma unroll
        for (int b = 0; b < 8; b++) {
            a01[b] = pack2(b1s[4 * lane], b1s[4 * lane + 1]);
            a23[b] = pack2(b1s[4 * lane + 2], b1s[4 * lane + 3]);
        }
        #pragma unroll 4
        for (int i = 0; i < 64; i++) {
            ulonglong2 w = Wp[i * 32 + lane];
            #pragma unroll
            for (int b = 0; b < 8; b++) {
                unsigned long long zz = zb[wid][b][i];
                fma2(a01[b], w.x, zz);
                fma2(a23[b], w.y, zz);
            }
        }

        #pragma unroll
        for (int b = 0; b < 8; b++) {
            if (!val[b]) continue;
            float h0, h1, h2v, h3;
            unpack2(a01[b], h0, h1);
            unpack2(a23[b], h2v, h3);
            h0 = tanh_approx(h0); h1 = tanh_approx(h1);
            h2v = tanh_approx(h2v); h3 = tanh_approx(h3);
            float tv = h0 * w2s[4 * lane] + h1 * w2s[4 * lane + 1]
                     + h2v * w2s[4 * lane + 2] + h3 * w2s[4 * lane + 3];
            int r = rs[b];
            if (r == 0) t0 += tv; else if (r == 1) t1 += tv; else t2 += tv;
        }
        __syncwarp();
    }

    #pragma unroll
    for (int o = 16; o; o >>= 1) {
        t0 += __shfl_xor_sync(0xffffffffu, t0, o);
        t1 += __shfl_xor_sync(0xffffffffu, t1, o);
        t2 += __shfl_xor_sync(0xffffffffu, t2, o);
    }
    if (lane == 0) { wsum[wid][0] = t0; wsum[wid][1] = t1; wsum[wid][2] = t2; }
    __syncthreads();
    if (tid < 3) {
        float s = 0.f;
        #pragma unroll
        for (int w = 0; w < 8; w++) s += wsum[w][tid];
        atomicAdd(&g_wpart[tid], s);
    }
}

// ---------- semantic softmax + mix ----------
__global__ void k_mix(float* __restrict__ out, int N, float invN) {
    float w0 = g_wpart[0] * invN, w1 = g_wpart[1] * invN, w2v = g_wpart[2] * invN;
    float m = fmaxf(w0, fmaxf(w1, w2v));
    float e0 = __expf(w0 - m), e1 = __expf(w1 - m), e2 = __expf(w2v - m);
    float si = 1.f / (e0 + e1 + e2);
    float a0 = e0 * si, a1 = e1 * si, a2 = e2 * si;

    const float4* z4 = (const float4*)g_z;
    float4* o4 = (float4*)out;
    int total = N * 16;
    int i = blockIdx.x * blockDim.x + threadIdx.x;
    int stride = gridDim.x * blockDim.x;
    for (int idx = i; idx < total; idx += stride) {
        int n = idx >> 4, q = idx & 15;
        float4 v0 = z4[(size_t)n * 48 + q];
        float4 v1 = z4[(size_t)n * 48 + 16 + q];
        float4 v2 = z4[(size_t)n * 48 + 32 + q];
        float4 o;
        o.x = a0 * v0.x + a1 * v1.x + a2 * v2.x;
        o.y = a0 * v0.y + a1 * v1.y + a2 * v2.y;
        o.z = a0 * v0.z + a1 * v1.z + a2 * v2.z;
        o.w = a0 * v0.w + a1 * v1.w + a2 * v2.w;
        o4[idx] = o;
    }
}

extern "C" void kernel_launch(void* const* d_in, const int* in_sizes, int n_in,
                              void* d_out, int out_size) {
    const float* dst_feat = (const float*)d_in[0];
    const float* neigh    = (const float*)d_in[1];
    const float* Wt       = (const float*)d_in[2];
    const float* bt       = (const float*)d_in[3];
    const float* attn_l   = (const float*)d_in[4];
    const float* attn_r   = (const float*)d_in[5];
    const float* W1       = (const float*)d_in[6];
    const float* b1       = (const float*)d_in[7];
    const float* w2       = (const float*)d_in[8];
    const int*   src      = (const int*)d_in[9];
    const int*   dst      = (const int*)d_in[10];

    int N = in_sizes[0] / 128;          // 100000
    int E = in_sizes[9] / 3;            // 1000000
    int E2 = 2 * E, E3 = 3 * E;
    int n3 = 3 * N;
    int nTiles = (n3 + 2047) / 2048;    // 147 for N=100000
    (void)n_in; (void)out_size;

    // zero counters (graph-capturable memset nodes)
    void* cp = nullptr; void* wp = nullptr;
    cudaGetSymbolAddress(&cp, g_cur);
    cudaGetSymbolAddress(&wp, g_wpart);
    cudaMemsetAsync(cp, 0, (size_t)n3 * sizeof(int));
    cudaMemsetAsync(wp, 0, 4 * sizeof(float));

    // CSR build
    k_hist<<<1184, 256>>>(dst, N, E, E2, E3);
    k_scanA<<<nTiles, 256>>>(n3);
    k_scanB<<<1, 256>>>(nTiles);
    k_scanC<<<(n3 + 255) / 256, 256>>>(n3, E3);
    k_fill<<<1184, 256>>>(src, dst, N, E, E2, E3);

    // node-level GEMMs
    dim3 ggrid((N + 127) / 128, 4);
    k_gemm<<<ggrid, 256>>>(dst_feat, neigh, Wt, bt, attn_l, attn_r, N);

    // per-destination gather aggregation (no atomics)
    k_agg<<<1184, 256>>>(N);

    k_finalize<<<444, 256>>>(W1, b1, w2, N);

    k_mix<<<1024, 256>>>((float*)d_out, N, 1.0f / (float)N);
}

// round 9
// speedup vs baseline: 1.7137x; 1.0417x over previous
#include <cuda_runtime.h>
#include <cuda_fp16.h>
#include <math.h>
#include <string.h>

#define NMAX 100000
#define RMAX 3
#define EMAX 1000000

// Scratch (device globals; no allocation allowed)
__device__ __align__(256) float g_z[(size_t)NMAX * 192];             // [N][3][64] final z_r
__device__ __align__(256) __half g_hsrc[(size_t)RMAX * NMAX * 64];   // h_src per relation (fp16)
__device__ __align__(256) float g_el[RMAX * NMAX];                   // el per relation
__device__ __align__(256) float g_er[RMAX * NMAX];                   // er per relation
__device__ __align__(256) int   g_off[RMAX * NMAX + 1];              // CSR row offsets
__device__ __align__(256) int   g_cur[RMAX * NMAX];                  // counts -> fill cursors
__device__ __align__(256) int   g_csr[(size_t)RMAX * EMAX];          // CSR src indices
__device__ __align__(256) int   g_tsum[256];                         // scan tile sums
__device__ __align__(256) float g_wpart[4];                          // semantic logit partials

// ---------- packed f32x2 helpers (sm_103a) ----------
__device__ __forceinline__ unsigned long long pack2(float a, float b) {
    unsigned long long r;
    asm("mov.b64 %0, {%1, %2};" : "=l"(r) : "f"(a), "f"(b));
    return r;
}
__device__ __forceinline__ void unpack2(unsigned long long v, float& a, float& b) {
    asm("mov.b64 {%0, %1}, %2;" : "=f"(a), "=f"(b) : "l"(v));
}
__device__ __forceinline__ void fma2(unsigned long long& d, unsigned long long a, unsigned long long b) {
    asm("fma.rn.f32x2 %0, %1, %2, %0;" : "+l"(d) : "l"(a), "l"(b));
}
__device__ __forceinline__ float tanh_approx(float x) {
    float y;
    asm("tanh.approx.f32 %0, %1;" : "=f"(y) : "f"(x));
    return y;
}
__device__ __forceinline__ unsigned int h2_as_u32(__half2 h) {
    unsigned int u;
    memcpy(&u, &h, 4);
    return u;
}
__device__ __forceinline__ __half2 u32_as_h2(unsigned int u) {
    __half2 h;
    memcpy(&h, &u, 4);
    return h;
}

// ---------- merged GEMM + CSR-fill launch ----------
// blockIdx.y in 0..3: GEMM segments (seg 0 = dst path, seg 1..3 = src paths).
// blockIdx.y == 4:   CSR fill workers (independent of GEMM, overlaps it).
__global__ __launch_bounds__(256) void k_gemm_fill(
    const float* __restrict__ dst_feat, const float* __restrict__ neigh,
    const float* __restrict__ Wt, const float* __restrict__ bt,
    const float* __restrict__ attn_l, const float* __restrict__ attn_r,
    const int* __restrict__ src, const int* __restrict__ dst,
    int N, int E, int E2, int E3)
{
    __shared__ __align__(16) float Ws[128 * 64];
    __shared__ float bs[64];
    __shared__ float as[3 * 64];
    int tid = threadIdx.x;
    int seg = blockIdx.y;

    if (seg == 4) {
        // ---- CSR fill path ----
        int i = blockIdx.x * 256 + tid;
        int st = gridDim.x * 256;
        for (int e = i; e < E3; e += st) {
            int r = (e >= E2) ? 2 : (e >= E) ? 1 : 0;
            int idx = r * N + __ldg(&dst[e]);
            int pos = atomicAdd(&g_cur[idx], 1);
            g_csr[pos] = __ldg(&src[e]);
        }
        return;
    }

    const float* X;
    const float* W;
    const float* bias;
    const float* av;
    int n_av;
    if (seg == 0) {
        X = dst_feat; W = Wt; bias = bt; av = attn_r; n_av = 3;
    } else {
        int r = seg - 1;
        X = neigh + (size_t)r * N * 128;
        W = Wt + (size_t)(r + 1) * 128 * 64;
        bias = bt + (size_t)(r + 1) * 64;
        av = attn_l + (size_t)r * 64;
        n_av = 1;
    }

    const float4* W4 = (const float4*)W;
    float4* Ws4 = (float4*)Ws;
    #pragma unroll
    for (int i = 0; i < 8; i++) Ws4[tid + 256 * i] = W4[tid + 256 * i];
    if (tid < 64) bs[tid] = bias[tid];
    if (tid < n_av * 64) as[tid] = av[tid];
    __syncthreads();

    int cg = tid & 7;            // col group: cols cg*8 .. cg*8+7
    int rg = tid >> 3;           // row group: 4 rows
    int c0 = cg * 8;
    int row0 = blockIdx.x * 128 + rg * 4;

    unsigned long long acc[4][4];
    #pragma unroll
    for (int rb = 0; rb < 4; rb++)
        #pragma unroll
        for (int m = 0; m < 4; m++)
            acc[rb][m] = pack2(bs[c0 + 2 * m], bs[c0 + 2 * m + 1]);

    int rc0 = min(row0 + 0, N - 1);
    int rc1 = min(row0 + 1, N - 1);
    int rc2 = min(row0 + 2, N - 1);
    int rc3 = min(row0 + 3, N - 1);
    const float4* Xr0 = (const float4*)(X + (size_t)rc0 * 128);
    const float4* Xr1 = (const float4*)(X + (size_t)rc1 * 128);
    const float4* Xr2 = (const float4*)(X + (size_t)rc2 * 128);
    const float4* Xr3 = (const float4*)(X + (size_t)rc3 * 128);
    const float* Wb = Ws + c0;

    #pragma unroll 2
    for (int k0 = 0; k0 < 32; k0++) {
        float4 xv[4];
        xv[0] = Xr0[k0]; xv[1] = Xr1[k0]; xv[2] = Xr2[k0]; xv[3] = Xr3[k0];
        #pragma unroll
        for (int kk = 0; kk < 4; kk++) {
            const ulonglong2* wr = (const ulonglong2*)(Wb + (k0 * 4 + kk) * 64);
            ulonglong2 w0 = wr[0], w1 = wr[1];
            #pragma unroll
            for (int rb = 0; rb < 4; rb++) {
                float xs = (kk == 0) ? xv[rb].x : (kk == 1) ? xv[rb].y
                         : (kk == 2) ? xv[rb].z : xv[rb].w;
                unsigned long long xx = pack2(xs, xs);
                fma2(acc[rb][0], w0.x, xx); fma2(acc[rb][1], w0.y, xx);
                fma2(acc[rb][2], w1.x, xx); fma2(acc[rb][3], w1.y, xx);
            }
        }
    }

    #pragma unroll
    for (int rb = 0; rb < 4; rb++) {
        int row = row0 + rb;
        float h[8];
        #pragma unroll
        for (int m = 0; m < 4; m++) unpack2(acc[rb][m], h[2 * m], h[2 * m + 1]);

        if (seg > 0 && row < N) {
            uint4 pk;
            pk.x = h2_as_u32(__floats2half2_rn(h[0], h[1]));
            pk.y = h2_as_u32(__floats2half2_rn(h[2], h[3]));
            pk.z = h2_as_u32(__floats2half2_rn(h[4], h[5]));
            pk.w = h2_as_u32(__floats2half2_rn(h[6], h[7]));
            *(uint4*)(g_hsrc + ((size_t)(seg - 1) * N + row) * 64 + c0) = pk;
        }
        for (int v = 0; v < n_av; v++) {
            float e = 0.f;
            #pragma unroll
            for (int j = 0; j < 8; j++) e += h[j] * as[v * 64 + c0 + j];
            e += __shfl_xor_sync(0xffffffffu, e, 1);
            e += __shfl_xor_sync(0xffffffffu, e, 2);
            e += __shfl_xor_sync(0xffffffffu, e, 4);
            if (cg == 0 && row < N) {
                if (seg == 0) g_er[(size_t)v * N + row] = e;
                else          g_el[(size_t)(seg - 1) * N + row] = e;
            }
        }
    }
}

// ---------- CSR build: histogram ----------
__global__ void k_hist(const int* __restrict__ dst, int N, int E, int E2, int E3) {
    int i = blockIdx.x * blockDim.x + threadIdx.x;
    int st = gridDim.x * blockDim.x;
    for (int e = i; e < E3; e += st) {
        int r = (e >= E2) ? 2 : (e >= E) ? 1 : 0;
        atomicAdd(&g_cur[r * N + __ldg(&dst[e])], 1);
    }
}

// ---------- scan stage A: per-tile (2048) exclusive scan ----------
__global__ void k_scanA(int n) {
    __shared__ int sd[256];
    int tid = threadIdx.x;
    int base = blockIdx.x * 2048 + tid * 8;
    int c[8], pre[8];
    int s = 0;
    #pragma unroll
    for (int i = 0; i < 8; i++) c[i] = (base + i < n) ? g_cur[base + i] : 0;
    #pragma unroll
    for (int i = 0; i < 8; i++) { pre[i] = s; s += c[i]; }
    sd[tid] = s;
    __syncthreads();
    for (int o = 1; o < 256; o <<= 1) {
        int v = (tid >= o) ? sd[tid - o] : 0;
        __syncthreads();
        sd[tid] += v;
        __syncthreads();
    }
    int excl = sd[tid] - s;
    #pragma unroll
    for (int i = 0; i < 8; i++)
        if (base + i < n) g_off[base + i] = excl + pre[i];
    if (tid == 255) g_tsum[blockIdx.x] = sd[255];
}

// ---------- scan stage B: exclusive scan of tile sums (single block) ----------
__global__ void k_scanB(int nt) {
    __shared__ int sd[256];
    int tid = threadIdx.x;
    int v = (tid < nt) ? g_tsum[tid] : 0;
    sd[tid] = v;
    __syncthreads();
    for (int o = 1; o < 256; o <<= 1) {
        int x = (tid >= o) ? sd[tid - o] : 0;
        __syncthreads();
        sd[tid] += x;
        __syncthreads();
    }
    if (tid < nt) g_tsum[tid] = sd[tid] - v;
}

// ---------- scan stage C: add tile offsets; copy to cursors; set sentinel ----------
__global__ void k_scanC(int n, int total) {
    int i = blockIdx.x * blockDim.x + threadIdx.x;
    int st = gridDim.x * blockDim.x;
    for (int j = i; j < n; j += st) {
        int o = g_off[j] + g_tsum[j >> 11];
        g_off[j] = o;
        g_cur[j] = o;
    }
    if (i == 0) g_off[n] = total;
}

// ---------- aggregate: per (r,dst) gather, depth-1 pipelined ----------
__global__ __launch_bounds__(256) void k_agg(int N) {
    int t = blockIdx.x * blockDim.x + threadIdx.x;
    int g = t >> 4;
    int lane = t & 15;
    int gsz = (gridDim.x * blockDim.x) >> 4;
    int items = 3 * N, N2 = 2 * N;
    const uint2* h2 = (const uint2*)g_hsrc;

    for (int item = g; item < items; item += gsz) {
        int r = (item >= N2) ? 2 : (item >= N) ? 1 : 0;
        int d = item - r * N;
        float er = __ldg(&g_er[item]);          // g_er layout is [r][row] == item
        int j0 = __ldg(&g_off[item]);
        int j1 = __ldg(&g_off[item + 1]);
        const float* elr = g_el + (size_t)r * N;
        const uint2* hr = h2 + (size_t)r * N * 16 + lane;
        float a0 = 0.f, a1 = 0.f, a2 = 0.f, a3 = 0.f, den = 0.f;

        // software pipeline: current (C) values preloaded, next (Nx) issued early
        int sC = 0; float elC = 0.f; uint2 vC = make_uint2(0u, 0u);
        if (j0 < j1) {
            sC = __ldg(&g_csr[j0]);
            elC = __ldg(&elr[sC]);
            vC = __ldg(&hr[(size_t)sC * 16]);
        }
        for (int j = j0; j < j1; j++) {
            int sN = 0; float elN = 0.f; uint2 vN = make_uint2(0u, 0u);
            if (j + 1 < j1) {
                sN = __ldg(&g_csr[j + 1]);
                elN = __ldg(&elr[sN]);
                vN = __ldg(&hr[(size_t)sN * 16]);
            }
            float x = elC + er;
            float lr = x > 0.f ? x : 0.01f * x;
            float p = __expf(lr);
            float2 f0 = __half22float2(u32_as_h2(vC.x));
            float2 f1 = __half22float2(u32_as_h2(vC.y));
            a0 += p * f0.x; a1 += p * f0.y; a2 += p * f1.x; a3 += p * f1.y;
            den += p;
            sC = sN; elC = elN; vC = vN;
        }
        float dinv = den > 0.f ? 1.f / den : 0.f;   // zero-degree -> elu(0)=0
        a0 *= dinv; a1 *= dinv; a2 *= dinv; a3 *= dinv;
        a0 = a0 > 0.f ? a0 : (__expf(a0) - 1.f);
        a1 = a1 > 0.f ? a1 : (__expf(a1) - 1.f);
        a2 = a2 > 0.f ? a2 : (__expf(a2) - 1.f);
        a3 = a3 > 0.f ? a3 : (__expf(a3) - 1.f);
        *(float4*)(g_z + (size_t)d * 192 + r * 64 + lane * 4) =
            make_float4(a0, a1, a2, a3);
    }
}

// ---------- finalize: semantic logits only (z already final) ----------
__global__ __launch_bounds__(256, 3) void k_finalize(
    const float* __restrict__ W1, const float* __restrict__ b1,
    const float* __restrict__ w2, int N)
{
    __shared__ __align__(16) float W1s[64 * 128];               // 32 KB
    __shared__ float b1s[128], w2s[128];
    __shared__ __align__(16) unsigned long long zb[8][8][64];   // 32 KB
    __shared__ float wsum[8][3];
    int tid = threadIdx.x, wid = tid >> 5, lane = tid & 31;
    const float4* W14 = (const float4*)W1;
    float4* W1s4 = (float4*)W1s;
    #pragma unroll
    for (int i = 0; i < 8; i++) W1s4[tid + 256 * i] = W14[tid + 256 * i];
    if (tid < 128) { b1s[tid] = b1[tid]; w2s[tid] = w2[tid]; }
    __syncthreads();

    int items = 3 * N, N2 = 2 * N;
    float t0 = 0.f, t1 = 0.f, t2 = 0.f;
    const ulonglong2* Wp = (const ulonglong2*)W1s;
    int stride = gridDim.x * 64;

    for (int item0 = blockIdx.x * 64 + wid * 8; item0 < items; item0 += stride) {
        int rs[8]; bool val[8];
        #pragma unroll
        for (int b = 0; b < 8; b++) {
            int it = item0 + b;
            val[b] = it < items;
            int iu = val[b] ? it : 0;
            int r = (iu >= N2) ? 2 : (iu >= N) ? 1 : 0;
            rs[b] = r;
            int row = iu - r * N;
            const float* zr = g_z + (size_t)row * 192 + r * 64;
            float z0 = zr[lane];
            float z1 = zr[32 + lane];
            zb[wid][b][lane] = pack2(z0, z0);
            zb[wid][b][32 + lane] = pack2(z1, z1);
        }
        __syncwarp();

        unsigned long long a01[8], a23[8];
        #pragma unroll
        for (int b = 0; b < 8; b++) {
            a01[b] = pack2(b1s[4 * lane], b1s[4 * lane + 1]);
            a23[b] = pack2(b1s[4 * lane + 2], b1s[4 * lane + 3]);
        }
        #pragma unroll 4
        for (int i = 0; i < 64; i++) {
            ulonglong2 w = Wp[i * 32 + lane];
            #pragma unroll
            for (int b = 0; b < 8; b++) {
                unsigned long long zz = zb[wid][b][i];
                fma2(a01[b], w.x, zz);
                fma2(a23[b], w.y, zz);
            }
        }

        #pragma unroll
        for (int b = 0; b < 8; b++) {
            if (!val[b]) continue;
            float h0, h1, h2v, h3;
            unpack2(a01[b], h0, h1);
            unpack2(a23[b], h2v, h3);
            h0 = tanh_approx(h0); h1 = tanh_approx(h1);
            h2v = tanh_approx(h2v); h3 = tanh_approx(h3);
            float tv = h0 * w2s[4 * lane] + h1 * w2s[4 * lane + 1]
                     + h2v * w2s[4 * lane + 2] + h3 * w2s[4 * lane + 3];
            int r = rs[b];
            if (r == 0) t0 += tv; else if (r == 1) t1 += tv; else t2 += tv;
        }
        __syncwarp();
    }

    #pragma unroll
    for (int o = 16; o; o >>= 1) {
        t0 += __shfl_xor_sync(0xffffffffu, t0, o);
        t1 += __shfl_xor_sync(0xffffffffu, t1, o);
        t2 += __shfl_xor_sync(0xffffffffu, t2, o);
    }
    if (lane == 0) { wsum[wid][0] = t0; wsum[wid][1] = t1; wsum[wid][2] = t2; }
    __syncthreads();
    if (tid < 3) {
        float s = 0.f;
        #pragma unroll
        for (int w = 0; w < 8; w++) s += wsum[w][tid];
        atomicAdd(&g_wpart[tid], s);
    }
}

// ---------- semantic softmax + mix ----------
__global__ void k_mix(float* __restrict__ out, int N, float invN) {
    float w0 = g_wpart[0] * invN, w1 = g_wpart[1] * invN, w2v = g_wpart[2] * invN;
    float m = fmaxf(w0, fmaxf(w1, w2v));
    float e0 = __expf(w0 - m), e1 = __expf(w1 - m), e2 = __expf(w2v - m);
    float si = 1.f / (e0 + e1 + e2);
    float a0 = e0 * si, a1 = e1 * si, a2 = e2 * si;

    const float4* z4 = (const float4*)g_z;
    float4* o4 = (float4*)out;
    int total = N * 16;
    int i = blockIdx.x * blockDim.x + threadIdx.x;
    int stride = gridDim.x * blockDim.x;
    for (int idx = i; idx < total; idx += stride) {
        int n = idx >> 4, q = idx & 15;
        float4 v0 = z4[(size_t)n * 48 + q];
        float4 v1 = z4[(size_t)n * 48 + 16 + q];
        float4 v2 = z4[(size_t)n * 48 + 32 + q];
        float4 o;
        o.x = a0 * v0.x + a1 * v1.x + a2 * v2.x;
        o.y = a0 * v0.y + a1 * v1.y + a2 * v2.y;
        o.z = a0 * v0.z + a1 * v1.z + a2 * v2.z;
        o.w = a0 * v0.w + a1 * v1.w + a2 * v2.w;
        o4[idx] = o;
    }
}

extern "C" void kernel_launch(void* const* d_in, const int* in_sizes, int n_in,
                              void* d_out, int out_size) {
    const float* dst_feat = (const float*)d_in[0];
    const float* neigh    = (const float*)d_in[1];
    const float* Wt       = (const float*)d_in[2];
    const float* bt       = (const float*)d_in[3];
    const float* attn_l   = (const float*)d_in[4];
    const float* attn_r   = (const float*)d_in[5];
    const float* W1       = (const float*)d_in[6];
    const float* b1       = (const float*)d_in[7];
    const float* w2       = (const float*)d_in[8];
    const int*   src      = (const int*)d_in[9];
    const int*   dst      = (const int*)d_in[10];

    int N = in_sizes[0] / 128;          // 100000
    int E = in_sizes[9] / 3;            // 1000000
    int E2 = 2 * E, E3 = 3 * E;
    int n3 = 3 * N;
    int nTiles = (n3 + 2047) / 2048;    // 147 for N=100000
    (void)n_in; (void)out_size;

    // zero counters (graph-capturable memset nodes)
    void* cp = nullptr; void* wp = nullptr;
    cudaGetSymbolAddress(&cp, g_cur);
    cudaGetSymbolAddress(&wp, g_wpart);
    cudaMemsetAsync(cp, 0, (size_t)n3 * sizeof(int));
    cudaMemsetAsync(wp, 0, 4 * sizeof(float));

    // CSR build prefix (hist + scans)
    k_hist<<<1184, 256>>>(dst, N, E, E2, E3);
    k_scanA<<<nTiles, 256>>>(n3);
    k_scanB<<<1, 256>>>(nTiles);
    k_scanC<<<(n3 + 255) / 256, 256>>>(n3, E3);

    // GEMMs + CSR fill in one launch (fill overlaps gemm)
    dim3 ggrid((N + 127) / 128, 5);
    k_gemm_fill<<<ggrid, 256>>>(dst_feat, neigh, Wt, bt, attn_l, attn_r,
                                src, dst, N, E, E2, E3);

    // per-destination gather aggregation (no atomics)
    k_agg<<<1184, 256>>>(N);

    k_finalize<<<444, 256>>>(W1, b1, w2, N);

    k_mix<<<1024, 256>>>((float*)d_out, N, 1.0f / (float)N);
}

// round 12
// speedup vs baseline: 2.0235x; 1.1808x over previous
#include <cuda_runtime.h>
#include <cuda_fp16.h>
#include <mma.h>
#include <math.h>
#include <string.h>

using namespace nvcuda;

#define NMAX 100000
#define RMAX 3
#define EMAX 1000000

// Scratch (device globals; no allocation allowed)
__device__ __align__(256) float g_z[(size_t)NMAX * 192];             // [N][3][64] final z_r
__device__ __align__(256) __half g_hsrc[(size_t)RMAX * NMAX * 64];   // h_src per relation (fp16)
__device__ __align__(256) float g_el[RMAX * NMAX];                   // el per relation
__device__ __align__(256) float g_er[RMAX * NMAX];                   // er per relation
__device__ __align__(256) int   g_off[RMAX * NMAX + 1];              // CSR row offsets
__device__ __align__(256) int   g_cur[RMAX * NMAX];                  // counts -> fill cursors
__device__ __align__(256) int   g_csr[(size_t)RMAX * EMAX];          // CSR src indices
__device__ __align__(256) int   g_tsum[256];                         // scan tile sums
__device__ __align__(256) float g_wpart[4];                          // semantic logit partials

// ---------- helpers ----------
__device__ __forceinline__ unsigned long long pack2(float a, float b) {
    unsigned long long r;
    asm("mov.b64 %0, {%1, %2};" : "=l"(r) : "f"(a), "f"(b));
    return r;
}
__device__ __forceinline__ void unpack2(unsigned long long v, float& a, float& b) {
    asm("mov.b64 {%0, %1}, %2;" : "=f"(a), "=f"(b) : "l"(v));
}
__device__ __forceinline__ void fma2(unsigned long long& d, unsigned long long a, unsigned long long b) {
    asm("fma.rn.f32x2 %0, %1, %2, %0;" : "+l"(d) : "l"(a), "l"(b));
}
__device__ __forceinline__ float tanh_approx(float x) {
    float y;
    asm("tanh.approx.f32 %0, %1;" : "=f"(y) : "f"(x));
    return y;
}
__device__ __forceinline__ unsigned int h2_as_u32(__half2 h) {
    unsigned int u;
    memcpy(&u, &h, 4);
    return u;
}
__device__ __forceinline__ __half2 u32_as_h2(unsigned int u) {
    __half2 h;
    memcpy(&h, &u, 4);
    return h;
}

// dynamic smem layout for k_gemm_tc (bytes)
//  SM_A : 128 rows x 136 halfs = 34816  (reused as C: 128 x 68 floats = 34816)
//  SM_B : 128 rows x 72 halfs  = 18432
//  SM_MISC : bias 64 f32 (256 B) + attn 192 f32 (768 B)
#define SM_A 0
#define SM_B 34816
#define SM_MISC 53248
#define SM_TOTAL 54272
#define LDA 136
#define LDB 72
#define LDC 68

// ---------- WMMA GEMM (+ overlapped CSR fill at blockIdx.y==4) ----------
__global__ void k_gemm_tc(
    const float* __restrict__ dst_feat, const float* __restrict__ neigh,
    const float* __restrict__ Wt, const float* __restrict__ bt,
    const float* __restrict__ attn_l, const float* __restrict__ attn_r,
    const int* __restrict__ src, const int* __restrict__ dst,
    int N, int E, int E2, int E3, int nTiles)
{
    extern __shared__ char smem[];
    int tid = threadIdx.x;
    int seg = blockIdx.y;

    if (seg == 4) {
        // ---- CSR fill (ILP-4 batched) ----
        int i0 = (blockIdx.x * 128 + tid) * 4;
        int st = gridDim.x * 128 * 4;
        for (int e = i0; e < E3; e += st) {
            #pragma unroll
            for (int q = 0; q < 4; q++) {
                int ee = e + q;
                if (ee < E3) {
                    int r = (ee >= E2) ? 2 : (ee >= E) ? 1 : 0;
                    int idx = r * N + __ldg(&dst[ee]);
                    int pos = atomicAdd(&g_cur[idx], 1);
                    g_csr[pos] = __ldg(&src[ee]);
                }
            }
        }
        return;
    }

    int wid = tid >> 5;
    __half* As = (__half*)(smem + SM_A);
    __half* Bs = (__half*)(smem + SM_B);
    float*  Cs = (float*)(smem + SM_A);     // aliased with As (warp-private rows)
    float*  bs = (float*)(smem + SM_MISC);
    float*  as_ = (float*)(smem + SM_MISC + 256);

    // ---- W [k=128][n=64] -> fp16 smem (one time) ----
    const float* W = Wt + (size_t)seg * 128 * 64;
    for (int idx = tid; idx < 8192; idx += 128) {
        int k = idx >> 6, n = idx & 63;
        Bs[k * LDB + n] = __float2half(W[idx]);
    }
    if (tid < 64) bs[tid] = bt[seg * 64 + tid];
    int n_av = (seg == 0) ? 3 : 1;
    const float* av = (seg == 0) ? attn_r : (attn_l + (size_t)(seg - 1) * 64);
    for (int i = tid; i < n_av * 64; i += 128) as_[i] = av[i];   // FIX: strided (192 > 128 threads)
    __syncthreads();

    const float4* X4 = (const float4*)((seg == 0) ? dst_feat : (neigh + (size_t)(seg - 1) * N * 128));

    for (int t = blockIdx.x; t < nTiles; t += gridDim.x) {
        int row0 = t * 128;
        // ---- X tile -> fp16 A smem (coalesced) ----
        #pragma unroll 4
        for (int i = 0; i < 32; i++) {
            int idx = i * 128 + tid;
            int row = idx >> 5, c4 = idx & 31;
            int rg = row0 + row;
            if (rg >= N) rg = N - 1;
            float4 f = __ldg(&X4[(size_t)rg * 32 + c4]);
            __half2* dstp = (__half2*)(As + row * LDA + c4 * 4);
            dstp[0] = __floats2half2_rn(f.x, f.y);
            dstp[1] = __floats2half2_rn(f.z, f.w);
        }
        __syncthreads();

        // ---- WMMA: warp computes rows [wid*32, wid*32+32) x 64 cols ----
        wmma::fragment<wmma::accumulator, 16, 16, 16, float> acc[2][4];
        #pragma unroll
        for (int i = 0; i < 2; i++)
            #pragma unroll
            for (int j = 0; j < 4; j++)
                wmma::fill_fragment(acc[i][j], 0.f);

        #pragma unroll
        for (int k0 = 0; k0 < 8; k0++) {
            wmma::fragment<wmma::matrix_a, 16, 16, 16, __half, wmma::row_major> af[2];
            wmma::load_matrix_sync(af[0], As + (wid * 32) * LDA + k0 * 16, LDA);
            wmma::load_matrix_sync(af[1], As + (wid * 32 + 16) * LDA + k0 * 16, LDA);
            #pragma unroll
            for (int n0 = 0; n0 < 4; n0++) {
                wmma::fragment<wmma::matrix_b, 16, 16, 16, __half, wmma::row_major> bf;
                wmma::load_matrix_sync(bf, Bs + (k0 * 16) * LDB + n0 * 16, LDB);
                wmma::mma_sync(acc[0][n0], af[0], bf, acc[0][n0]);
                wmma::mma_sync(acc[1][n0], af[1], bf, acc[1][n0]);
            }
        }
        // store accumulators into C (aliases A; rows are warp-private)
        #pragma unroll
        for (int i = 0; i < 2; i++)
            #pragma unroll
            for (int n0 = 0; n0 < 4; n0++)
                wmma::store_matrix_sync(Cs + (wid * 32 + i * 16) * LDC + n0 * 16,
                                        acc[i][n0], LDC, wmma::mem_row_major);
        __syncthreads();

        // ---- epilogue: one row per thread ----
        int row = row0 + tid;
        if (row < N) {
            float h[64];
            const float4* cr = (const float4*)(Cs + tid * LDC);
            #pragma unroll
            for (int q = 0; q < 16; q++) {
                float4 f = cr[q];
                h[4 * q + 0] = f.x + bs[4 * q + 0];
                h[4 * q + 1] = f.y + bs[4 * q + 1];
                h[4 * q + 2] = f.z + bs[4 * q + 2];
                h[4 * q + 3] = f.w + bs[4 * q + 3];
            }
            if (seg > 0) {
                uint4* o4 = (uint4*)(g_hsrc + ((size_t)(seg - 1) * N + row) * 64);
                #pragma unroll
                for (int q = 0; q < 8; q++) {
                    uint4 pk;
                    pk.x = h2_as_u32(__floats2half2_rn(h[8 * q + 0], h[8 * q + 1]));
                    pk.y = h2_as_u32(__floats2half2_rn(h[8 * q + 2], h[8 * q + 3]));
                    pk.z = h2_as_u32(__floats2half2_rn(h[8 * q + 4], h[8 * q + 5]));
                    pk.w = h2_as_u32(__floats2half2_rn(h[8 * q + 6], h[8 * q + 7]));
                    o4[q] = pk;
                }
            }
            for (int v = 0; v < n_av; v++) {
                float e = 0.f;
                #pragma unroll
                for (int j = 0; j < 64; j++) e += h[j] * as_[v * 64 + j];
                if (seg == 0) g_er[(size_t)v * N + row] = e;
                else          g_el[(size_t)(seg - 1) * N + row] = e;
            }
        }
        __syncthreads();
    }
}

// ---------- CSR build: histogram ----------
__global__ void k_hist(const int* __restrict__ dst, int N, int E, int E2, int E3) {
    int i = blockIdx.x * blockDim.x + threadIdx.x;
    int st = gridDim.x * blockDim.x;
    for (int e = i; e < E3; e += st) {
        int r = (e >= E2) ? 2 : (e >= E) ? 1 : 0;
        atomicAdd(&g_cur[r * N + __ldg(&dst[e])], 1);
    }
}

// ---------- scan stage A: per-tile (2048) exclusive scan ----------
__global__ void k_scanA(int n) {
    __shared__ int sd[256];
    int tid = threadIdx.x;
    int base = blockIdx.x * 2048 + tid * 8;
    int c[8], pre[8];
    int s = 0;
    #pragma unroll
    for (int i = 0; i < 8; i++) c[i] = (base + i < n) ? g_cur[base + i] : 0;
    #pragma unroll
    for (int i = 0; i < 8; i++) { pre[i] = s; s += c[i]; }
    sd[tid] = s;
    __syncthreads();
    for (int o = 1; o < 256; o <<= 1) {
        int v = (tid >= o) ? sd[tid - o] : 0;
        __syncthreads();
        sd[tid] += v;
        __syncthreads();
    }
    int excl = sd[tid] - s;
    #pragma unroll
    for (int i = 0; i < 8; i++)
        if (base + i < n) g_off[base + i] = excl + pre[i];
    if (tid == 255) g_tsum[blockIdx.x] = sd[255];
}

// ---------- scan stage B ----------
__global__ void k_scanB(int nt) {
    __shared__ int sd[256];
    int tid = threadIdx.x;
    int v = (tid < nt) ? g_tsum[tid] : 0;
    sd[tid] = v;
    __syncthreads();
    for (int o = 1; o < 256; o <<= 1) {
        int x = (tid >= o) ? sd[tid - o] : 0;
        __syncthreads();
        sd[tid] += x;
        __syncthreads();
    }
    if (tid < nt) g_tsum[tid] = sd[tid] - v;
}

// ---------- scan stage C ----------
__global__ void k_scanC(int n, int total) {
    int i = blockIdx.x * blockDim.x + threadIdx.x;
    int st = gridDim.x * blockDim.x;
    for (int j = i; j < n; j += st) {
        int o = g_off[j] + g_tsum[j >> 11];
        g_off[j] = o;
        g_cur[j] = o;
    }
    if (i == 0) g_off[n] = total;
}

// ---------- aggregate: per (r,dst) gather, depth-1 pipelined ----------
__global__ __launch_bounds__(256) void k_agg(int N) {
    int t = blockIdx.x * blockDim.x + threadIdx.x;
    int g = t >> 4;
    int lane = t & 15;
    int gsz = (gridDim.x * blockDim.x) >> 4;
    int items = 3 * N, N2 = 2 * N;
    const uint2* h2 = (const uint2*)g_hsrc;

    for (int item = g; item < items; item += gsz) {
        int r = (item >= N2) ? 2 : (item >= N) ? 1 : 0;
        int d = item - r * N;
        float er = __ldg(&g_er[item]);
        int j0 = __ldg(&g_off[item]);
        int j1 = __ldg(&g_off[item + 1]);
        const float* elr = g_el + (size_t)r * N;
        const uint2* hr = h2 + (size_t)r * N * 16 + lane;
        float a0 = 0.f, a1 = 0.f, a2 = 0.f, a3 = 0.f, den = 0.f;

        int sC = 0; float elC = 0.f; uint2 vC = make_uint2(0u, 0u);
        if (j0 < j1) {
            sC = __ldg(&g_csr[j0]);
            elC = __ldg(&elr[sC]);
            vC = __ldg(&hr[(size_t)sC * 16]);
        }
        for (int j = j0; j < j1; j++) {
            int sN = 0; float elN = 0.f; uint2 vN = make_uint2(0u, 0u);
            if (j + 1 < j1) {
                sN = __ldg(&g_csr[j + 1]);
                elN = __ldg(&elr[sN]);
                vN = __ldg(&hr[(size_t)sN * 16]);
            }
            float x = elC + er;
            float lr = x > 0.f ? x : 0.01f * x;
            float p = __expf(lr);
            float2 f0 = __half22float2(u32_as_h2(vC.x));
            float2 f1 = __half22float2(u32_as_h2(vC.y));
            a0 += p * f0.x; a1 += p * f0.y; a2 += p * f1.x; a3 += p * f1.y;
            den += p;
            sC = sN; elC = elN; vC = vN;
        }
        float dinv = den > 0.f ? 1.f / den : 0.f;   // zero-degree -> elu(0)=0
        a0 *= dinv; a1 *= dinv; a2 *= dinv; a3 *= dinv;
        a0 = a0 > 0.f ? a0 : (__expf(a0) - 1.f);
        a1 = a1 > 0.f ? a1 : (__expf(a1) - 1.f);
        a2 = a2 > 0.f ? a2 : (__expf(a2) - 1.f);
        a3 = a3 > 0.f ? a3 : (__expf(a3) - 1.f);
        *(float4*)(g_z + (size_t)d * 192 + r * 64 + lane * 4) =
            make_float4(a0, a1, a2, a3);
    }
}

// ---------- finalize: semantic logits only ----------
__global__ __launch_bounds__(256, 3) void k_finalize(
    const float* __restrict__ W1, const float* __restrict__ b1,
    const float* __restrict__ w2, int N)
{
    __shared__ __align__(16) float W1s[64 * 128];
    __shared__ float b1s[128], w2s[128];
    __shared__ __align__(16) unsigned long long zb[8][8][64];
    __shared__ float wsum[8][3];
    int tid = threadIdx.x, wid = tid >> 5, lane = tid & 31;
    const float4* W14 = (const float4*)W1;
    float4* W1s4 = (float4*)W1s;
    #pragma unroll
    for (int i = 0; i < 8; i++) W1s4[tid + 256 * i] = W14[tid + 256 * i];
    if (tid < 128) { b1s[tid] = b1[tid]; w2s[tid] = w2[tid]; }
    __syncthreads();

    int items = 3 * N, N2 = 2 * N;
    float t0 = 0.f, t1 = 0.f, t2 = 0.f;
    const ulonglong2* Wp = (const ulonglong2*)W1s;
    int stride = gridDim.x * 64;

    for (int item0 = blockIdx.x * 64 + wid * 8; item0 < items; item0 += stride) {
        int rs[8]; bool val[8];
        #pragma unroll
        for (int b = 0; b < 8; b++) {
            int it = item0 + b;
            val[b] = it < items;
            int iu = val[b] ? it : 0;
            int r = (iu >= N2) ? 2 : (iu >= N) ? 1 : 0;
            rs[b] = r;
            int row = iu - r * N;
            const float* zr = g_z + (size_t)row * 192 + r * 64;
            float z0 = zr[lane];
            float z1 = zr[32 + lane];
            zb[wid][b][lane] = pack2(z0, z0);
            zb[wid][b][32 + lane] = pack2(z1, z1);
        }
        __syncwarp();

        unsigned long long a01[8], a23[8];
        #pragma unroll
        for (int b = 0; b < 8; b++) {
            a01[b] = pack2(b1s[4 * lane], b1s[4 * lane + 1]);
            a23[b] = pack2(b1s[4 * lane + 2], b1s[4 * lane + 3]);
        }
        #pragma unroll 4
        for (int i = 0; i < 64; i++) {
            ulonglong2 w = Wp[i * 32 + lane];
            #pragma unroll
            for (int b = 0; b < 8; b++) {
                unsigned long long zz = zb[wid][b][i];
                fma2(a01[b], w.x, zz);
                fma2(a23[b], w.y, zz);
            }
        }

        #pragma unroll
        for (int b = 0; b < 8; b++) {
            if (!val[b]) continue;
            float h0, h1, h2v, h3;
            unpack2(a01[b], h0, h1);
            unpack2(a23[b], h2v, h3);
            h0 = tanh_approx(h0); h1 = tanh_approx(h1);
            h2v = tanh_approx(h2v); h3 = tanh_approx(h3);
            float tv = h0 * w2s[4 * lane] + h1 * w2s[4 * lane + 1]
                     + h2v * w2s[4 * lane + 2] + h3 * w2s[4 * lane + 3];
            int r = rs[b];
            if (r == 0) t0 += tv; else if (r == 1) t1 += tv; else t2 += tv;
        }
        __syncwarp();
    }

    #pragma unroll
    for (int o = 16; o; o >>= 1) {
        t0 += __shfl_xor_sync(0xffffffffu, t0, o);
        t1 += __shfl_xor_sync(0xffffffffu, t1, o);
        t2 += __shfl_xor_sync(0xffffffffu, t2, o);
    }
    if (lane == 0) { wsum[wid][0] = t0; wsum[wid][1] = t1; wsum[wid][2] = t2; }
    __syncthreads();
    if (tid < 3) {
        float s = 0.f;
        #pragma unroll
        for (int w = 0; w < 8; w++) s += wsum[w][tid];
        atomicAdd(&g_wpart[tid], s);
    }
}

// ---------- semantic softmax + mix ----------
__global__ void k_mix(float* __restrict__ out, int N, float invN) {
    float w0 = g_wpart[0] * invN, w1 = g_wpart[1] * invN, w2v = g_wpart[2] * invN;
    float m = fmaxf(w0, fmaxf(w1, w2v));
    float e0 = __expf(w0 - m), e1 = __expf(w1 - m), e2 = __expf(w2v - m);
    float si = 1.f / (e0 + e1 + e2);
    float a0 = e0 * si, a1 = e1 * si, a2 = e2 * si;

    const float4* z4 = (const float4*)g_z;
    float4* o4 = (float4*)out;
    int total = N * 16;
    int i = blockIdx.x * blockDim.x + threadIdx.x;
    int stride = gridDim.x * blockDim.x;
    for (int idx = i; idx < total; idx += stride) {
        int n = idx >> 4, q = idx & 15;
        float4 v0 = z4[(size_t)n * 48 + q];
        float4 v1 = z4[(size_t)n * 48 + 16 + q];
        float4 v2 = z4[(size_t)n * 48 + 32 + q];
        float4 o;
        o.x = a0 * v0.x + a1 * v1.x + a2 * v2.x;
        o.y = a0 * v0.y + a1 * v1.y + a2 * v2.y;
        o.z = a0 * v0.z + a1 * v1.z + a2 * v2.z;
        o.w = a0 * v0.w + a1 * v1.w + a2 * v2.w;
        o4[idx] = o;
    }
}

extern "C" void kernel_launch(void* const* d_in, const int* in_sizes, int n_in,
                              void* d_out, int out_size) {
    const float* dst_feat = (const float*)d_in[0];
    const float* neigh    = (const float*)d_in[1];
    const float* Wt       = (const float*)d_in[2];
    const float* bt       = (const float*)d_in[3];
    const float* attn_l   = (const float*)d_in[4];
    const float* attn_r   = (const float*)d_in[5];
    const float* W1       = (const float*)d_in[6];
    const float* b1       = (const float*)d_in[7];
    const float* w2       = (const float*)d_in[8];
    const int*   src      = (const int*)d_in[9];
    const int*   dst      = (const int*)d_in[10];

    int N = in_sizes[0] / 128;          // 100000
    int E = in_sizes[9] / 3;            // 1000000
    int E2 = 2 * E, E3 = 3 * E;
    int n3 = 3 * N;
    int nScanTiles = (n3 + 2047) / 2048;
    int nTiles = (N + 127) / 128;       // 782 row tiles
    (void)n_in; (void)out_size;

    void* cp = nullptr; void* wp = nullptr;
    cudaGetSymbolAddress(&cp, g_cur);
    cudaGetSymbolAddress(&wp, g_wpart);
    cudaMemsetAsync(cp, 0, (size_t)n3 * sizeof(int));
    cudaMemsetAsync(wp, 0, 4 * sizeof(float));

    k_hist<<<1184, 256>>>(dst, N, E, E2, E3);
    k_scanA<<<nScanTiles, 256>>>(n3);
    k_scanB<<<1, 256>>>(nScanTiles);
    k_scanC<<<(n3 + 255) / 256, 256>>>(n3, E3);

    // WMMA GEMMs + CSR fill in one launch
    cudaFuncSetAttribute(k_gemm_tc, cudaFuncAttributeMaxDynamicSharedMemorySize, SM_TOTAL);
    dim3 ggrid(148, 5);
    k_gemm_tc<<<ggrid, 128, SM_TOTAL>>>(dst_feat, neigh, Wt, bt, attn_l, attn_r,
                                        src, dst, N, E, E2, E3, nTiles);

    k_agg<<<1184, 256>>>(N);

    k_finalize<<<444, 256>>>(W1, b1, w2, N);

    k_mix<<<1024, 256>>>((float*)d_out, N, 1.0f / (float)N);
}

// round 13
// speedup vs baseline: 2.4012x; 1.1866x over previous
#include <cuda_runtime.h>
#include <cuda_fp16.h>
#include <mma.h>
#include <math.h>
#include <string.h>

using namespace nvcuda;

#define NMAX 100000
#define RMAX 3
#define EMAX 1000000

// Scratch (device globals; no allocation allowed)
__device__ __align__(256) float g_z[(size_t)NMAX * 192];             // [N][3][64] final z_r
__device__ __align__(256) __half g_hsrc[(size_t)RMAX * NMAX * 64];   // h_src per relation (fp16)
__device__ __align__(256) float g_el[RMAX * NMAX];                   // el per relation
__device__ __align__(256) float g_er[RMAX * NMAX];                   // er per relation
__device__ __align__(256) int   g_off[RMAX * NMAX + 1];              // CSR row offsets
__device__ __align__(256) int   g_cur[RMAX * NMAX];                  // counts -> fill cursors
__device__ __align__(256) int   g_csr[(size_t)RMAX * EMAX];          // CSR src indices
__device__ __align__(256) int   g_tsum[256];                         // scan tile sums
__device__ __align__(256) float g_wpart[4];                          // semantic logit partials

// ---------- helpers ----------
__device__ __forceinline__ float tanh_approx(float x) {
    float y;
    asm("tanh.approx.f32 %0, %1;" : "=f"(y) : "f"(x));
    return y;
}
__device__ __forceinline__ unsigned int h2_as_u32(__half2 h) {
    unsigned int u;
    memcpy(&u, &h, 4);
    return u;
}
__device__ __forceinline__ __half2 u32_as_h2(unsigned int u) {
    __half2 h;
    memcpy(&h, &u, 4);
    return h;
}

// dynamic smem layout for k_gemm_tc (bytes)
#define SM_A 0
#define SM_B 34816
#define SM_MISC 53248
#define SM_TOTAL 54272
#define LDA 136
#define LDB 72
#define LDC 68

// ---------- WMMA GEMM (+ overlapped CSR fill at blockIdx.y==4) ----------
__global__ void k_gemm_tc(
    const float* __restrict__ dst_feat, const float* __restrict__ neigh,
    const float* __restrict__ Wt, const float* __restrict__ bt,
    const float* __restrict__ attn_l, const float* __restrict__ attn_r,
    const int* __restrict__ src, const int* __restrict__ dst,
    int N, int E, int E2, int E3, int nTiles)
{
    extern __shared__ char smem[];
    int tid = threadIdx.x;
    int seg = blockIdx.y;

    if (seg == 4) {
        // ---- CSR fill (ILP-4 batched) ----
        int i0 = (blockIdx.x * 128 + tid) * 4;
        int st = gridDim.x * 128 * 4;
        for (int e = i0; e < E3; e += st) {
            #pragma unroll
            for (int q = 0; q < 4; q++) {
                int ee = e + q;
                if (ee < E3) {
                    int r = (ee >= E2) ? 2 : (ee >= E) ? 1 : 0;
                    int idx = r * N + __ldg(&dst[ee]);
                    int pos = atomicAdd(&g_cur[idx], 1);
                    g_csr[pos] = __ldg(&src[ee]);
                }
            }
        }
        return;
    }

    int wid = tid >> 5;
    __half* As = (__half*)(smem + SM_A);
    __half* Bs = (__half*)(smem + SM_B);
    float*  Cs = (float*)(smem + SM_A);     // aliased with As (warp-private rows)
    float*  bs = (float*)(smem + SM_MISC);
    float*  as_ = (float*)(smem + SM_MISC + 256);

    // ---- W [k=128][n=64] -> fp16 smem (one time) ----
    const float* W = Wt + (size_t)seg * 128 * 64;
    for (int idx = tid; idx < 8192; idx += 128) {
        int k = idx >> 6, n = idx & 63;
        Bs[k * LDB + n] = __float2half(W[idx]);
    }
    if (tid < 64) bs[tid] = bt[seg * 64 + tid];
    int n_av = (seg == 0) ? 3 : 1;
    const float* av = (seg == 0) ? attn_r : (attn_l + (size_t)(seg - 1) * 64);
    for (int i = tid; i < n_av * 64; i += 128) as_[i] = av[i];
    __syncthreads();

    const float4* X4 = (const float4*)((seg == 0) ? dst_feat : (neigh + (size_t)(seg - 1) * N * 128));

    for (int t = blockIdx.x; t < nTiles; t += gridDim.x) {
        int row0 = t * 128;
        // ---- X tile -> fp16 A smem (coalesced) ----
        #pragma unroll 4
        for (int i = 0; i < 32; i++) {
            int idx = i * 128 + tid;
            int row = idx >> 5, c4 = idx & 31;
            int rg = row0 + row;
            if (rg >= N) rg = N - 1;
            float4 f = __ldg(&X4[(size_t)rg * 32 + c4]);
            __half2* dstp = (__half2*)(As + row * LDA + c4 * 4);
            dstp[0] = __floats2half2_rn(f.x, f.y);
            dstp[1] = __floats2half2_rn(f.z, f.w);
        }
        __syncthreads();

        // ---- WMMA: warp computes rows [wid*32, wid*32+32) x 64 cols ----
        wmma::fragment<wmma::accumulator, 16, 16, 16, float> acc[2][4];
        #pragma unroll
        for (int i = 0; i < 2; i++)
            #pragma unroll
            for (int j = 0; j < 4; j++)
                wmma::fill_fragment(acc[i][j], 0.f);

        #pragma unroll
        for (int k0 = 0; k0 < 8; k0++) {
            wmma::fragment<wmma::matrix_a, 16, 16, 16, __half, wmma::row_major> af[2];
            wmma::load_matrix_sync(af[0], As + (wid * 32) * LDA + k0 * 16, LDA);
            wmma::load_matrix_sync(af[1], As + (wid * 32 + 16) * LDA + k0 * 16, LDA);
            #pragma unroll
            for (int n0 = 0; n0 < 4; n0++) {
                wmma::fragment<wmma::matrix_b, 16, 16, 16, __half, wmma::row_major> bf;
                wmma::load_matrix_sync(bf, Bs + (k0 * 16) * LDB + n0 * 16, LDB);
                wmma::mma_sync(acc[0][n0], af[0], bf, acc[0][n0]);
                wmma::mma_sync(acc[1][n0], af[1], bf, acc[1][n0]);
            }
        }
        #pragma unroll
        for (int i = 0; i < 2; i++)
            #pragma unroll
            for (int n0 = 0; n0 < 4; n0++)
                wmma::store_matrix_sync(Cs + (wid * 32 + i * 16) * LDC + n0 * 16,
                                        acc[i][n0], LDC, wmma::mem_row_major);
        __syncthreads();

        // ---- epilogue: one row per thread ----
        int row = row0 + tid;
        if (row < N) {
            float h[64];
            const float4* cr = (const float4*)(Cs + tid * LDC);
            #pragma unroll
            for (int q = 0; q < 16; q++) {
                float4 f = cr[q];
                h[4 * q + 0] = f.x + bs[4 * q + 0];
                h[4 * q + 1] = f.y + bs[4 * q + 1];
                h[4 * q + 2] = f.z + bs[4 * q + 2];
                h[4 * q + 3] = f.w + bs[4 * q + 3];
            }
            if (seg > 0) {
                uint4* o4 = (uint4*)(g_hsrc + ((size_t)(seg - 1) * N + row) * 64);
                #pragma unroll
                for (int q = 0; q < 8; q++) {
                    uint4 pk;
                    pk.x = h2_as_u32(__floats2half2_rn(h[8 * q + 0], h[8 * q + 1]));
                    pk.y = h2_as_u32(__floats2half2_rn(h[8 * q + 2], h[8 * q + 3]));
                    pk.z = h2_as_u32(__floats2half2_rn(h[8 * q + 4], h[8 * q + 5]));
                    pk.w = h2_as_u32(__floats2half2_rn(h[8 * q + 6], h[8 * q + 7]));
                    o4[q] = pk;
                }
            }
            for (int v = 0; v < n_av; v++) {
                float e = 0.f;
                #pragma unroll
                for (int j = 0; j < 64; j++) e += h[j] * as_[v * 64 + j];
                if (seg == 0) g_er[(size_t)v * N + row] = e;
                else          g_el[(size_t)(seg - 1) * N + row] = e;
            }
        }
        __syncthreads();
    }
}

// ---------- CSR build: histogram ----------
__global__ void k_hist(const int* __restrict__ dst, int N, int E, int E2, int E3) {
    int i = blockIdx.x * blockDim.x + threadIdx.x;
    int st = gridDim.x * blockDim.x;
    for (int e = i; e < E3; e += st) {
        int r = (e >= E2) ? 2 : (e >= E) ? 1 : 0;
        atomicAdd(&g_cur[r * N + __ldg(&dst[e])], 1);
    }
}

// ---------- scan stage A ----------
__global__ void k_scanA(int n) {
    __shared__ int sd[256];
    int tid = threadIdx.x;
    int base = blockIdx.x * 2048 + tid * 8;
    int c[8], pre[8];
    int s = 0;
    #pragma unroll
    for (int i = 0; i < 8; i++) c[i] = (base + i < n) ? g_cur[base + i] : 0;
    #pragma unroll
    for (int i = 0; i < 8; i++) { pre[i] = s; s += c[i]; }
    sd[tid] = s;
    __syncthreads();
    for (int o = 1; o < 256; o <<= 1) {
        int v = (tid >= o) ? sd[tid - o] : 0;
        __syncthreads();
        sd[tid] += v;
        __syncthreads();
    }
    int excl = sd[tid] - s;
    #pragma unroll
    for (int i = 0; i < 8; i++)
        if (base + i < n) g_off[base + i] = excl + pre[i];
    if (tid == 255) g_tsum[blockIdx.x] = sd[255];
}

// ---------- scan stage B ----------
__global__ void k_scanB(int nt) {
    __shared__ int sd[256];
    int tid = threadIdx.x;
    int v = (tid < nt) ? g_tsum[tid] : 0;
    sd[tid] = v;
    __syncthreads();
    for (int o = 1; o < 256; o <<= 1) {
        int x = (tid >= o) ? sd[tid - o] : 0;
        __syncthreads();
        sd[tid] += x;
        __syncthreads();
    }
    if (tid < nt) g_tsum[tid] = sd[tid] - v;
}

// ---------- scan stage C ----------
__global__ void k_scanC(int n, int total) {
    int i = blockIdx.x * blockDim.x + threadIdx.x;
    int st = gridDim.x * blockDim.x;
    for (int j = i; j < n; j += st) {
        int o = g_off[j] + g_tsum[j >> 11];
        g_off[j] = o;
        g_cur[j] = o;
    }
    if (i == 0) g_off[n] = total;
}

// ---------- aggregate: per (r,dst) gather, depth-1 pipelined ----------
__global__ __launch_bounds__(256) void k_agg(int N) {
    int t = blockIdx.x * blockDim.x + threadIdx.x;
    int g = t >> 4;
    int lane = t & 15;
    int gsz = (gridDim.x * blockDim.x) >> 4;
    int items = 3 * N, N2 = 2 * N;
    const uint2* h2 = (const uint2*)g_hsrc;

    for (int item = g; item < items; item += gsz) {
        int r = (item >= N2) ? 2 : (item >= N) ? 1 : 0;
        int d = item - r * N;
        float er = __ldg(&g_er[item]);
        int j0 = __ldg(&g_off[item]);
        int j1 = __ldg(&g_off[item + 1]);
        const float* elr = g_el + (size_t)r * N;
        const uint2* hr = h2 + (size_t)r * N * 16 + lane;
        float a0 = 0.f, a1 = 0.f, a2 = 0.f, a3 = 0.f, den = 0.f;

        int sC = 0; float elC = 0.f; uint2 vC = make_uint2(0u, 0u);
        if (j0 < j1) {
            sC = __ldg(&g_csr[j0]);
            elC = __ldg(&elr[sC]);
            vC = __ldg(&hr[(size_t)sC * 16]);
        }
        for (int j = j0; j < j1; j++) {
            int sN = 0; float elN = 0.f; uint2 vN = make_uint2(0u, 0u);
            if (j + 1 < j1) {
                sN = __ldg(&g_csr[j + 1]);
                elN = __ldg(&elr[sN]);
                vN = __ldg(&hr[(size_t)sN * 16]);
            }
            float x = elC + er;
            float lr = x > 0.f ? x : 0.01f * x;
            float p = __expf(lr);
            float2 f0 = __half22float2(u32_as_h2(vC.x));
            float2 f1 = __half22float2(u32_as_h2(vC.y));
            a0 += p * f0.x; a1 += p * f0.y; a2 += p * f1.x; a3 += p * f1.y;
            den += p;
            sC = sN; elC = elN; vC = vN;
        }
        float dinv = den > 0.f ? 1.f / den : 0.f;   // zero-degree -> elu(0)=0
        a0 *= dinv; a1 *= dinv; a2 *= dinv; a3 *= dinv;
        a0 = a0 > 0.f ? a0 : (__expf(a0) - 1.f);
        a1 = a1 > 0.f ? a1 : (__expf(a1) - 1.f);
        a2 = a2 > 0.f ? a2 : (__expf(a2) - 1.f);
        a3 = a3 > 0.f ? a3 : (__expf(a3) - 1.f);
        *(float4*)(g_z + (size_t)d * 192 + r * 64 + lane * 4) =
            make_float4(a0, a1, a2, a3);
    }
}

// ---------- finalize (WMMA): w logits = mean tanh(z@W1+b1)@w2 per relation ----------
// dyn smem layout (bytes)
#define FZ_W1 0            // 64 x 136 halfs = 17408
#define FZ_Z  17408        // 64 items x 72 halfs = 9216
#define FZ_C  26624        // 64 x 132 floats = 33792
#define FZ_B1 60416        // 128 f32
#define FZ_W2 60928        // 128 f32
#define FZ_TOTAL 61440
#define FLDW 136
#define FLDZ 72
#define FLDC 132

__global__ void k_finalize_tc(
    const float* __restrict__ W1, const float* __restrict__ b1,
    const float* __restrict__ w2, int N)
{
    extern __shared__ char smem[];
    __half* W1h = (__half*)(smem + FZ_W1);
    __half* Zh  = (__half*)(smem + FZ_Z);
    float*  Cs  = (float*)(smem + FZ_C);
    float*  b1s = (float*)(smem + FZ_B1);
    float*  w2s = (float*)(smem + FZ_W2);
    __shared__ float wsum[4][3];

    int tid = threadIdx.x, wid = tid >> 5, lane = tid & 31;

    // W1 [k=64][n=128] -> fp16 smem once
    for (int idx = tid; idx < 8192; idx += 128) {
        int k = idx >> 7, n = idx & 127;
        W1h[k * FLDW + n] = __float2half(W1[idx]);
    }
    if (tid < 128) { b1s[tid] = b1[tid]; w2s[tid] = w2[tid]; }
    __syncthreads();

    int items = 3 * N, N2 = 2 * N;
    int li = tid >> 1, half = tid & 1;
    float t0 = 0.f, t1 = 0.f, t2 = 0.f;
    int stride = gridDim.x * 64;

    for (int item0 = blockIdx.x * 64; item0 < items; item0 += stride) {
        // ---- stage 64 items of z into fp16 smem ----
        {
            int it = item0 + li;
            int iu = (it < items) ? it : 0;
            int r = (iu >= N2) ? 2 : (iu >= N) ? 1 : 0;
            int row = iu - r * N;
            const float4* zr = (const float4*)(g_z + (size_t)row * 192 + r * 64) + half * 8;
            __half2* zd = (__half2*)(Zh + li * FLDZ + half * 32);
            #pragma unroll
            for (int q = 0; q < 8; q++) {
                float4 f = zr[q];
                zd[2 * q + 0] = __floats2half2_rn(f.x, f.y);
                zd[2 * q + 1] = __floats2half2_rn(f.z, f.w);
            }
        }
        __syncthreads();

        // ---- WMMA: warp computes items [wid*16, wid*16+16) x 128 cols ----
        {
            wmma::fragment<wmma::accumulator, 16, 16, 16, float> acc[8];
            #pragma unroll
            for (int j = 0; j < 8; j++) wmma::fill_fragment(acc[j], 0.f);
            #pragma unroll
            for (int k0 = 0; k0 < 4; k0++) {
                wmma::fragment<wmma::matrix_a, 16, 16, 16, __half, wmma::row_major> af;
                wmma::load_matrix_sync(af, Zh + (wid * 16) * FLDZ + k0 * 16, FLDZ);
                #pragma unroll
                for (int n0 = 0; n0 < 8; n0++) {
                    wmma::fragment<wmma::matrix_b, 16, 16, 16, __half, wmma::row_major> bf;
                    wmma::load_matrix_sync(bf, W1h + (k0 * 16) * FLDW + n0 * 16, FLDW);
                    wmma::mma_sync(acc[n0], af, bf, acc[n0]);
                }
            }
            #pragma unroll
            for (int n0 = 0; n0 < 8; n0++)
                wmma::store_matrix_sync(Cs + (wid * 16) * FLDC + n0 * 16, acc[n0],
                                        FLDC, wmma::mem_row_major);
        }
        __syncthreads();

        // ---- epilogue: 2 threads/item, 64 cols each ----
        {
            int it = item0 + li;
            if (it < items) {
                int r = (it >= N2) ? 2 : (it >= N) ? 1 : 0;
                const float* cr = Cs + li * FLDC + half * 64;
                const float* b1p = b1s + half * 64;
                const float* w2p = w2s + half * 64;
                float s = 0.f;
                #pragma unroll 16
                for (int c = 0; c < 64; c++)
                    s += tanh_approx(cr[c] + b1p[c]) * w2p[c];
                s += __shfl_xor_sync(0xffffffffu, s, 1);
                if (half == 0) {
                    if (r == 0) t0 += s; else if (r == 1) t1 += s; else t2 += s;
                }
            }
        }
        __syncthreads();
    }

    #pragma unroll
    for (int o = 16; o; o >>= 1) {
        t0 += __shfl_xor_sync(0xffffffffu, t0, o);
        t1 += __shfl_xor_sync(0xffffffffu, t1, o);
        t2 += __shfl_xor_sync(0xffffffffu, t2, o);
    }
    if (lane == 0) { wsum[wid][0] = t0; wsum[wid][1] = t1; wsum[wid][2] = t2; }
    __syncthreads();
    if (tid < 3) {
        float s = 0.f;
        #pragma unroll
        for (int w = 0; w < 4; w++) s += wsum[w][tid];
        atomicAdd(&g_wpart[tid], s);
    }
}

// ---------- semantic softmax + mix ----------
__global__ void k_mix(float* __restrict__ out, int N, float invN) {
    float w0 = g_wpart[0] * invN, w1 = g_wpart[1] * invN, w2v = g_wpart[2] * invN;
    float m = fmaxf(w0, fmaxf(w1, w2v));
    float e0 = __expf(w0 - m), e1 = __expf(w1 - m), e2 = __expf(w2v - m);
    float si = 1.f / (e0 + e1 + e2);
    float a0 = e0 * si, a1 = e1 * si, a2 = e2 * si;

    const float4* z4 = (const float4*)g_z;
    float4* o4 = (float4*)out;
    int total = N * 16;
    int i = blockIdx.x * blockDim.x + threadIdx.x;
    int stride = gridDim.x * blockDim.x;
    for (int idx = i; idx < total; idx += stride) {
        int n = idx >> 4, q = idx & 15;
        float4 v0 = z4[(size_t)n * 48 + q];
        float4 v1 = z4[(size_t)n * 48 + 16 + q];
        float4 v2 = z4[(size_t)n * 48 + 32 + q];
        float4 o;
        o.x = a0 * v0.x + a1 * v1.x + a2 * v2.x;
        o.y = a0 * v0.y + a1 * v1.y + a2 * v2.y;
        o.z = a0 * v0.z + a1 * v1.z + a2 * v2.z;
        o.w = a0 * v0.w + a1 * v1.w + a2 * v2.w;
        o4[idx] = o;
    }
}

extern "C" void kernel_launch(void* const* d_in, const int* in_sizes, int n_in,
                              void* d_out, int out_size) {
    const float* dst_feat = (const float*)d_in[0];
    const float* neigh    = (const float*)d_in[1];
    const float* Wt       = (const float*)d_in[2];
    const float* bt       = (const float*)d_in[3];
    const float* attn_l   = (const float*)d_in[4];
    const float* attn_r   = (const float*)d_in[5];
    const float* W1       = (const float*)d_in[6];
    const float* b1       = (const float*)d_in[7];
    const float* w2       = (const float*)d_in[8];
    const int*   src      = (const int*)d_in[9];
    const int*   dst      = (const int*)d_in[10];

    int N = in_sizes[0] / 128;          // 100000
    int E = in_sizes[9] / 3;            // 1000000
    int E2 = 2 * E, E3 = 3 * E;
    int n3 = 3 * N;
    int nScanTiles = (n3 + 2047) / 2048;
    int nTiles = (N + 127) / 128;       // 782 row tiles
    (void)n_in; (void)out_size;

    void* cp = nullptr; void* wp = nullptr;
    cudaGetSymbolAddress(&cp, g_cur);
    cudaGetSymbolAddress(&wp, g_wpart);
    cudaMemsetAsync(cp, 0, (size_t)n3 * sizeof(int));
    cudaMemsetAsync(wp, 0, 4 * sizeof(float));

    k_hist<<<1184, 256>>>(dst, N, E, E2, E3);
    k_scanA<<<nScanTiles, 256>>>(n3);
    k_scanB<<<1, 256>>>(nScanTiles);
    k_scanC<<<(n3 + 255) / 256, 256>>>(n3, E3);

    // WMMA GEMMs + CSR fill in one launch
    cudaFuncSetAttribute(k_gemm_tc, cudaFuncAttributeMaxDynamicSharedMemorySize, SM_TOTAL);
    dim3 ggrid(148, 5);
    k_gemm_tc<<<ggrid, 128, SM_TOTAL>>>(dst_feat, neigh, Wt, bt, attn_l, attn_r,
                                        src, dst, N, E, E2, E3, nTiles);

    k_agg<<<1184, 256>>>(N);

    cudaFuncSetAttribute(k_finalize_tc, cudaFuncAttributeMaxDynamicSharedMemorySize, FZ_TOTAL);
    k_finalize_tc<<<444, 128, FZ_TOTAL>>>(W1, b1, w2, N);

    k_mix<<<1024, 256>>>((float*)d_out, N, 1.0f / (float)N);
}

// round 14
// speedup vs baseline: 2.4806x; 1.0331x over previous
#include <cuda_runtime.h>
#include <cuda_fp16.h>
#include <mma.h>
#include <math.h>
#include <string.h>

using namespace nvcuda;

#define NMAX 100000
#define RMAX 3
#define EMAX 1000000

// Scratch (device globals; no allocation allowed)
__device__ __align__(256) float g_z[(size_t)NMAX * 192];             // [N][3][64] final z_r
__device__ __align__(256) __half g_hsrc[(size_t)RMAX * NMAX * 64];   // h_src per relation (fp16)
__device__ __align__(256) float g_el[RMAX * NMAX];                   // el per relation
__device__ __align__(256) float g_er[RMAX * NMAX];                   // er per relation
__device__ __align__(256) int   g_off[RMAX * NMAX + 1];              // CSR row offsets
__device__ __align__(256) int   g_cur[RMAX * NMAX];                  // counts -> fill cursors
__device__ __align__(256) int   g_csr[(size_t)RMAX * EMAX];          // CSR src indices
__device__ __align__(256) int   g_tsum[256];                         // scan tile sums
__device__ __align__(256) float g_wpart[4];                          // semantic logit partials

// ---------- helpers ----------
__device__ __forceinline__ float tanh_approx(float x) {
    float y;
    asm("tanh.approx.f32 %0, %1;" : "=f"(y) : "f"(x));
    return y;
}
__device__ __forceinline__ unsigned int h2_as_u32(__half2 h) {
    unsigned int u;
    memcpy(&u, &h, 4);
    return u;
}
__device__ __forceinline__ __half2 u32_as_h2(unsigned int u) {
    __half2 h;
    memcpy(&h, &u, 4);
    return h;
}

// dynamic smem layout for k_gemm_tc (bytes)
#define SM_A 0
#define SM_B 34816
#define SM_MISC 53248
#define SM_TOTAL 54272
#define LDA 136
#define LDB 72
#define LDC 68

// ---------- WMMA GEMM (+ overlapped CSR fill at blockIdx.y==4) ----------
__global__ void k_gemm_tc(
    const float* __restrict__ dst_feat, const float* __restrict__ neigh,
    const float* __restrict__ Wt, const float* __restrict__ bt,
    const float* __restrict__ attn_l, const float* __restrict__ attn_r,
    const int* __restrict__ src, const int* __restrict__ dst,
    int N, int E, int E2, int E3, int nTiles)
{
    extern __shared__ char smem[];
    int tid = threadIdx.x;
    int seg = blockIdx.y;

    if (seg == 4) {
        // ---- CSR fill (ILP-4 batched) ----
        int i0 = (blockIdx.x * 128 + tid) * 4;
        int st = gridDim.x * 128 * 4;
        for (int e = i0; e < E3; e += st) {
            #pragma unroll
            for (int q = 0; q < 4; q++) {
                int ee = e + q;
                if (ee < E3) {
                    int r = (ee >= E2) ? 2 : (ee >= E) ? 1 : 0;
                    int idx = r * N + __ldg(&dst[ee]);
                    int pos = atomicAdd(&g_cur[idx], 1);
                    g_csr[pos] = __ldg(&src[ee]);
                }
            }
        }
        return;
    }

    int wid = tid >> 5;
    __half* As = (__half*)(smem + SM_A);
    __half* Bs = (__half*)(smem + SM_B);
    float*  Cs = (float*)(smem + SM_A);     // aliased with As (warp-private rows)
    float*  bs = (float*)(smem + SM_MISC);
    float*  as_ = (float*)(smem + SM_MISC + 256);

    // ---- W [k=128][n=64] -> fp16 smem (one time) ----
    const float* W = Wt + (size_t)seg * 128 * 64;
    for (int idx = tid; idx < 8192; idx += 128) {
        int k = idx >> 6, n = idx & 63;
        Bs[k * LDB + n] = __float2half(W[idx]);
    }
    if (tid < 64) bs[tid] = bt[seg * 64 + tid];
    int n_av = (seg == 0) ? 3 : 1;
    const float* av = (seg == 0) ? attn_r : (attn_l + (size_t)(seg - 1) * 64);
    for (int i = tid; i < n_av * 64; i += 128) as_[i] = av[i];
    __syncthreads();

    const float4* X4 = (const float4*)((seg == 0) ? dst_feat : (neigh + (size_t)(seg - 1) * N * 128));

    for (int t = blockIdx.x; t < nTiles; t += gridDim.x) {
        int row0 = t * 128;
        // ---- X tile -> fp16 A smem (coalesced) ----
        #pragma unroll 4
        for (int i = 0; i < 32; i++) {
            int idx = i * 128 + tid;
            int row = idx >> 5, c4 = idx & 31;
            int rg = row0 + row;
            if (rg >= N) rg = N - 1;
            float4 f = __ldg(&X4[(size_t)rg * 32 + c4]);
            __half2* dstp = (__half2*)(As + row * LDA + c4 * 4);
            dstp[0] = __floats2half2_rn(f.x, f.y);
            dstp[1] = __floats2half2_rn(f.z, f.w);
        }
        __syncthreads();

        // ---- WMMA: warp computes rows [wid*32, wid*32+32) x 64 cols ----
        wmma::fragment<wmma::accumulator, 16, 16, 16, float> acc[2][4];
        #pragma unroll
        for (int i = 0; i < 2; i++)
            #pragma unroll
            for (int j = 0; j < 4; j++)
                wmma::fill_fragment(acc[i][j], 0.f);

        #pragma unroll
        for (int k0 = 0; k0 < 8; k0++) {
            wmma::fragment<wmma::matrix_a, 16, 16, 16, __half, wmma::row_major> af[2];
            wmma::load_matrix_sync(af[0], As + (wid * 32) * LDA + k0 * 16, LDA);
            wmma::load_matrix_sync(af[1], As + (wid * 32 + 16) * LDA + k0 * 16, LDA);
            #pragma unroll
            for (int n0 = 0; n0 < 4; n0++) {
                wmma::fragment<wmma::matrix_b, 16, 16, 16, __half, wmma::row_major> bf;
                wmma::load_matrix_sync(bf, Bs + (k0 * 16) * LDB + n0 * 16, LDB);
                wmma::mma_sync(acc[0][n0], af[0], bf, acc[0][n0]);
                wmma::mma_sync(acc[1][n0], af[1], bf, acc[1][n0]);
            }
        }
        #pragma unroll
        for (int i = 0; i < 2; i++)
            #pragma unroll
            for (int n0 = 0; n0 < 4; n0++)
                wmma::store_matrix_sync(Cs + (wid * 32 + i * 16) * LDC + n0 * 16,
                                        acc[i][n0], LDC, wmma::mem_row_major);
        __syncthreads();

        // ---- epilogue: one row per thread ----
        int row = row0 + tid;
        if (row < N) {
            float h[64];
            const float4* cr = (const float4*)(Cs + tid * LDC);
            #pragma unroll
            for (int q = 0; q < 16; q++) {
                float4 f = cr[q];
                h[4 * q + 0] = f.x + bs[4 * q + 0];
                h[4 * q + 1] = f.y + bs[4 * q + 1];
                h[4 * q + 2] = f.z + bs[4 * q + 2];
                h[4 * q + 3] = f.w + bs[4 * q + 3];
            }
            if (seg > 0) {
                uint4* o4 = (uint4*)(g_hsrc + ((size_t)(seg - 1) * N + row) * 64);
                #pragma unroll
                for (int q = 0; q < 8; q++) {
                    uint4 pk;
                    pk.x = h2_as_u32(__floats2half2_rn(h[8 * q + 0], h[8 * q + 1]));
                    pk.y = h2_as_u32(__floats2half2_rn(h[8 * q + 2], h[8 * q + 3]));
                    pk.z = h2_as_u32(__floats2half2_rn(h[8 * q + 4], h[8 * q + 5]));
                    pk.w = h2_as_u32(__floats2half2_rn(h[8 * q + 6], h[8 * q + 7]));
                    o4[q] = pk;
                }
            }
            for (int v = 0; v < n_av; v++) {
                float e = 0.f;
                #pragma unroll
                for (int j = 0; j < 64; j++) e += h[j] * as_[v * 64 + j];
                if (seg == 0) g_er[(size_t)v * N + row] = e;
                else          g_el[(size_t)(seg - 1) * N + row] = e;
            }
        }
        __syncthreads();
    }
}

// ---------- CSR build: histogram ----------
__global__ void k_hist(const int* __restrict__ dst, int N, int E, int E2, int E3) {
    int i = blockIdx.x * blockDim.x + threadIdx.x;
    int st = gridDim.x * blockDim.x;
    for (int e = i; e < E3; e += st) {
        int r = (e >= E2) ? 2 : (e >= E) ? 1 : 0;
        atomicAdd(&g_cur[r * N + __ldg(&dst[e])], 1);
    }
}

// ---------- scan stage A ----------
__global__ void k_scanA(int n) {
    __shared__ int sd[256];
    int tid = threadIdx.x;
    int base = blockIdx.x * 2048 + tid * 8;
    int c[8], pre[8];
    int s = 0;
    #pragma unroll
    for (int i = 0; i < 8; i++) c[i] = (base + i < n) ? g_cur[base + i] : 0;
    #pragma unroll
    for (int i = 0; i < 8; i++) { pre[i] = s; s += c[i]; }
    sd[tid] = s;
    __syncthreads();
    for (int o = 1; o < 256; o <<= 1) {
        int v = (tid >= o) ? sd[tid - o] : 0;
        __syncthreads();
        sd[tid] += v;
        __syncthreads();
    }
    int excl = sd[tid] - s;
    #pragma unroll
    for (int i = 0; i < 8; i++)
        if (base + i < n) g_off[base + i] = excl + pre[i];
    if (tid == 255) g_tsum[blockIdx.x] = sd[255];
}

// ---------- scan stage B ----------
__global__ void k_scanB(int nt) {
    __shared__ int sd[256];
    int tid = threadIdx.x;
    int v = (tid < nt) ? g_tsum[tid] : 0;
    sd[tid] = v;
    __syncthreads();
    for (int o = 1; o < 256; o <<= 1) {
        int x = (tid >= o) ? sd[tid - o] : 0;
        __syncthreads();
        sd[tid] += x;
        __syncthreads();
    }
    if (tid < nt) g_tsum[tid] = sd[tid] - v;
}

// ---------- scan stage C (+ zero g_wpart so no extra memset launch) ----------
__global__ void k_scanC(int n, int total) {
    int i = blockIdx.x * blockDim.x + threadIdx.x;
    int st = gridDim.x * blockDim.x;
    for (int j = i; j < n; j += st) {
        int o = g_off[j] + g_tsum[j >> 11];
        g_off[j] = o;
        g_cur[j] = o;
    }
    if (i == 0) {
        g_off[n] = total;
        g_wpart[0] = 0.f; g_wpart[1] = 0.f; g_wpart[2] = 0.f; g_wpart[3] = 0.f;
    }
}

// ---------- aggregate: per (r,dst) gather, 2 edges/iteration ----------
__global__ __launch_bounds__(256) void k_agg(int N) {
    int t = blockIdx.x * blockDim.x + threadIdx.x;
    int g = t >> 4;
    int lane = t & 15;
    int gsz = (gridDim.x * blockDim.x) >> 4;
    int items = 3 * N, N2 = 2 * N;
    const uint2* h2 = (const uint2*)g_hsrc;

    for (int item = g; item < items; item += gsz) {
        int r = (item >= N2) ? 2 : (item >= N) ? 1 : 0;
        int d = item - r * N;
        float er = __ldg(&g_er[item]);
        int j0 = __ldg(&g_off[item]);
        int j1 = __ldg(&g_off[item + 1]);
        const float* elr = g_el + (size_t)r * N;
        const uint2* hr = h2 + (size_t)r * N * 16 + lane;
        float a0 = 0.f, a1 = 0.f, a2 = 0.f, a3 = 0.f, den = 0.f;

        for (int j = j0; j < j1; j += 2) {
            // two independent load chains per iteration (2x MLP)
            int sA = __ldg(&g_csr[j]);
            bool hasB = (j + 1 < j1);
            int sB = hasB ? __ldg(&g_csr[j + 1]) : sA;
            float elA = __ldg(&elr[sA]);
            uint2 vA = __ldg(&hr[(size_t)sA * 16]);
            float elB = __ldg(&elr[sB]);
            uint2 vB = __ldg(&hr[(size_t)sB * 16]);

            float xA = elA + er;
            float pA = __expf(xA > 0.f ? xA : 0.01f * xA);
            float2 fA0 = __half22float2(u32_as_h2(vA.x));
            float2 fA1 = __half22float2(u32_as_h2(vA.y));
            a0 += pA * fA0.x; a1 += pA * fA0.y; a2 += pA * fA1.x; a3 += pA * fA1.y;
            den += pA;

            if (hasB) {
                float xB = elB + er;
                float pB = __expf(xB > 0.f ? xB : 0.01f * xB);
                float2 fB0 = __half22float2(u32_as_h2(vB.x));
                float2 fB1 = __half22float2(u32_as_h2(vB.y));
                a0 += pB * fB0.x; a1 += pB * fB0.y; a2 += pB * fB1.x; a3 += pB * fB1.y;
                den += pB;
            }
        }
        float dinv = den > 0.f ? 1.f / den : 0.f;   // zero-degree -> elu(0)=0
        a0 *= dinv; a1 *= dinv; a2 *= dinv; a3 *= dinv;
        a0 = a0 > 0.f ? a0 : (__expf(a0) - 1.f);
        a1 = a1 > 0.f ? a1 : (__expf(a1) - 1.f);
        a2 = a2 > 0.f ? a2 : (__expf(a2) - 1.f);
        a3 = a3 > 0.f ? a3 : (__expf(a3) - 1.f);
        *(float4*)(g_z + (size_t)d * 192 + r * 64 + lane * 4) =
            make_float4(a0, a1, a2, a3);
    }
}

// ---------- finalize (WMMA): w logits = mean tanh(z@W1+b1)@w2 per relation ----------
#define FZ_W1 0            // 64 x 136 halfs = 17408
#define FZ_Z  17408        // 64 items x 72 halfs = 9216
#define FZ_C  26624        // 64 x 132 floats = 33792
#define FZ_B1 60416        // 128 f32
#define FZ_W2 60928        // 128 f32
#define FZ_TOTAL 61440
#define FLDW 136
#define FLDZ 72
#define FLDC 132

__global__ void k_finalize_tc(
    const float* __restrict__ W1, const float* __restrict__ b1,
    const float* __restrict__ w2, int N)
{
    extern __shared__ char smem[];
    __half* W1h = (__half*)(smem + FZ_W1);
    __half* Zh  = (__half*)(smem + FZ_Z);
    float*  Cs  = (float*)(smem + FZ_C);
    float*  b1s = (float*)(smem + FZ_B1);
    float*  w2s = (float*)(smem + FZ_W2);
    __shared__ float wsum[4][3];

    int tid = threadIdx.x, wid = tid >> 5, lane = tid & 31;

    for (int idx = tid; idx < 8192; idx += 128) {
        int k = idx >> 7, n = idx & 127;
        W1h[k * FLDW + n] = __float2half(W1[idx]);
    }
    if (tid < 128) { b1s[tid] = b1[tid]; w2s[tid] = w2[tid]; }
    __syncthreads();

    int items = 3 * N, N2 = 2 * N;
    int li = tid >> 1, half = tid & 1;
    float t0 = 0.f, t1 = 0.f, t2 = 0.f;
    int stride = gridDim.x * 64;

    for (int item0 = blockIdx.x * 64; item0 < items; item0 += stride) {
        {
            int it = item0 + li;
            int iu = (it < items) ? it : 0;
            int r = (iu >= N2) ? 2 : (iu >= N) ? 1 : 0;
            int row = iu - r * N;
            const float4* zr = (const float4*)(g_z + (size_t)row * 192 + r * 64) + half * 8;
            __half2* zd = (__half2*)(Zh + li * FLDZ + half * 32);
            #pragma unroll
            for (int q = 0; q < 8; q++) {
                float4 f = zr[q];
                zd[2 * q + 0] = __floats2half2_rn(f.x, f.y);
                zd[2 * q + 1] = __floats2half2_rn(f.z, f.w);
            }
        }
        __syncthreads();

        {
            wmma::fragment<wmma::accumulator, 16, 16, 16, float> acc[8];
            #pragma unroll
            for (int j = 0; j < 8; j++) wmma::fill_fragment(acc[j], 0.f);
            #pragma unroll
            for (int k0 = 0; k0 < 4; k0++) {
                wmma::fragment<wmma::matrix_a, 16, 16, 16, __half, wmma::row_major> af;
                wmma::load_matrix_sync(af, Zh + (wid * 16) * FLDZ + k0 * 16, FLDZ);
                #pragma unroll
                for (int n0 = 0; n0 < 8; n0++) {
                    wmma::fragment<wmma::matrix_b, 16, 16, 16, __half, wmma::row_major> bf;
                    wmma::load_matrix_sync(bf, W1h + (k0 * 16) * FLDW + n0 * 16, FLDW);
                    wmma::mma_sync(acc[n0], af, bf, acc[n0]);
                }
            }
            #pragma unroll
            for (int n0 = 0; n0 < 8; n0++)
                wmma::store_matrix_sync(Cs + (wid * 16) * FLDC + n0 * 16, acc[n0],
                                        FLDC, wmma::mem_row_major);
        }
        __syncthreads();

        {
            int it = item0 + li;
            if (it < items) {
                int r = (it >= N2) ? 2 : (it >= N) ? 1 : 0;
                const float* cr = Cs + li * FLDC + half * 64;
                const float* b1p = b1s + half * 64;
                const float* w2p = w2s + half * 64;
                float s = 0.f;
                #pragma unroll 16
                for (int c = 0; c < 64; c++)
                    s += tanh_approx(cr[c] + b1p[c]) * w2p[c];
                s += __shfl_xor_sync(0xffffffffu, s, 1);
                if (half == 0) {
                    if (r == 0) t0 += s; else if (r == 1) t1 += s; else t2 += s;
                }
            }
        }
        __syncthreads();
    }

    #pragma unroll
    for (int o = 16; o; o >>= 1) {
        t0 += __shfl_xor_sync(0xffffffffu, t0, o);
        t1 += __shfl_xor_sync(0xffffffffu, t1, o);
        t2 += __shfl_xor_sync(0xffffffffu, t2, o);
    }
    if (lane == 0) { wsum[wid][0] = t0; wsum[wid][1] = t1; wsum[wid][2] = t2; }
    __syncthreads();
    if (tid < 3) {
        float s = 0.f;
        #pragma unroll
        for (int w = 0; w < 4; w++) s += wsum[w][tid];
        atomicAdd(&g_wpart[tid], s);
    }
}

// ---------- semantic softmax + mix ----------
__global__ void k_mix(float* __restrict__ out, int N, float invN) {
    float w0 = g_wpart[0] * invN, w1 = g_wpart[1] * invN, w2v = g_wpart[2] * invN;
    float m = fmaxf(w0, fmaxf(w1, w2v));
    float e0 = __expf(w0 - m), e1 = __expf(w1 - m), e2 = __expf(w2v - m);
    float si = 1.f / (e0 + e1 + e2);
    float a0 = e0 * si, a1 = e1 * si, a2 = e2 * si;

    const float4* z4 = (const float4*)g_z;
    float4* o4 = (float4*)out;
    int total = N * 16;
    int i = blockIdx.x * blockDim.x + threadIdx.x;
    int stride = gridDim.x * blockDim.x;
    for (int idx = i; idx < total; idx += stride) {
        int n = idx >> 4, q = idx & 15;
        float4 v0 = z4[(size_t)n * 48 + q];
        float4 v1 = z4[(size_t)n * 48 + 16 + q];
        float4 v2 = z4[(size_t)n * 48 + 32 + q];
        float4 o;
        o.x = a0 * v0.x + a1 * v1.x + a2 * v2.x;
        o.y = a0 * v0.y + a1 * v1.y + a2 * v2.y;
        o.z = a0 * v0.z + a1 * v1.z + a2 * v2.z;
        o.w = a0 * v0.w + a1 * v1.w + a2 * v2.w;
        o4[idx] = o;
    }
}

extern "C" void kernel_launch(void* const* d_in, const int* in_sizes, int n_in,
                              void* d_out, int out_size) {
    const float* dst_feat = (const float*)d_in[0];
    const float* neigh    = (const float*)d_in[1];
    const float* Wt       = (const float*)d_in[2];
    const float* bt       = (const float*)d_in[3];
    const float* attn_l   = (const float*)d_in[4];
    const float* attn_r   = (const float*)d_in[5];
    const float* W1       = (const float*)d_in[6];
    const float* b1       = (const float*)d_in[7];
    const float* w2       = (const float*)d_in[8];
    const int*   src      = (const int*)d_in[9];
    const int*   dst      = (const int*)d_in[10];

    int N = in_sizes[0] / 128;          // 100000
    int E = in_sizes[9] / 3;            // 1000000
    int E2 = 2 * E, E3 = 3 * E;
    int n3 = 3 * N;
    int nScanTiles = (n3 + 2047) / 2048;
    int nTiles = (N + 127) / 128;       // 782 row tiles
    (void)n_in; (void)out_size;

    void* cp = nullptr;
    cudaGetSymbolAddress(&cp, g_cur);
    cudaMemsetAsync(cp, 0, (size_t)n3 * sizeof(int));

    k_hist<<<1184, 256>>>(dst, N, E, E2, E3);
    k_scanA<<<nScanTiles, 256>>>(n3);
    k_scanB<<<1, 256>>>(nScanTiles);
    k_scanC<<<(n3 + 255) / 256, 256>>>(n3, E3);

    // WMMA GEMMs + CSR fill in one launch  (6th launch -> ncu capture window)
    cudaFuncSetAttribute(k_gemm_tc, cudaFuncAttributeMaxDynamicSharedMemorySize, SM_TOTAL);
    dim3 ggrid(148, 5);
    k_gemm_tc<<<ggrid, 128, SM_TOTAL>>>(dst_feat, neigh, Wt, bt, attn_l, attn_r,
                                        src, dst, N, E, E2, E3, nTiles);

    k_agg<<<1184, 256>>>(N);

    cudaFuncSetAttribute(k_finalize_tc, cudaFuncAttributeMaxDynamicSharedMemorySize, FZ_TOTAL);
    k_finalize_tc<<<444, 128, FZ_TOTAL>>>(W1, b1, w2, N);

    k_mix<<<1024, 256>>>((float*)d_out, N, 1.0f / (float)N);
}

// round 15
// speedup vs baseline: 2.4808x; 1.0001x over previous
#include <cuda_runtime.h>
#include <cuda_fp16.h>
#include <mma.h>
#include <math.h>
#include <string.h>

using namespace nvcuda;

#define NMAX 100000
#define RMAX 3
#define EMAX 1000000

// Scratch (device globals; no allocation allowed)
__device__ __align__(256) float g_z[(size_t)NMAX * 192];             // [N][3][64] final z_r
__device__ __align__(256) __half g_hsrc[(size_t)RMAX * NMAX * 64];   // h_src per relation (fp16)
__device__ __align__(256) float g_el[RMAX * NMAX];                   // el per relation
__device__ __align__(256) float g_er[RMAX * NMAX];                   // er per relation
__device__ __align__(256) int   g_off[RMAX * NMAX + 1];              // CSR row offsets
__device__ __align__(256) int   g_cur[RMAX * NMAX];                  // counts -> fill cursors
__device__ __align__(256) int   g_csr[(size_t)RMAX * EMAX];          // CSR src indices
__device__ __align__(256) int   g_tsum[256];                         // scan tile sums
__device__ __align__(256) float g_wpart[4];                          // semantic logit partials

// ---------- helpers ----------
__device__ __forceinline__ float tanh_approx(float x) {
    float y;
    asm("tanh.approx.f32 %0, %1;" : "=f"(y) : "f"(x));
    return y;
}
__device__ __forceinline__ unsigned int h2_as_u32(__half2 h) {
    unsigned int u;
    memcpy(&u, &h, 4);
    return u;
}
__device__ __forceinline__ __half2 u32_as_h2(unsigned int u) {
    __half2 h;
    memcpy(&h, &u, 4);
    return h;
}

// dynamic smem layout for k_gemm_tc (bytes)
#define SM_A 0
#define SM_B 34816
#define SM_MISC 53248
#define SM_TOTAL 54272
#define LDA 136
#define LDB 72
#define LDC 68

// ---------- WMMA GEMM (+ overlapped CSR fill at blockIdx.y==4) ----------
__global__ void k_gemm_tc(
    const float* __restrict__ dst_feat, const float* __restrict__ neigh,
    const float* __restrict__ Wt, const float* __restrict__ bt,
    const float* __restrict__ attn_l, const float* __restrict__ attn_r,
    const int* __restrict__ src, const int* __restrict__ dst,
    int N, int E, int E2, int E3, int nTiles)
{
    extern __shared__ char smem[];
    int tid = threadIdx.x;
    int seg = blockIdx.y;

    if (seg == 4) {
        // ---- CSR fill (ILP-4 batched) ----
        int i0 = (blockIdx.x * 128 + tid) * 4;
        int st = gridDim.x * 128 * 4;
        for (int e = i0; e < E3; e += st) {
            #pragma unroll
            for (int q = 0; q < 4; q++) {
                int ee = e + q;
                if (ee < E3) {
                    int r = (ee >= E2) ? 2 : (ee >= E) ? 1 : 0;
                    int idx = r * N + __ldg(&dst[ee]);
                    int pos = atomicAdd(&g_cur[idx], 1);
                    g_csr[pos] = __ldg(&src[ee]);
                }
            }
        }
        return;
    }

    int wid = tid >> 5;
    __half* As = (__half*)(smem + SM_A);
    __half* Bs = (__half*)(smem + SM_B);
    float*  Cs = (float*)(smem + SM_A);     // aliased with As (warp-private rows)
    float*  bs = (float*)(smem + SM_MISC);
    float*  as_ = (float*)(smem + SM_MISC + 256);

    // ---- W [k=128][n=64] -> fp16 smem (one time) ----
    const float* W = Wt + (size_t)seg * 128 * 64;
    for (int idx = tid; idx < 8192; idx += 128) {
        int k = idx >> 6, n = idx & 63;
        Bs[k * LDB + n] = __float2half(W[idx]);
    }
    if (tid < 64) bs[tid] = bt[seg * 64 + tid];
    int n_av = (seg == 0) ? 3 : 1;
    const float* av = (seg == 0) ? attn_r : (attn_l + (size_t)(seg - 1) * 64);
    for (int i = tid; i < n_av * 64; i += 128) as_[i] = av[i];
    __syncthreads();

    const float4* X4 = (const float4*)((seg == 0) ? dst_feat : (neigh + (size_t)(seg - 1) * N * 128));

    for (int t = blockIdx.x; t < nTiles; t += gridDim.x) {
        int row0 = t * 128;
        // ---- X tile -> fp16 A smem (coalesced) ----
        #pragma unroll 4
        for (int i = 0; i < 32; i++) {
            int idx = i * 128 + tid;
            int row = idx >> 5, c4 = idx & 31;
            int rg = row0 + row;
            if (rg >= N) rg = N - 1;
            float4 f = __ldg(&X4[(size_t)rg * 32 + c4]);
            __half2* dstp = (__half2*)(As + row * LDA + c4 * 4);
            dstp[0] = __floats2half2_rn(f.x, f.y);
            dstp[1] = __floats2half2_rn(f.z, f.w);
        }
        __syncthreads();

        // ---- WMMA: warp computes rows [wid*32, wid*32+32) x 64 cols ----
        wmma::fragment<wmma::accumulator, 16, 16, 16, float> acc[2][4];
        #pragma unroll
        for (int i = 0; i < 2; i++)
            #pragma unroll
            for (int j = 0; j < 4; j++)
                wmma::fill_fragment(acc[i][j], 0.f);

        #pragma unroll
        for (int k0 = 0; k0 < 8; k0++) {
            wmma::fragment<wmma::matrix_a, 16, 16, 16, __half, wmma::row_major> af[2];
            wmma::load_matrix_sync(af[0], As + (wid * 32) * LDA + k0 * 16, LDA);
            wmma::load_matrix_sync(af[1], As + (wid * 32 + 16) * LDA + k0 * 16, LDA);
            #pragma unroll
            for (int n0 = 0; n0 < 4; n0++) {
                wmma::fragment<wmma::matrix_b, 16, 16, 16, __half, wmma::row_major> bf;
                wmma::load_matrix_sync(bf, Bs + (k0 * 16) * LDB + n0 * 16, LDB);
                wmma::mma_sync(acc[0][n0], af[0], bf, acc[0][n0]);
                wmma::mma_sync(acc[1][n0], af[1], bf, acc[1][n0]);
            }
        }
        #pragma unroll
        for (int i = 0; i < 2; i++)
            #pragma unroll
            for (int n0 = 0; n0 < 4; n0++)
                wmma::store_matrix_sync(Cs + (wid * 32 + i * 16) * LDC + n0 * 16,
                                        acc[i][n0], LDC, wmma::mem_row_major);
        __syncthreads();

        // ---- epilogue: one row per thread ----
        int row = row0 + tid;
        if (row < N) {
            float h[64];
            const float4* cr = (const float4*)(Cs + tid * LDC);
            #pragma unroll
            for (int q = 0; q < 16; q++) {
                float4 f = cr[q];
                h[4 * q + 0] = f.x + bs[4 * q + 0];
                h[4 * q + 1] = f.y + bs[4 * q + 1];
                h[4 * q + 2] = f.z + bs[4 * q + 2];
                h[4 * q + 3] = f.w + bs[4 * q + 3];
            }
            if (seg > 0) {
                uint4* o4 = (uint4*)(g_hsrc + ((size_t)(seg - 1) * N + row) * 64);
                #pragma unroll
                for (int q = 0; q < 8; q++) {
                    uint4 pk;
                    pk.x = h2_as_u32(__floats2half2_rn(h[8 * q + 0], h[8 * q + 1]));
                    pk.y = h2_as_u32(__floats2half2_rn(h[8 * q + 2], h[8 * q + 3]));
                    pk.z = h2_as_u32(__floats2half2_rn(h[8 * q + 4], h[8 * q + 5]));
                    pk.w = h2_as_u32(__floats2half2_rn(h[8 * q + 6], h[8 * q + 7]));
                    o4[q] = pk;
                }
            }
            for (int v = 0; v < n_av; v++) {
                float e = 0.f;
                #pragma unroll
                for (int j = 0; j < 64; j++) e += h[j] * as_[v * 64 + j];
                if (seg == 0) g_er[(size_t)v * N + row] = e;
                else          g_el[(size_t)(seg - 1) * N + row] = e;
            }
        }
        __syncthreads();
    }
}

// ---------- CSR build: histogram (int4-vectorized dst loads) ----------
__global__ void k_hist(const int* __restrict__ dst, int N, int E, int E2, int E3) {
    int i = blockIdx.x * blockDim.x + threadIdx.x;
    int st = gridDim.x * blockDim.x;
    int n4 = E3 >> 2;
    const int4* d4 = (const int4*)dst;
    for (int q = i; q < n4; q += st) {
        int4 v = __ldg(&d4[q]);
        int e0 = q << 2;
        int r0 = (e0 >= E2) ? 2 : (e0 >= E) ? 1 : 0;
        int r3 = (e0 + 3 >= E2) ? 2 : (e0 + 3 >= E) ? 1 : 0;
        if (r0 == r3) {
            int base = r0 * N;
            atomicAdd(&g_cur[base + v.x], 1);
            atomicAdd(&g_cur[base + v.y], 1);
            atomicAdd(&g_cur[base + v.z], 1);
            atomicAdd(&g_cur[base + v.w], 1);
        } else {
            int es[4] = {v.x, v.y, v.z, v.w};
            #pragma unroll
            for (int k = 0; k < 4; k++) {
                int ee = e0 + k;
                int r = (ee >= E2) ? 2 : (ee >= E) ? 1 : 0;
                atomicAdd(&g_cur[r * N + es[k]], 1);
            }
        }
    }
    for (int e = (n4 << 2) + i; e < E3; e += st) {
        int r = (e >= E2) ? 2 : (e >= E) ? 1 : 0;
        atomicAdd(&g_cur[r * N + __ldg(&dst[e])], 1);
    }
}

// ---------- scan stage A ----------
__global__ void k_scanA(int n) {
    __shared__ int sd[256];
    int tid = threadIdx.x;
    int base = blockIdx.x * 2048 + tid * 8;
    int c[8], pre[8];
    int s = 0;
    #pragma unroll
    for (int i = 0; i < 8; i++) c[i] = (base + i < n) ? g_cur[base + i] : 0;
    #pragma unroll
    for (int i = 0; i < 8; i++) { pre[i] = s; s += c[i]; }
    sd[tid] = s;
    __syncthreads();
    for (int o = 1; o < 256; o <<= 1) {
        int v = (tid >= o) ? sd[tid - o] : 0;
        __syncthreads();
        sd[tid] += v;
        __syncthreads();
    }
    int excl = sd[tid] - s;
    #pragma unroll
    for (int i = 0; i < 8; i++)
        if (base + i < n) g_off[base + i] = excl + pre[i];
    if (tid == 255) g_tsum[blockIdx.x] = sd[255];
}

// ---------- scan stage B+C merged: every block scans tile sums redundantly ----------
__global__ void k_scanBC(int n, int total, int nt) {
    __shared__ int sd[256];
    __shared__ int ex[256];
    int tid = threadIdx.x;
    int v = (tid < nt) ? g_tsum[tid] : 0;
    sd[tid] = v;
    __syncthreads();
    for (int o = 1; o < 256; o <<= 1) {
        int x = (tid >= o) ? sd[tid - o] : 0;
        __syncthreads();
        sd[tid] += x;
        __syncthreads();
    }
    ex[tid] = sd[tid] - v;   // exclusive scan of tile sums
    __syncthreads();

    int i = blockIdx.x * blockDim.x + tid;
    int st = gridDim.x * blockDim.x;
    for (int j = i; j < n; j += st) {
        int o = g_off[j] + ex[j >> 11];
        g_off[j] = o;
        g_cur[j] = o;
    }
    if (i == 0) {
        g_off[n] = total;
        g_wpart[0] = 0.f; g_wpart[1] = 0.f; g_wpart[2] = 0.f; g_wpart[3] = 0.f;
    }
}

// ---------- aggregate: per (r,dst) gather, 2 edges/iteration ----------
__global__ __launch_bounds__(256) void k_agg(int N) {
    int t = blockIdx.x * blockDim.x + threadIdx.x;
    int g = t >> 4;
    int lane = t & 15;
    int gsz = (gridDim.x * blockDim.x) >> 4;
    int items = 3 * N, N2 = 2 * N;
    const uint2* h2 = (const uint2*)g_hsrc;

    for (int item = g; item < items; item += gsz) {
        int r = (item >= N2) ? 2 : (item >= N) ? 1 : 0;
        int d = item - r * N;
        float er = __ldg(&g_er[item]);
        int j0 = __ldg(&g_off[item]);
        int j1 = __ldg(&g_off[item + 1]);
        const float* elr = g_el + (size_t)r * N;
        const uint2* hr = h2 + (size_t)r * N * 16 + lane;
        float a0 = 0.f, a1 = 0.f, a2 = 0.f, a3 = 0.f, den = 0.f;

        for (int j = j0; j < j1; j += 2) {
            int sA = __ldg(&g_csr[j]);
            bool hasB = (j + 1 < j1);
            int sB = hasB ? __ldg(&g_csr[j + 1]) : sA;
            float elA = __ldg(&elr[sA]);
            uint2 vA = __ldg(&hr[(size_t)sA * 16]);
            float elB = __ldg(&elr[sB]);
            uint2 vB = __ldg(&hr[(size_t)sB * 16]);

            float xA = elA + er;
            float pA = __expf(xA > 0.f ? xA : 0.01f * xA);
            float2 fA0 = __half22float2(u32_as_h2(vA.x));
            float2 fA1 = __half22float2(u32_as_h2(vA.y));
            a0 += pA * fA0.x; a1 += pA * fA0.y; a2 += pA * fA1.x; a3 += pA * fA1.y;
            den += pA;

            if (hasB) {
                float xB = elB + er;
                float pB = __expf(xB > 0.f ? xB : 0.01f * xB);
                float2 fB0 = __half22float2(u32_as_h2(vB.x));
                float2 fB1 = __half22float2(u32_as_h2(vB.y));
                a0 += pB * fB0.x; a1 += pB * fB0.y; a2 += pB * fB1.x; a3 += pB * fB1.y;
                den += pB;
            }
        }
        float dinv = den > 0.f ? 1.f / den : 0.f;   // zero-degree -> elu(0)=0
        a0 *= dinv; a1 *= dinv; a2 *= dinv; a3 *= dinv;
        a0 = a0 > 0.f ? a0 : (__expf(a0) - 1.f);
        a1 = a1 > 0.f ? a1 : (__expf(a1) - 1.f);
        a2 = a2 > 0.f ? a2 : (__expf(a2) - 1.f);
        a3 = a3 > 0.f ? a3 : (__expf(a3) - 1.f);
        *(float4*)(g_z + (size_t)d * 192 + r * 64 + lane * 4) =
            make_float4(a0, a1, a2, a3);
    }
}

// ---------- finalize (WMMA): w logits = mean tanh(z@W1+b1)@w2 per relation ----------
#define FZ_W1 0            // 64 x 136 halfs = 17408
#define FZ_Z  17408        // 64 items x 72 halfs = 9216
#define FZ_C  26624        // 64 x 132 floats = 33792
#define FZ_B1 60416        // 128 f32
#define FZ_W2 60928        // 128 f32
#define FZ_TOTAL 61440
#define FLDW 136
#define FLDZ 72
#define FLDC 132

__global__ void k_finalize_tc(
    const float* __restrict__ W1, const float* __restrict__ b1,
    const float* __restrict__ w2, int N)
{
    extern __shared__ char smem[];
    __half* W1h = (__half*)(smem + FZ_W1);
    __half* Zh  = (__half*)(smem + FZ_Z);
    float*  Cs  = (float*)(smem + FZ_C);
    float*  b1s = (float*)(smem + FZ_B1);
    float*  w2s = (float*)(smem + FZ_W2);
    __shared__ float wsum[4][3];

    int tid = threadIdx.x, wid = tid >> 5, lane = tid & 31;

    for (int idx = tid; idx < 8192; idx += 128) {
        int k = idx >> 7, n = idx & 127;
        W1h[k * FLDW + n] = __float2half(W1[idx]);
    }
    if (tid < 128) { b1s[tid] = b1[tid]; w2s[tid] = w2[tid]; }
    __syncthreads();

    int items = 3 * N, N2 = 2 * N;
    int li = tid >> 1, half = tid & 1;
    float t0 = 0.f, t1 = 0.f, t2 = 0.f;
    int stride = gridDim.x * 64;

    for (int item0 = blockIdx.x * 64; item0 < items; item0 += stride) {
        {
            int it = item0 + li;
            int iu = (it < items) ? it : 0;
            int r = (iu >= N2) ? 2 : (iu >= N) ? 1 : 0;
            int row = iu - r * N;
            const float4* zr = (const float4*)(g_z + (size_t)row * 192 + r * 64) + half * 8;
            __half2* zd = (__half2*)(Zh + li * FLDZ + half * 32);
            #pragma unroll
            for (int q = 0; q < 8; q++) {
                float4 f = zr[q];
                zd[2 * q + 0] = __floats2half2_rn(f.x, f.y);
                zd[2 * q + 1] = __floats2half2_rn(f.z, f.w);
            }
        }
        __syncthreads();

        {
            wmma::fragment<wmma::accumulator, 16, 16, 16, float> acc[8];
            #pragma unroll
            for (int j = 0; j < 8; j++) wmma::fill_fragment(acc[j], 0.f);
            #pragma unroll
            for (int k0 = 0; k0 < 4; k0++) {
                wmma::fragment<wmma::matrix_a, 16, 16, 16, __half, wmma::row_major> af;
                wmma::load_matrix_sync(af, Zh + (wid * 16) * FLDZ + k0 * 16, FLDZ);
                #pragma unroll
                for (int n0 = 0; n0 < 8; n0++) {
                    wmma::fragment<wmma::matrix_b, 16, 16, 16, __half, wmma::row_major> bf;
                    wmma::load_matrix_sync(bf, W1h + (k0 * 16) * FLDW + n0 * 16, FLDW);
                    wmma::mma_sync(acc[n0], af, bf, acc[n0]);
                }
            }
            #pragma unroll
            for (int n0 = 0; n0 < 8; n0++)
                wmma::store_matrix_sync(Cs + (wid * 16) * FLDC + n0 * 16, acc[n0],
                                        FLDC, wmma::mem_row_major);
        }
        __syncthreads();

        {
            int it = item0 + li;
            if (it < items) {
                int r = (it >= N2) ? 2 : (it >= N) ? 1 : 0;
                const float* cr = Cs + li * FLDC + half * 64;
                const float* b1p = b1s + half * 64;
                const float* w2p = w2s + half * 64;
                float s = 0.f;
                #pragma unroll 16
                for (int c = 0; c < 64; c++)
                    s += tanh_approx(cr[c] + b1p[c]) * w2p[c];
                s += __shfl_xor_sync(0xffffffffu, s, 1);
                if (half == 0) {
                    if (r == 0) t0 += s; else if (r == 1) t1 += s; else t2 += s;
                }
            }
        }
        __syncthreads();
    }

    #pragma unroll
    for (int o = 16; o; o >>= 1) {
        t0 += __shfl_xor_sync(0xffffffffu, t0, o);
        t1 += __shfl_xor_sync(0xffffffffu, t1, o);
        t2 += __shfl_xor_sync(0xffffffffu, t2, o);
    }
    if (lane == 0) { wsum[wid][0] = t0; wsum[wid][1] = t1; wsum[wid][2] = t2; }
    __syncthreads();
    if (tid < 3) {
        float s = 0.f;
        #pragma unroll
        for (int w = 0; w < 4; w++) s += wsum[w][tid];
        atomicAdd(&g_wpart[tid], s);
    }
}

// ---------- semantic softmax + mix ----------
__global__ void k_mix(float* __restrict__ out, int N, float invN) {
    float w0 = g_wpart[0] * invN, w1 = g_wpart[1] * invN, w2v = g_wpart[2] * invN;
    float m = fmaxf(w0, fmaxf(w1, w2v));
    float e0 = __expf(w0 - m), e1 = __expf(w1 - m), e2 = __expf(w2v - m);
    float si = 1.f / (e0 + e1 + e2);
    float a0 = e0 * si, a1 = e1 * si, a2 = e2 * si;

    const float4* z4 = (const float4*)g_z;
    float4* o4 = (float4*)out;
    int total = N * 16;
    int i = blockIdx.x * blockDim.x + threadIdx.x;
    int stride = gridDim.x * blockDim.x;
    for (int idx = i; idx < total; idx += stride) {
        int n = idx >> 4, q = idx & 15;
        float4 v0 = z4[(size_t)n * 48 + q];
        float4 v1 = z4[(size_t)n * 48 + 16 + q];
        float4 v2 = z4[(size_t)n * 48 + 32 + q];
        float4 o;
        o.x = a0 * v0.x + a1 * v1.x + a2 * v2.x;
        o.y = a0 * v0.y + a1 * v1.y + a2 * v2.y;
        o.z = a0 * v0.z + a1 * v1.z + a2 * v2.z;
        o.w = a0 * v0.w + a1 * v1.w + a2 * v2.w;
        o4[idx] = o;
    }
}

extern "C" void kernel_launch(void* const* d_in, const int* in_sizes, int n_in,
                              void* d_out, int out_size) {
    const float* dst_feat = (const float*)d_in[0];
    const float* neigh    = (const float*)d_in[1];
    const float* Wt       = (const float*)d_in[2];
    const float* bt       = (const float*)d_in[3];
    const float* attn_l   = (const float*)d_in[4];
    const float* attn_r   = (const float*)d_in[5];
    const float* W1       = (const float*)d_in[6];
    const float* b1       = (const float*)d_in[7];
    const float* w2       = (const float*)d_in[8];
    const int*   src      = (const int*)d_in[9];
    const int*   dst      = (const int*)d_in[10];

    int N = in_sizes[0] / 128;          // 100000
    int E = in_sizes[9] / 3;            // 1000000
    int E2 = 2 * E, E3 = 3 * E;
    int n3 = 3 * N;
    int nScanTiles = (n3 + 2047) / 2048;   // 147 <= 256
    int nTiles = (N + 127) / 128;          // 782 row tiles
    (void)n_in; (void)out_size;

    void* cp = nullptr;
    cudaGetSymbolAddress(&cp, g_cur);
    cudaMemsetAsync(cp, 0, (size_t)n3 * sizeof(int));

    k_hist<<<1184, 256>>>(dst, N, E, E2, E3);        // kernel 1
    k_scanA<<<nScanTiles, 256>>>(n3);                // kernel 2
    k_scanBC<<<(n3 + 255) / 256, 256>>>(n3, E3, nScanTiles);  // kernel 3

    // WMMA GEMMs + CSR fill in one launch  — 4th kernel (ncu capture target)
    cudaFuncSetAttribute(k_gemm_tc, cudaFuncAttributeMaxDynamicSharedMemorySize, SM_TOTAL);
    dim3 ggrid(148, 5);
    k_gemm_tc<<<ggrid, 128, SM_TOTAL>>>(dst_feat, neigh, Wt, bt, attn_l, attn_r,
                                        src, dst, N, E, E2, E3, nTiles);

    k_agg<<<1184, 256>>>(N);

    cudaFuncSetAttribute(k_finalize_tc, cudaFuncAttributeMaxDynamicSharedMemorySize, FZ_TOTAL);
    k_finalize_tc<<<444, 128, FZ_TOTAL>>>(W1, b1, w2, N);

    k_mix<<<1024, 256>>>((float*)d_out, N, 1.0f / (float)N);
}

// round 16
// speedup vs baseline: 2.8586x; 1.1523x over previous
#include <cuda_runtime.h>
#include <cuda_fp16.h>
#include <mma.h>
#include <math.h>
#include <string.h>

using namespace nvcuda;

#define NMAX 100000
#define RMAX 3
#define EMAX 1000000

// Scratch (device globals; no allocation allowed)
__device__ __align__(256) float g_z[(size_t)NMAX * 192];             // [N][3][64] final z_r
__device__ __align__(256) __half g_hsrc[(size_t)RMAX * NMAX * 64];   // h_src per relation (fp16)
__device__ __align__(256) float g_el[RMAX * NMAX];                   // el per relation
__device__ __align__(256) float g_er[RMAX * NMAX];                   // er per relation
__device__ __align__(256) int   g_off[RMAX * NMAX + 1];              // CSR row offsets
__device__ __align__(256) int   g_cur[RMAX * NMAX];                  // counts -> fill cursors
__device__ __align__(256) int   g_csr[(size_t)RMAX * EMAX];          // CSR src indices
__device__ __align__(256) int   g_tsum[256];                         // scan tile sums
__device__ __align__(256) float g_wpart[4];                          // semantic logit partials

// ---------- helpers ----------
__device__ __forceinline__ float tanh_approx(float x) {
    float y;
    asm("tanh.approx.f32 %0, %1;" : "=f"(y) : "f"(x));
    return y;
}
__device__ __forceinline__ unsigned int h2_as_u32(__half2 h) {
    unsigned int u;
    memcpy(&u, &h, 4);
    return u;
}
__device__ __forceinline__ __half2 u32_as_h2(unsigned int u) {
    __half2 h;
    memcpy(&h, &u, 4);
    return h;
}

// dynamic smem layout for k_gemm_tc (bytes)
#define SM_A 0
#define SM_B 34816
#define SM_MISC 53248
#define SM_TOTAL 54272
#define LDA 136
#define LDB 72
#define LDC 68

// ---------- WMMA GEMM, 256 threads (+ overlapped CSR fill at blockIdx.y==4) ----------
__global__ __launch_bounds__(256, 3) void k_gemm_tc(
    const float* __restrict__ dst_feat, const float* __restrict__ neigh,
    const float* __restrict__ Wt, const float* __restrict__ bt,
    const float* __restrict__ attn_l, const float* __restrict__ attn_r,
    const int* __restrict__ src, const int* __restrict__ dst,
    int N, int E, int E2, int E3, int nTiles)
{
    extern __shared__ char smem[];
    int tid = threadIdx.x;
    int seg = blockIdx.y;

    if (seg == 4) {
        // ---- CSR fill (ILP-4 batched) ----
        int i0 = (blockIdx.x * 256 + tid) * 4;
        int st = gridDim.x * 256 * 4;
        for (int e = i0; e < E3; e += st) {
            #pragma unroll
            for (int q = 0; q < 4; q++) {
                int ee = e + q;
                if (ee < E3) {
                    int r = (ee >= E2) ? 2 : (ee >= E) ? 1 : 0;
                    int idx = r * N + __ldg(&dst[ee]);
                    int pos = atomicAdd(&g_cur[idx], 1);
                    g_csr[pos] = __ldg(&src[ee]);
                }
            }
        }
        return;
    }

    int wid = tid >> 5;
    __half* As = (__half*)(smem + SM_A);
    __half* Bs = (__half*)(smem + SM_B);
    float*  Cs = (float*)(smem + SM_A);     // aliased with As (warp-private rows)
    float*  bs = (float*)(smem + SM_MISC);
    float*  as_ = (float*)(smem + SM_MISC + 256);

    // ---- W [k=128][n=64] -> fp16 smem (one time) ----
    const float* W = Wt + (size_t)seg * 128 * 64;
    for (int idx = tid; idx < 8192; idx += 256) {
        int k = idx >> 6, n = idx & 63;
        Bs[k * LDB + n] = __float2half(W[idx]);
    }
    if (tid < 64) bs[tid] = bt[seg * 64 + tid];
    int n_av = (seg == 0) ? 3 : 1;
    const float* av = (seg == 0) ? attn_r : (attn_l + (size_t)(seg - 1) * 64);
    for (int i = tid; i < n_av * 64; i += 256) as_[i] = av[i];
    __syncthreads();

    const float4* X4 = (const float4*)((seg == 0) ? dst_feat : (neigh + (size_t)(seg - 1) * N * 128));

    for (int t = blockIdx.x; t < nTiles; t += gridDim.x) {
        int row0 = t * 128;
        // ---- X tile -> fp16 A smem (coalesced; 16 float4/thread) ----
        #pragma unroll 4
        for (int i = 0; i < 16; i++) {
            int idx = i * 256 + tid;
            int row = idx >> 5, c4 = idx & 31;
            int rg = row0 + row;
            if (rg >= N) rg = N - 1;
            float4 f = __ldg(&X4[(size_t)rg * 32 + c4]);
            __half2* dstp = (__half2*)(As + row * LDA + c4 * 4);
            dstp[0] = __floats2half2_rn(f.x, f.y);
            dstp[1] = __floats2half2_rn(f.z, f.w);
        }
        __syncthreads();

        // ---- WMMA: warp computes rows [wid*16, wid*16+16) x 64 cols ----
        wmma::fragment<wmma::accumulator, 16, 16, 16, float> acc[4];
        #pragma unroll
        for (int j = 0; j < 4; j++) wmma::fill_fragment(acc[j], 0.f);

        #pragma unroll
        for (int k0 = 0; k0 < 8; k0++) {
            wmma::fragment<wmma::matrix_a, 16, 16, 16, __half, wmma::row_major> af;
            wmma::load_matrix_sync(af, As + (wid * 16) * LDA + k0 * 16, LDA);
            #pragma unroll
            for (int n0 = 0; n0 < 4; n0++) {
                wmma::fragment<wmma::matrix_b, 16, 16, 16, __half, wmma::row_major> bf;
                wmma::load_matrix_sync(bf, Bs + (k0 * 16) * LDB + n0 * 16, LDB);
                wmma::mma_sync(acc[n0], af, bf, acc[n0]);
            }
        }
        #pragma unroll
        for (int n0 = 0; n0 < 4; n0++)
            wmma::store_matrix_sync(Cs + (wid * 16) * LDC + n0 * 16, acc[n0],
                                    LDC, wmma::mem_row_major);
        __syncthreads();

        // ---- epilogue: 2 threads per row (32 cols each) ----
        int li = tid >> 1, half = tid & 1;
        int row = row0 + li;
        if (row < N) {
            float h[32];
            const float4* cr = (const float4*)(Cs + li * LDC + half * 32);
            const float* bsp = bs + half * 32;
            #pragma unroll
            for (int q = 0; q < 8; q++) {
                float4 f = cr[q];
                h[4 * q + 0] = f.x + bsp[4 * q + 0];
                h[4 * q + 1] = f.y + bsp[4 * q + 1];
                h[4 * q + 2] = f.z + bsp[4 * q + 2];
                h[4 * q + 3] = f.w + bsp[4 * q + 3];
            }
            if (seg > 0) {
                uint4* o4 = (uint4*)(g_hsrc + ((size_t)(seg - 1) * N + row) * 64 + half * 32);
                #pragma unroll
                for (int q = 0; q < 4; q++) {
                    uint4 pk;
                    pk.x = h2_as_u32(__floats2half2_rn(h[8 * q + 0], h[8 * q + 1]));
                    pk.y = h2_as_u32(__floats2half2_rn(h[8 * q + 2], h[8 * q + 3]));
                    pk.z = h2_as_u32(__floats2half2_rn(h[8 * q + 4], h[8 * q + 5]));
                    pk.w = h2_as_u32(__floats2half2_rn(h[8 * q + 6], h[8 * q + 7]));
                    o4[q] = pk;
                }
            }
            for (int v = 0; v < n_av; v++) {
                const float* ap = as_ + v * 64 + half * 32;
                float e = 0.f;
                #pragma unroll
                for (int j = 0; j < 32; j++) e += h[j] * ap[j];
                e += __shfl_xor_sync(0xffffffffu, e, 1);
                if (half == 0) {
                    if (seg == 0) g_er[(size_t)v * N + row] = e;
                    else          g_el[(size_t)(seg - 1) * N + row] = e;
                }
            }
        }
        __syncthreads();
    }
}

// ---------- CSR build: histogram (int4-vectorized dst loads) ----------
__global__ void k_hist(const int* __restrict__ dst, int N, int E, int E2, int E3) {
    int i = blockIdx.x * blockDim.x + threadIdx.x;
    int st = gridDim.x * blockDim.x;
    int n4 = E3 >> 2;
    const int4* d4 = (const int4*)dst;
    for (int q = i; q < n4; q += st) {
        int4 v = __ldg(&d4[q]);
        int e0 = q << 2;
        int r0 = (e0 >= E2) ? 2 : (e0 >= E) ? 1 : 0;
        int r3 = (e0 + 3 >= E2) ? 2 : (e0 + 3 >= E) ? 1 : 0;
        if (r0 == r3) {
            int base = r0 * N;
            atomicAdd(&g_cur[base + v.x], 1);
            atomicAdd(&g_cur[base + v.y], 1);
            atomicAdd(&g_cur[base + v.z], 1);
            atomicAdd(&g_cur[base + v.w], 1);
        } else {
            int es[4] = {v.x, v.y, v.z, v.w};
            #pragma unroll
            for (int k = 0; k < 4; k++) {
                int ee = e0 + k;
                int r = (ee >= E2) ? 2 : (ee >= E) ? 1 : 0;
                atomicAdd(&g_cur[r * N + es[k]], 1);
            }
        }
    }
    for (int e = (n4 << 2) + i; e < E3; e += st) {
        int r = (e >= E2) ? 2 : (e >= E) ? 1 : 0;
        atomicAdd(&g_cur[r * N + __ldg(&dst[e])], 1);
    }
}

// ---------- scan stage A ----------
__global__ void k_scanA(int n) {
    __shared__ int sd[256];
    int tid = threadIdx.x;
    int base = blockIdx.x * 2048 + tid * 8;
    int c[8], pre[8];
    int s = 0;
    #pragma unroll
    for (int i = 0; i < 8; i++) c[i] = (base + i < n) ? g_cur[base + i] : 0;
    #pragma unroll
    for (int i = 0; i < 8; i++) { pre[i] = s; s += c[i]; }
    sd[tid] = s;
    __syncthreads();
    for (int o = 1; o < 256; o <<= 1) {
        int v = (tid >= o) ? sd[tid - o] : 0;
        __syncthreads();
        sd[tid] += v;
        __syncthreads();
    }
    int excl = sd[tid] - s;
    #pragma unroll
    for (int i = 0; i < 8; i++)
        if (base + i < n) g_off[base + i] = excl + pre[i];
    if (tid == 255) g_tsum[blockIdx.x] = sd[255];
}

// ---------- scan stage B+C merged ----------
__global__ void k_scanBC(int n, int total, int nt) {
    __shared__ int sd[256];
    __shared__ int ex[256];
    int tid = threadIdx.x;
    int v = (tid < nt) ? g_tsum[tid] : 0;
    sd[tid] = v;
    __syncthreads();
    for (int o = 1; o < 256; o <<= 1) {
        int x = (tid >= o) ? sd[tid - o] : 0;
        __syncthreads();
        sd[tid] += x;
        __syncthreads();
    }
    ex[tid] = sd[tid] - v;
    __syncthreads();

    int i = blockIdx.x * blockDim.x + tid;
    int st = gridDim.x * blockDim.x;
    for (int j = i; j < n; j += st) {
        int o = g_off[j] + ex[j >> 11];
        g_off[j] = o;
        g_cur[j] = o;
    }
    if (i == 0) {
        g_off[n] = total;
        g_wpart[0] = 0.f; g_wpart[1] = 0.f; g_wpart[2] = 0.f; g_wpart[3] = 0.f;
    }
}

// ---------- aggregate: per (r,dst) gather, 2 edges/iteration ----------
__global__ __launch_bounds__(256) void k_agg(int N) {
    int t = blockIdx.x * blockDim.x + threadIdx.x;
    int g = t >> 4;
    int lane = t & 15;
    int gsz = (gridDim.x * blockDim.x) >> 4;
    int items = 3 * N, N2 = 2 * N;
    const uint2* h2 = (const uint2*)g_hsrc;

    for (int item = g; item < items; item += gsz) {
        int r = (item >= N2) ? 2 : (item >= N) ? 1 : 0;
        int d = item - r * N;
        float er = __ldg(&g_er[item]);
        int j0 = __ldg(&g_off[item]);
        int j1 = __ldg(&g_off[item + 1]);
        const float* elr = g_el + (size_t)r * N;
        const uint2* hr = h2 + (size_t)r * N * 16 + lane;
        float a0 = 0.f, a1 = 0.f, a2 = 0.f, a3 = 0.f, den = 0.f;

        for (int j = j0; j < j1; j += 2) {
            int sA = __ldg(&g_csr[j]);
            bool hasB = (j + 1 < j1);
            int sB = hasB ? __ldg(&g_csr[j + 1]) : sA;
            float elA = __ldg(&elr[sA]);
            uint2 vA = __ldg(&hr[(size_t)sA * 16]);
            float elB = __ldg(&elr[sB]);
            uint2 vB = __ldg(&hr[(size_t)sB * 16]);

            float xA = elA + er;
            float pA = __expf(xA > 0.f ? xA : 0.01f * xA);
            float2 fA0 = __half22float2(u32_as_h2(vA.x));
            float2 fA1 = __half22float2(u32_as_h2(vA.y));
            a0 += pA * fA0.x; a1 += pA * fA0.y; a2 += pA * fA1.x; a3 += pA * fA1.y;
            den += pA;

            if (hasB) {
                float xB = elB + er;
                float pB = __expf(xB > 0.f ? xB : 0.01f * xB);
                float2 fB0 = __half22float2(u32_as_h2(vB.x));
                float2 fB1 = __half22float2(u32_as_h2(vB.y));
                a0 += pB * fB0.x; a1 += pB * fB0.y; a2 += pB * fB1.x; a3 += pB * fB1.y;
                den += pB;
            }
        }
        float dinv = den > 0.f ? 1.f / den : 0.f;   // zero-degree -> elu(0)=0
        a0 *= dinv; a1 *= dinv; a2 *= dinv; a3 *= dinv;
        a0 = a0 > 0.f ? a0 : (__expf(a0) - 1.f);
        a1 = a1 > 0.f ? a1 : (__expf(a1) - 1.f);
        a2 = a2 > 0.f ? a2 : (__expf(a2) - 1.f);
        a3 = a3 > 0.f ? a3 : (__expf(a3) - 1.f);
        *(float4*)(g_z + (size_t)d * 192 + r * 64 + lane * 4) =
            make_float4(a0, a1, a2, a3);
    }
}

// ---------- finalize (WMMA): w logits = mean tanh(z@W1+b1)@w2 per relation ----------
#define FZ_W1 0            // 64 x 136 halfs = 17408
#define FZ_Z  17408        // 64 items x 72 halfs = 9216
#define FZ_C  26624        // 64 x 132 floats = 33792
#define FZ_B1 60416        // 128 f32
#define FZ_W2 60928        // 128 f32
#define FZ_TOTAL 61440
#define FLDW 136
#define FLDZ 72
#define FLDC 132

__global__ void k_finalize_tc(
    const float* __restrict__ W1, const float* __restrict__ b1,
    const float* __restrict__ w2, int N)
{
    extern __shared__ char smem[];
    __half* W1h = (__half*)(smem + FZ_W1);
    __half* Zh  = (__half*)(smem + FZ_Z);
    float*  Cs  = (float*)(smem + FZ_C);
    float*  b1s = (float*)(smem + FZ_B1);
    float*  w2s = (float*)(smem + FZ_W2);
    __shared__ float wsum[4][3];

    int tid = threadIdx.x, wid = tid >> 5, lane = tid & 31;

    for (int idx = tid; idx < 8192; idx += 128) {
        int k = idx >> 7, n = idx & 127;
        W1h[k * FLDW + n] = __float2half(W1[idx]);
    }
    if (tid < 128) { b1s[tid] = b1[tid]; w2s[tid] = w2[tid]; }
    __syncthreads();

    int items = 3 * N, N2 = 2 * N;
    int li = tid >> 1, half = tid & 1;
    float t0 = 0.f, t1 = 0.f, t2 = 0.f;
    int stride = gridDim.x * 64;

    for (int item0 = blockIdx.x * 64; item0 < items; item0 += stride) {
        {
            int it = item0 + li;
            int iu = (it < items) ? it : 0;
            int r = (iu >= N2) ? 2 : (iu >= N) ? 1 : 0;
            int row = iu - r * N;
            const float4* zr = (const float4*)(g_z + (size_t)row * 192 + r * 64) + half * 8;
            __half2* zd = (__half2*)(Zh + li * FLDZ + half * 32);
            #pragma unroll
            for (int q = 0; q < 8; q++) {
                float4 f = zr[q];
                zd[2 * q + 0] = __floats2half2_rn(f.x, f.y);
                zd[2 * q + 1] = __floats2half2_rn(f.z, f.w);
            }
        }
        __syncthreads();

        {
            wmma::fragment<wmma::accumulator, 16, 16, 16, float> acc[8];
            #pragma unroll
            for (int j = 0; j < 8; j++) wmma::fill_fragment(acc[j], 0.f);
            #pragma unroll
            for (int k0 = 0; k0 < 4; k0++) {
                wmma::fragment<wmma::matrix_a, 16, 16, 16, __half, wmma::row_major> af;
                wmma::load_matrix_sync(af, Zh + (wid * 16) * FLDZ + k0 * 16, FLDZ);
                #pragma unroll
                for (int n0 = 0; n0 < 8; n0++) {
                    wmma::fragment<wmma::matrix_b, 16, 16, 16, __half, wmma::row_major> bf;
                    wmma::load_matrix_sync(bf, W1h + (k0 * 16) * FLDW + n0 * 16, FLDW);
                    wmma::mma_sync(acc[n0], af, bf, acc[n0]);
                }
            }
            #pragma unroll
            for (int n0 = 0; n0 < 8; n0++)
                wmma::store_matrix_sync(Cs + (wid * 16) * FLDC + n0 * 16, acc[n0],
                                        FLDC, wmma::mem_row_major);
        }
        __syncthreads();

        {
            int it = item0 + li;
            if (it < items) {
                int r = (it >= N2) ? 2 : (it >= N) ? 1 : 0;
                const float* cr = Cs + li * FLDC + half * 64;
                const float* b1p = b1s + half * 64;
                const float* w2p = w2s + half * 64;
                float s = 0.f;
                #pragma unroll 16
                for (int c = 0; c < 64; c++)
                    s += tanh_approx(cr[c] + b1p[c]) * w2p[c];
                s += __shfl_xor_sync(0xffffffffu, s, 1);
                if (half == 0) {
                    if (r == 0) t0 += s; else if (r == 1) t1 += s; else t2 += s;
                }
            }
        }
        __syncthreads();
    }

    #pragma unroll
    for (int o = 16; o; o >>= 1) {
        t0 += __shfl_xor_sync(0xffffffffu, t0, o);
        t1 += __shfl_xor_sync(0xffffffffu, t1, o);
        t2 += __shfl_xor_sync(0xffffffffu, t2, o);
    }
    if (lane == 0) { wsum[wid][0] = t0; wsum[wid][1] = t1; wsum[wid][2] = t2; }
    __syncthreads();
    if (tid < 3) {
        float s = 0.f;
        #pragma unroll
        for (int w = 0; w < 4; w++) s += wsum[w][tid];
        atomicAdd(&g_wpart[tid], s);
    }
}

// ---------- semantic softmax + mix ----------
__global__ void k_mix(float* __restrict__ out, int N, float invN) {
    float w0 = g_wpart[0] * invN, w1 = g_wpart[1] * invN, w2v = g_wpart[2] * invN;
    float m = fmaxf(w0, fmaxf(w1, w2v));
    float e0 = __expf(w0 - m), e1 = __expf(w1 - m), e2 = __expf(w2v - m);
    float si = 1.f / (e0 + e1 + e2);
    float a0 = e0 * si, a1 = e1 * si, a2 = e2 * si;

    const float4* z4 = (const float4*)g_z;
    float4* o4 = (float4*)out;
    int total = N * 16;
    int i = blockIdx.x * blockDim.x + threadIdx.x;
    int stride = gridDim.x * blockDim.x;
    for (int idx = i; idx < total; idx += stride) {
        int n = idx >> 4, q = idx & 15;
        float4 v0 = z4[(size_t)n * 48 + q];
        float4 v1 = z4[(size_t)n * 48 + 16 + q];
        float4 v2 = z4[(size_t)n * 48 + 32 + q];
        float4 o;
        o.x = a0 * v0.x + a1 * v1.x + a2 * v2.x;
        o.y = a0 * v0.y + a1 * v1.y + a2 * v2.y;
        o.z = a0 * v0.z + a1 * v1.z + a2 * v2.z;
        o.w = a0 * v0.w + a1 * v1.w + a2 * v2.w;
        o4[idx] = o;
    }
}

extern "C" void kernel_launch(void* const* d_in, const int* in_sizes, int n_in,
                              void* d_out, int out_size) {
    const float* dst_feat = (const float*)d_in[0];
    const float* neigh    = (const float*)d_in[1];
    const float* Wt       = (const float*)d_in[2];
    const float* bt       = (const float*)d_in[3];
    const float* attn_l   = (const float*)d_in[4];
    const float* attn_r   = (const float*)d_in[5];
    const float* W1       = (const float*)d_in[6];
    const float* b1       = (const float*)d_in[7];
    const float* w2       = (const float*)d_in[8];
    const int*   src      = (const int*)d_in[9];
    const int*   dst      = (const int*)d_in[10];

    int N = in_sizes[0] / 128;          // 100000
    int E = in_sizes[9] / 3;            // 1000000
    int E2 = 2 * E, E3 = 3 * E;
    int n3 = 3 * N;
    int nScanTiles = (n3 + 2047) / 2048;   // 147 <= 256
    int nTiles = (N + 127) / 128;          // 782 row tiles
    (void)n_in; (void)out_size;

    void* cp = nullptr;
    cudaGetSymbolAddress(&cp, g_cur);
    cudaMemsetAsync(cp, 0, (size_t)n3 * sizeof(int));

    k_hist<<<1184, 256>>>(dst, N, E, E2, E3);
    k_scanA<<<nScanTiles, 256>>>(n3);
    k_scanBC<<<(n3 + 255) / 256, 256>>>(n3, E3, nScanTiles);

    // WMMA GEMMs + CSR fill in one launch — 4th kernel (ncu capture target)
    cudaFuncSetAttribute(k_gemm_tc, cudaFuncAttributeMaxDynamicSharedMemorySize, SM_TOTAL);
    dim3 ggrid(148, 5);
    k_gemm_tc<<<ggrid, 256, SM_TOTAL>>>(dst_feat, neigh, Wt, bt, attn_l, attn_r,
                                        src, dst, N, E, E2, E3, nTiles);

    k_agg<<<1184, 256>>>(N);

    cudaFuncSetAttribute(k_finalize_tc, cudaFuncAttributeMaxDynamicSharedMemorySize, FZ_TOTAL);
    k_finalize_tc<<<444, 128, FZ_TOTAL>>>(W1, b1, w2, N);

    k_mix<<<1024, 256>>>((float*)d_out, N, 1.0f / (float)N);
}